// round 12
// baseline (speedup 1.0000x reference)
#include <cuda_runtime.h>
#include <cuda_bf16.h>
#include <math.h>
#include <stdint.h>

// Problem constants
#define Hh 256
#define Ll 4
#define Nn 100000
#define Ee 300000
#define BN_EPS 1e-5f
#define AGG_EPS 1e-6f
#define K_DEC 544   // 520 padded to multiple of 32

typedef __nv_bfloat16 bf16;

// ------------------------- static device scratch -------------------------
__device__ float g_ABDE[(size_t)Nn * 4 * Hh];   // [N,1024]: A|B|D|E
__device__ float g_Ce[(size_t)Ee * Hh];         // e_hat scratch (sorted edge order)
__device__ float g_num[(size_t)Nn * Hh];
__device__ float g_den[(size_t)Nn * Hh];
__device__ float g_stats[4 * Hh];
__device__ float g_bpack[Ll * 4 * Hh];
__device__ float g_fbias[Hh];
__device__ float g_b0p[Hh];                     // layer-0 collapsed Ce bias
__device__ int   g_src[Ee];     // sorted by dst
__device__ int   g_dst[Ee];     // sorted (non-decreasing)
__device__ int   g_eorig[Ee];   // sorted pos -> original edge id
__device__ int   g_srcO[Ee];
__device__ int   g_dstO[Ee];
__device__ int   g_hist[Nn];
__device__ int   g_idx64;

// split bf16 weights, transposed to [N][K]
__device__ bf16 g_abde_hi[(size_t)Ll * 1024 * 256];
__device__ bf16 g_abde_lo[(size_t)Ll * 1024 * 256];
__device__ bf16 g_c_hi[(size_t)Ll * 256 * 256];
__device__ bf16 g_c_lo[(size_t)Ll * 256 * 256];
__device__ bf16 g_fw_hi[256 * 256];
__device__ bf16 g_fw_lo[256 * 256];
__device__ bf16 g_d1_hi[256 * K_DEC];
__device__ bf16 g_d1_lo[256 * K_DEC];
__device__ bf16 g_w0p_hi[256 * 32];             // layer-0 collapsed Ce weight [n][32]
__device__ bf16 g_w0p_lo[256 * 32];

// split bf16 activations (x/e live ONLY here; e in sorted edge order)
__device__ bf16 g_xh[(size_t)Nn * Hh];
__device__ bf16 g_xl[(size_t)Nn * Hh];
__device__ bf16 g_eh[(size_t)Ee * Hh];
__device__ bf16 g_el[(size_t)Ee * Hh];
__device__ bf16 g_hh[(size_t)Nn * Hh];
__device__ bf16 g_hl[(size_t)Nn * Hh];
__device__ bf16 g_afh[(size_t)Ee * 32];
__device__ bf16 g_afl[(size_t)Ee * 32];

// ------------------------- prep kernels -------------------------
__global__ void k_detect_idx(const unsigned int* __restrict__ w) {
    unsigned int s = 0;
    for (int i = threadIdx.x; i < 1024; i += 256) s |= w[2 * i + 1];
#pragma unroll
    for (int off = 16; off; off >>= 1) s |= __shfl_xor_sync(0xFFFFFFFFu, s, off);
    __shared__ unsigned int red[8];
    if ((threadIdx.x & 31) == 0) red[threadIdx.x >> 5] = s;
    __syncthreads();
    if (threadIdx.x == 0) {
        unsigned int t = 0;
        for (int i = 0; i < 8; i++) t |= red[i];
        g_idx64 = (t == 0u) ? 1 : 0;
    }
}

__global__ void k_convert_idx(const void* __restrict__ eidx) {
    int i = blockIdx.x * blockDim.x + threadIdx.x;
    if (i < Ee) {
        int s, d;
        if (g_idx64) {
            const long long* p = (const long long*)eidx;
            s = (int)p[i];
            d = (int)p[(size_t)Ee + i];
        } else {
            const int* p = (const int*)eidx;
            s = p[i];
            d = p[Ee + i];
        }
        g_srcO[i] = s;
        g_dstO[i] = d;
        atomicAdd(&g_hist[d], 1);
    }
}

__global__ __launch_bounds__(1024) void k_scan() {
    __shared__ int part[1024];
    int t = threadIdx.x;
    const int CH = (Nn + 1023) / 1024;
    int base = t * CH;
    int s = 0;
    for (int j = 0; j < CH; j++) {
        int b = base + j;
        if (b < Nn) s += g_hist[b];
    }
    part[t] = s;
    __syncthreads();
    if (t == 0) {
        int acc = 0;
        for (int i = 0; i < 1024; i++) { int v = part[i]; part[i] = acc; acc += v; }
    }
    __syncthreads();
    int acc = part[t];
    for (int j = 0; j < CH; j++) {
        int b = base + j;
        if (b < Nn) { int v = g_hist[b]; g_hist[b] = acc; acc += v; }
    }
}

__global__ void k_scatter() {
    int i = blockIdx.x * blockDim.x + threadIdx.x;
    if (i < Ee) {
        int d = g_dstO[i];
        int pos = atomicAdd(&g_hist[d], 1);
        g_src[pos] = g_srcO[i];
        g_dst[pos] = d;
        g_eorig[pos] = i;
    }
}

__device__ __forceinline__ void split_write(float v, bf16* hi, bf16* lo, size_t i) {
    bf16 h = __float2bfloat16_rn(v);
    hi[i] = h;
    lo[i] = __float2bfloat16_rn(v - __bfloat162float(h));
}

__global__ void k_split_abde(const float* __restrict__ Aw, const float* __restrict__ Bw,
                             const float* __restrict__ Dw, const float* __restrict__ Ew) {
    size_t i = (size_t)blockIdx.x * 256 + threadIdx.x;
    if (i < (size_t)Ll * 1024 * 256) {
        int k = (int)(i & 255);
        int n = (int)((i >> 8) & 1023);
        int l = (int)(i >> 18);
        const float* W = (n < 256) ? Aw : (n < 512) ? Bw : (n < 768) ? Dw : Ew;
        float v = W[(size_t)l * 65536 + (size_t)k * 256 + (n & 255)];
        split_write(v, g_abde_hi, g_abde_lo, i);
    }
}

// layer-0 collapsed Ce: W0'[k8][n] = sum_m epw[k8][m] * C0[m][n]; b0' = epb@C0 + C0b
__global__ void k_w0prime(const float* __restrict__ epw, const float* __restrict__ epb,
                          const float* __restrict__ C0, const float* __restrict__ C0b) {
    int i = blockIdx.x * 256 + threadIdx.x;   // 32 blocks * 256 = 8192 = 256n * 32k
    int n = i >> 5, k = i & 31;
    float v = 0.f;
    if (k < 8) {
        for (int m = 0; m < 256; m++) v += epw[k * 256 + m] * C0[(size_t)m * 256 + n];
    }
    split_write(v, g_w0p_hi, g_w0p_lo, (size_t)n * 32 + k);
    if (k == 0) {
        float b = C0b[n];
        for (int m = 0; m < 256; m++) b += epb[m] * C0[(size_t)m * 256 + n];
        g_b0p[n] = b;
    }
}

// block-range partitioned prep (af split uses g_eorig -> run AFTER scatter)
#define MB0 16
#define MB1 1
#define MB2 256
#define MB3 1024
#define MB4 576
#define MB5 100000
#define MB6 75000
__global__ void k_megaprep(
    const float* __restrict__ Ab, const float* __restrict__ Bb,
    const float* __restrict__ Db, const float* __restrict__ Eb,
    const float* __restrict__ fw, const float* __restrict__ fb,
    const float* __restrict__ Cw, const float* __restrict__ d1w,
    const float* __restrict__ hold, const float* __restrict__ af)
{
    int b = blockIdx.x, t = threadIdx.x;
    if (b < MB0) {
        int i = b * 256 + t;
        if (i < Ll * 4 * Hh) {
            int j4 = i % (4 * Hh);
            int l = i / (4 * Hh);
            int which = j4 >> 8, j = j4 & 255;
            const float* B = (which == 0) ? Ab : (which == 1) ? Bb : (which == 2) ? Db : Eb;
            g_bpack[i] = B[l * Hh + j];
        }
        return;
    }
    b -= MB0;
    if (b < MB1) {
        float s = fb[t];
        for (int k = 0; k < Hh; k++) s += fw[(size_t)k * Hh + t];
        g_fbias[t] = s;
        return;
    }
    b -= MB1;
    if (b < MB2) {
        int i = b * 256 + t;
        int k = i & 255, n = i >> 8;
        split_write(fw[(size_t)(Hh + k) * Hh + n], g_fw_hi, g_fw_lo, i);
        return;
    }
    b -= MB2;
    if (b < MB3) {
        size_t i = (size_t)b * 256 + t;
        int k = (int)(i & 255), n = (int)((i >> 8) & 255), l = (int)(i >> 16);
        split_write(Cw[(size_t)l * 65536 + (size_t)k * 256 + n], g_c_hi, g_c_lo, i);
        return;
    }
    b -= MB3;
    if (b < MB4) {
        int i = b * 256 + t;
        if (i < 256 * K_DEC) {
            int k = i % K_DEC, n = i / K_DEC;
            float v = (k < 520) ? d1w[(size_t)k * 256 + n] : 0.0f;
            split_write(v, g_d1_hi, g_d1_lo, i);
        }
        return;
    }
    b -= MB4;
    if (b < MB5) {
        size_t i = (size_t)b * 256 + t;
        if (i < (size_t)Nn * Hh) split_write(hold[i], g_hh, g_hl, i);
        return;
    }
    b -= MB5;
    {
        size_t i = (size_t)b * 256 + t;
        if (i < (size_t)Ee * 32) {
            int c = (int)(i & 31);
            size_t e = i >> 5;
            float v = (c < 8) ? af[(size_t)g_eorig[e] * 8 + c] : 0.0f;
            split_write(v, g_afh, g_afl, i);
        }
    }
}

__global__ void k_init_out(float* __restrict__ out, const float* __restrict__ b2) {
    int i = blockIdx.x * blockDim.x + threadIdx.x;
    if (i < Ee) out[i] = b2[0];
}

// ------------------------- tensor-core machinery -------------------------
__device__ __forceinline__ void mma16816(float* c, const uint32_t* a, const uint32_t* b) {
    asm volatile(
        "mma.sync.aligned.m16n8k16.row.col.f32.bf16.bf16.f32 "
        "{%0,%1,%2,%3}, {%4,%5,%6,%7}, {%8,%9}, {%0,%1,%2,%3};"
        : "+f"(c[0]), "+f"(c[1]), "+f"(c[2]), "+f"(c[3])
        : "r"(a[0]), "r"(a[1]), "r"(a[2]), "r"(a[3]), "r"(b[0]), "r"(b[1]));
}
__device__ __forceinline__ void ldm_x4(uint32_t* r, uint32_t addr) {
    asm volatile("ldmatrix.sync.aligned.m8n8.x4.shared.b16 {%0,%1,%2,%3}, [%4];"
                 : "=r"(r[0]), "=r"(r[1]), "=r"(r[2]), "=r"(r[3]) : "r"(addr));
}
__device__ __forceinline__ void ldm_x2(uint32_t* r, uint32_t addr) {
    asm volatile("ldmatrix.sync.aligned.m8n8.x2.shared.b16 {%0,%1}, [%2];"
                 : "=r"(r[0]), "=r"(r[1]) : "r"(addr));
}
__device__ __forceinline__ void cpa16(uint32_t s, const void* g) {
    asm volatile("cp.async.cg.shared.global [%0], [%1], 16;" :: "r"(s), "l"(g));
}
__device__ __forceinline__ void cpa_commit() { asm volatile("cp.async.commit_group;"); }
template<int N>
__device__ __forceinline__ void cpa_wait() { asm volatile("cp.async.wait_group %0;" :: "n"(N) : "memory"); }

__device__ __forceinline__ int sw_off(int row, int chunk) {
    return row * 64 + ((chunk ^ ((row >> 1) & 3)) << 4);
}

#define ST_ALO 8192
#define ST_BHI 16384
#define ST_BLO 24576
#define ST_STRIDE 32768
#define SMEM3 (3 * ST_STRIDE)   // 96 KB (pure GEMM)
#define SMEM2 (2 * ST_STRIDE)   // 64 KB (gather kernels; keep L1)

// 3-pass bf16x3: one A fragment array reused
__device__ __forceinline__ void tile_compute(
    float acc[4][4][4], uint32_t sbase, int lane, int wr, int wc) {
    uint32_t sAhiB = sbase, sAloB = sbase + ST_ALO, sBhiB = sbase + ST_BHI, sBloB = sbase + ST_BLO;
#pragma unroll
    for (int kg = 0; kg < 2; kg++) {
        uint32_t ra[4][4], rbh[4][2], rbl[4][2];
#pragma unroll
        for (int tm = 0; tm < 4; tm++) {
            int row = wr * 64 + tm * 16 + (lane & 15);
            int ch = 2 * kg + (lane >> 4);
            ldm_x4(ra[tm], sAhiB + sw_off(row, ch));
        }
#pragma unroll
        for (int tn = 0; tn < 4; tn++) {
            int row = wc * 32 + tn * 8 + (lane & 7);
            int ch = 2 * kg + ((lane >> 3) & 1);
            uint32_t off = sw_off(row, ch);
            ldm_x2(rbh[tn], sBhiB + off);
            ldm_x2(rbl[tn], sBloB + off);
        }
#pragma unroll
        for (int tm = 0; tm < 4; tm++)
#pragma unroll
            for (int tn = 0; tn < 4; tn++) {
                mma16816(acc[tm][tn], ra[tm], rbh[tn]);
                mma16816(acc[tm][tn], ra[tm], rbl[tn]);
            }
#pragma unroll
        for (int tm = 0; tm < 4; tm++) {
            int row = wr * 64 + tm * 16 + (lane & 15);
            int ch = 2 * kg + (lane >> 4);
            ldm_x4(ra[tm], sAloB + sw_off(row, ch));
        }
#pragma unroll
        for (int tm = 0; tm < 4; tm++)
#pragma unroll
            for (int tn = 0; tn < 4; tn++)
                mma16816(acc[tm][tn], ra[tm], rbh[tn]);
    }
}

__device__ __forceinline__ uint32_t pack_bf2(float a, float b) {
    __nv_bfloat162 t = __floats2bfloat162_rn(a, b);
    return *(uint32_t*)&t;
}

// 3-stage mainloop (pure GEMM kernels)
#define PIPE_MAIN3(K, LOADER) do { \
    LOADER(sbase0, 0); \
    if ((K) > 32) LOADER(sbase0 + ST_STRIDE, 32); else cpa_commit(); \
    for (int k0 = 0, st = 0; k0 < (K); k0 += 32, st = (st == 2) ? 0 : st + 1) { \
        cpa_wait<1>(); \
        __syncthreads(); \
        if (k0 + 64 < (K)) { \
            int st2 = st + 2; if (st2 >= 3) st2 -= 3; \
            LOADER(sbase0 + st2 * ST_STRIDE, k0 + 64); \
        } else cpa_commit(); \
        tile_compute(acc, sbase0 + st * ST_STRIDE, lane, wr, wc); \
    } \
} while (0)

// 2-stage mainloop (gather kernels; 64 KB smem -> L1 preserved)
#define PIPE_MAIN2(K, LOADER) do { \
    LOADER(sbase0, 0); \
    int cur = 0; \
    for (int k0 = 0; k0 < (K); k0 += 32) { \
        cpa_wait<0>(); \
        __syncthreads(); \
        if (k0 + 32 < (K)) LOADER(sbase0 + (cur ^ 1) * ST_STRIDE, k0 + 32); \
        tile_compute(acc, sbase0 + cur * ST_STRIDE, lane, wr, wc); \
        cur ^= 1; \
    } \
} while (0)

// ------------------------- bf16x3 GEMM, 3-stage pipeline -------------------------
// EPI: 0 = bias -> fp32 C; 2 = bias+relu -> bf16 hi/lo ONLY
template<int EPI>
__global__ __launch_bounds__(256) void gemm_tc2(
    const bf16* __restrict__ Ahi, const bf16* __restrict__ Alo,
    const bf16* __restrict__ Bhi, const bf16* __restrict__ Blo,
    const float* __restrict__ bias, float* __restrict__ C,
    bf16* __restrict__ Chi, bf16* __restrict__ Clo,
    int M, int K, int Nc)
{
    extern __shared__ __align__(16) char smem[];
    uint32_t sbase0 = (uint32_t)__cvta_generic_to_shared(smem);

    int tid = threadIdx.x, lane = tid & 31, w = tid >> 5;
    int wr = w >> 2, wc = w & 3;
    int bm = blockIdx.y * 128, bn = blockIdx.x * 128;

    int r = tid >> 1, ch0 = (tid & 1) * 2;
    int gr = bm + r; if (gr >= M) gr = M - 1;
    size_t aRow = (size_t)gr * K;
    size_t bRow = (size_t)(bn + r) * K;

    float acc[4][4][4];
#pragma unroll
    for (int i = 0; i < 4; i++)
#pragma unroll
        for (int j = 0; j < 4; j++)
#pragma unroll
            for (int q = 0; q < 4; q++) acc[i][j][q] = 0.f;

    auto load_stage = [&](uint32_t sb, int k0) {
#pragma unroll
        for (int i = 0; i < 2; i++) {
            int ch = ch0 + i;
            uint32_t so = sw_off(r, ch);
            size_t go = (size_t)k0 + ch * 8;
            cpa16(sb + so,          Ahi + aRow + go);
            cpa16(sb + ST_ALO + so, Alo + aRow + go);
            cpa16(sb + ST_BHI + so, Bhi + bRow + go);
            cpa16(sb + ST_BLO + so, Blo + bRow + go);
        }
        cpa_commit();
    };

    PIPE_MAIN3(K, load_stage);

    int g = lane >> 2, tig = lane & 3;
#pragma unroll
    for (int tm = 0; tm < 4; tm++) {
        int r0 = bm + wr * 64 + tm * 16 + g;
#pragma unroll
        for (int tn = 0; tn < 4; tn++) {
            int col = bn + wc * 32 + tn * 8 + 2 * tig;
            float b0 = bias[col], b1 = bias[col + 1];
            float v0 = acc[tm][tn][0] + b0, v1 = acc[tm][tn][1] + b1;
            float v2 = acc[tm][tn][2] + b0, v3 = acc[tm][tn][3] + b1;
            if (EPI >= 1) {
                v0 = fmaxf(v0, 0.f); v1 = fmaxf(v1, 0.f);
                v2 = fmaxf(v2, 0.f); v3 = fmaxf(v3, 0.f);
            }
            if (r0 < M) {
                size_t o = (size_t)r0 * Nc + col;
                if (EPI != 2) { float2 t = {v0, v1}; *(float2*)&C[o] = t; }
                else {
                    bf16 h0 = __float2bfloat16_rn(v0), h1 = __float2bfloat16_rn(v1);
                    __nv_bfloat162 hp = __halves2bfloat162(h0, h1);
                    *(uint32_t*)&Chi[o] = *(uint32_t*)&hp;
                    *(uint32_t*)&Clo[o] = pack_bf2(v0 - __bfloat162float(h0), v1 - __bfloat162float(h1));
                }
            }
            if (r0 + 8 < M) {
                size_t o = (size_t)(r0 + 8) * Nc + col;
                if (EPI != 2) { float2 t = {v2, v3}; *(float2*)&C[o] = t; }
                else {
                    bf16 h2 = __float2bfloat16_rn(v2), h3 = __float2bfloat16_rn(v3);
                    __nv_bfloat162 hp = __halves2bfloat162(h2, h3);
                    *(uint32_t*)&Chi[o] = *(uint32_t*)&hp;
                    *(uint32_t*)&Clo[o] = pack_bf2(v2 - __bfloat162float(h2), v3 - __bfloat162float(h3));
                }
            }
        }
    }
}

// ------------------------- Ce GEMM with fused edge epilogue (2-stage, runtime K) -------------------------
template<int WRITE_EH>
__global__ __launch_bounds__(256) void gemm_ce_fused(
    const bf16* __restrict__ Ahi, const bf16* __restrict__ Alo,
    const bf16* __restrict__ Bhi, const bf16* __restrict__ Blo,
    const float* __restrict__ bias, float* __restrict__ EHout, int K)
{
    const int M = Ee, Nc = 256;
    extern __shared__ __align__(16) char smem[];
    uint32_t sbase0 = (uint32_t)__cvta_generic_to_shared(smem);

    int tid = threadIdx.x, lane = tid & 31, w = tid >> 5;
    int wr = w >> 2, wc = w & 3;
    int bm = blockIdx.y * 128, bn = blockIdx.x * 128;

    int r = tid >> 1, ch0 = (tid & 1) * 2;
    int gr = bm + r; if (gr >= M) gr = M - 1;
    size_t aRow = (size_t)gr * K;
    size_t bRow = (size_t)(bn + r) * K;

    float acc[4][4][4];
#pragma unroll
    for (int i = 0; i < 4; i++)
#pragma unroll
        for (int j = 0; j < 4; j++)
#pragma unroll
            for (int q = 0; q < 4; q++) acc[i][j][q] = 0.f;

    auto load_stage = [&](uint32_t sb, int k0) {
#pragma unroll
        for (int i = 0; i < 2; i++) {
            int ch = ch0 + i;
            uint32_t so = sw_off(r, ch);
            size_t go = (size_t)k0 + ch * 8;
            cpa16(sb + so,          Ahi + aRow + go);
            cpa16(sb + ST_ALO + so, Alo + aRow + go);
            cpa16(sb + ST_BHI + so, Bhi + bRow + go);
            cpa16(sb + ST_BLO + so, Blo + bRow + go);
        }
        cpa_commit();
    };

    PIPE_MAIN2(K, load_stage);

    int g = lane >> 2, tig = lane & 3;
    float ls[4][2], lq[4][2];
    if (WRITE_EH) {
#pragma unroll
        for (int tn = 0; tn < 4; tn++) { ls[tn][0] = ls[tn][1] = lq[tn][0] = lq[tn][1] = 0.f; }
    }

#pragma unroll
    for (int tm = 0; tm < 4; tm++) {
#pragma unroll
        for (int half = 0; half < 2; half++) {
            int e = bm + wr * 64 + tm * 16 + g + 8 * half;
            if (e < M) {
                int sN = g_src[e], dN = g_dst[e];
                const float* Drow = g_ABDE + (size_t)dN * 1024 + 512;
                const float* Erow = g_ABDE + (size_t)sN * 1024 + 768;
                const float* Brow = g_ABDE + (size_t)sN * 1024 + 256;
                float* nrow = g_num + (size_t)dN * Hh;
                float* drow = g_den + (size_t)dN * Hh;
#pragma unroll
                for (int tn = 0; tn < 4; tn++) {
                    int col = bn + wc * 32 + tn * 8 + 2 * tig;
                    float2 dv = *(const float2*)&Drow[col];
                    float2 ev = *(const float2*)&Erow[col];
                    float2 bv = *(const float2*)&Brow[col];
                    float eh0 = acc[tm][tn][2 * half + 0] + bias[col]     + dv.x + ev.x;
                    float eh1 = acc[tm][tn][2 * half + 1] + bias[col + 1] + dv.y + ev.y;
                    float sg0 = 1.f / (1.f + __expf(-eh0));
                    float sg1 = 1.f / (1.f + __expf(-eh1));
                    atomicAdd(&nrow[col],     sg0 * bv.x);
                    atomicAdd(&nrow[col + 1], sg1 * bv.y);
                    atomicAdd(&drow[col],     sg0);
                    atomicAdd(&drow[col + 1], sg1);
                    if (WRITE_EH) {
                        float2 t = {eh0, eh1};
                        *(float2*)&EHout[(size_t)e * Nc + col] = t;
                        ls[tn][0] += eh0; ls[tn][1] += eh1;
                        lq[tn][0] += eh0 * eh0; lq[tn][1] += eh1 * eh1;
                    }
                }
            }
        }
    }

    if (WRITE_EH) {
#pragma unroll
        for (int tn = 0; tn < 4; tn++) {
#pragma unroll
            for (int j = 0; j < 2; j++) {
                float v = ls[tn][j], q = lq[tn][j];
#pragma unroll
                for (int off = 4; off <= 16; off <<= 1) {
                    v += __shfl_xor_sync(0xFFFFFFFFu, v, off);
                    q += __shfl_xor_sync(0xFFFFFFFFu, q, off);
                }
                if (g == 0) {
                    int col = bn + wc * 32 + tn * 8 + 2 * tig + j;
                    atomicAdd(&g_stats[2 * Hh + col], v);
                    atomicAdd(&g_stats[3 * Hh + col], q);
                }
            }
        }
    }
}

// ------------------------- decoder gather-GEMM with fused dec2 (2-stage) -------------------------
__global__ __launch_bounds__(256) void gemm_dec_fused(
    const float* __restrict__ bias, const float* __restrict__ w2,
    float* __restrict__ out)
{
    const int K = K_DEC, M = Ee;
    extern __shared__ __align__(16) char smem[];
    uint32_t sbase0 = (uint32_t)__cvta_generic_to_shared(smem);

    int tid = threadIdx.x, lane = tid & 31, w = tid >> 5;
    int wr = w >> 2, wc = w & 3;
    int bm = blockIdx.y * 128, bn = blockIdx.x * 128;

    int r = tid >> 1, ch0 = (tid & 1) * 2;
    int e = bm + r; if (e >= M) e = M - 1;
    int sN = g_src[e], dN = g_dst[e];
    size_t bRow = (size_t)(bn + r) * K;

    float acc[4][4][4];
#pragma unroll
    for (int i = 0; i < 4; i++)
#pragma unroll
        for (int j = 0; j < 4; j++)
#pragma unroll
            for (int q = 0; q < 4; q++) acc[i][j][q] = 0.f;

    auto load_stage = [&](uint32_t sb, int k0) {
#pragma unroll
        for (int i = 0; i < 2; i++) {
            int ch = ch0 + i;
            uint32_t so = sw_off(r, ch);
            int c0 = k0 + ch * 8;
            const bf16 *ph, *pl;
            if (c0 < 256)      { ph = g_xh + (size_t)sN * Hh + c0;        pl = g_xl + (size_t)sN * Hh + c0; }
            else if (c0 < 512) { ph = g_xh + (size_t)dN * Hh + (c0-256);  pl = g_xl + (size_t)dN * Hh + (c0-256); }
            else               { ph = g_afh + (size_t)e * 32 + (c0-512);  pl = g_afl + (size_t)e * 32 + (c0-512); }
            cpa16(sb + so,          ph);
            cpa16(sb + ST_ALO + so, pl);
            cpa16(sb + ST_BHI + so, g_d1_hi + bRow + c0);
            cpa16(sb + ST_BLO + so, g_d1_lo + bRow + c0);
        }
        cpa_commit();
    };

    PIPE_MAIN2(K, load_stage);

    int g = lane >> 2, tig = lane & 3;
#pragma unroll
    for (int tm = 0; tm < 4; tm++) {
        int r0 = bm + wr * 64 + tm * 16 + g;
        float p0 = 0.f, p1 = 0.f;
#pragma unroll
        for (int tn = 0; tn < 4; tn++) {
            int col = bn + wc * 32 + tn * 8 + 2 * tig;
            float b0 = bias[col], b1 = bias[col + 1];
            float w0 = w2[col], w1 = w2[col + 1];
            p0 += fmaxf(acc[tm][tn][0] + b0, 0.f) * w0 + fmaxf(acc[tm][tn][1] + b1, 0.f) * w1;
            p1 += fmaxf(acc[tm][tn][2] + b0, 0.f) * w0 + fmaxf(acc[tm][tn][3] + b1, 0.f) * w1;
        }
        p0 += __shfl_xor_sync(0xFFFFFFFFu, p0, 1);
        p0 += __shfl_xor_sync(0xFFFFFFFFu, p0, 2);
        p1 += __shfl_xor_sync(0xFFFFFFFFu, p1, 1);
        p1 += __shfl_xor_sync(0xFFFFFFFFu, p1, 2);
        if (tig == 0) {
            if (r0 < M)     atomicAdd(&out[g_eorig[r0]], p0);
            if (r0 + 8 < M) atomicAdd(&out[g_eorig[r0 + 8]], p1);
        }
    }
}

// ------------------------- edge projection (K=8, sorted order) -------------------------
__global__ void k_eproj(const float* __restrict__ af, const float* __restrict__ W,
                        const float* __restrict__ b) {
    size_t idx = (size_t)blockIdx.x * blockDim.x + threadIdx.x;
    if (idx < (size_t)Ee * Hh) {
        int c = (int)(idx & 255);
        size_t e = idx >> 8;
        size_t eo = (size_t)g_eorig[e];
        float v = b[c];
#pragma unroll
        for (int k = 0; k < 8; k++) v += af[eo * 8 + k] * W[k * Hh + c];
        split_write(v, g_eh, g_el, idx);
    }
}

// ------------------------- per-layer node kernels -------------------------
__global__ __launch_bounds__(256) void k_node() {
    int c = threadIdx.x;
    int base = blockIdx.x * 32;
    float s = 0.f, sq = 0.f;
    for (int i = 0; i < 32; i++) {
        int n = base + i;
        size_t o = (size_t)n * Hh + c;
        float xc = g_ABDE[(size_t)n * 1024 + c] + g_num[o] / (g_den[o] + AGG_EPS);
        g_num[o] = xc;
        s += xc; sq += xc * xc;
    }
    atomicAdd(&g_stats[c], s);
    atomicAdd(&g_stats[Hh + c], sq);
}

__global__ void k_apply_x(const float* __restrict__ gam, const float* __restrict__ bet) {
    size_t idx = (size_t)blockIdx.x * blockDim.x + threadIdx.x;
    if (idx < (size_t)Nn * Hh) {
        int c = (int)(idx & 255);
        float mu = g_stats[c] * (1.f / Nn);
        float var = g_stats[Hh + c] * (1.f / Nn) - mu * mu;
        float v = gam[c] * (g_num[idx] - mu) * rsqrtf(var + BN_EPS) + bet[c];
        float old = __bfloat162float(g_xh[idx]) + __bfloat162float(g_xl[idx]);
        float o = old + fmaxf(v, 0.f);
        split_write(o, g_xh, g_xl, idx);
    }
}

__global__ void k_apply_e(const float* __restrict__ ehat,
                          const float* __restrict__ gam, const float* __restrict__ bet) {
    size_t idx = (size_t)blockIdx.x * blockDim.x + threadIdx.x;
    if (idx < (size_t)Ee * Hh) {
        int c = (int)(idx & 255);
        float mu = g_stats[2 * Hh + c] * (1.f / Ee);
        float var = g_stats[3 * Hh + c] * (1.f / Ee) - mu * mu;
        float v = gam[c] * (ehat[idx] - mu) * rsqrtf(var + BN_EPS) + bet[c];
        float old = __bfloat162float(g_eh[idx]) + __bfloat162float(g_el[idx]);
        float o = old + fmaxf(v, 0.f);
        split_write(o, g_eh, g_el, idx);
    }
}

// ------------------------- host launcher -------------------------
extern "C" void kernel_launch(void* const* d_in, const int* in_sizes, int n_in,
                              void* d_out, int out_size)
{
    int wb = 3;
    for (int i = 3; i < n_in && i < 6; i++) {
        if (in_sizes[i] == 2 * Hh * Hh) { wb = i; break; }
    }

    const void*  eidx = d_in[0];
    const float* af   = (const float*)d_in[1];
    const float* hold = (const float*)d_in[2];
    const float* fw   = (const float*)d_in[wb + 0];
    const float* fb   = (const float*)d_in[wb + 1];
    const float* epw  = (const float*)d_in[wb + 2];
    const float* epb  = (const float*)d_in[wb + 3];
    const float* Aw   = (const float*)d_in[wb + 4];
    const float* Ab   = (const float*)d_in[wb + 5];
    const float* Bw   = (const float*)d_in[wb + 6];
    const float* Bb   = (const float*)d_in[wb + 7];
    const float* Cw   = (const float*)d_in[wb + 8];
    const float* Cb   = (const float*)d_in[wb + 9];
    const float* Dw   = (const float*)d_in[wb + 10];
    const float* Db   = (const float*)d_in[wb + 11];
    const float* Ew   = (const float*)d_in[wb + 12];
    const float* Eb   = (const float*)d_in[wb + 13];
    const float* bxg  = (const float*)d_in[wb + 14];
    const float* bxb  = (const float*)d_in[wb + 15];
    const float* beg  = (const float*)d_in[wb + 16];
    const float* beb  = (const float*)d_in[wb + 17];
    const float* d1w  = (const float*)d_in[wb + 18];
    const float* d1b  = (const float*)d_in[wb + 19];
    const float* d2w  = (const float*)d_in[wb + 20];
    const float* d2b  = (const float*)d_in[wb + 21];

    float *abde, *ce, *nump, *denp, *statsp, *bpackp, *fbiasp, *b0pp;
    bf16 *abde_hi, *abde_lo, *c_hi, *c_lo, *fw_hi, *fw_lo, *w0p_hi, *w0p_lo;
    bf16 *xh, *xl, *eh, *el, *hh, *hl, *afh, *afl;
    int *histp;
    cudaGetSymbolAddress((void**)&abde, g_ABDE);
    cudaGetSymbolAddress((void**)&ce, g_Ce);
    cudaGetSymbolAddress((void**)&nump, g_num);
    cudaGetSymbolAddress((void**)&denp, g_den);
    cudaGetSymbolAddress((void**)&statsp, g_stats);
    cudaGetSymbolAddress((void**)&bpackp, g_bpack);
    cudaGetSymbolAddress((void**)&fbiasp, g_fbias);
    cudaGetSymbolAddress((void**)&b0pp, g_b0p);
    cudaGetSymbolAddress((void**)&abde_hi, g_abde_hi);
    cudaGetSymbolAddress((void**)&abde_lo, g_abde_lo);
    cudaGetSymbolAddress((void**)&c_hi, g_c_hi);
    cudaGetSymbolAddress((void**)&c_lo, g_c_lo);
    cudaGetSymbolAddress((void**)&fw_hi, g_fw_hi);
    cudaGetSymbolAddress((void**)&fw_lo, g_fw_lo);
    cudaGetSymbolAddress((void**)&w0p_hi, g_w0p_hi);
    cudaGetSymbolAddress((void**)&w0p_lo, g_w0p_lo);
    cudaGetSymbolAddress((void**)&xh, g_xh);
    cudaGetSymbolAddress((void**)&xl, g_xl);
    cudaGetSymbolAddress((void**)&eh, g_eh);
    cudaGetSymbolAddress((void**)&el, g_el);
    cudaGetSymbolAddress((void**)&hh, g_hh);
    cudaGetSymbolAddress((void**)&hl, g_hl);
    cudaGetSymbolAddress((void**)&afh, g_afh);
    cudaGetSymbolAddress((void**)&afl, g_afl);
    cudaGetSymbolAddress((void**)&histp, g_hist);

    cudaFuncSetAttribute(gemm_tc2<0>, cudaFuncAttributeMaxDynamicSharedMemorySize, SMEM3);
    cudaFuncSetAttribute(gemm_tc2<2>, cudaFuncAttributeMaxDynamicSharedMemorySize, SMEM3);
    cudaFuncSetAttribute(gemm_ce_fused<0>, cudaFuncAttributeMaxDynamicSharedMemorySize, SMEM2);
    cudaFuncSetAttribute(gemm_ce_fused<1>, cudaFuncAttributeMaxDynamicSharedMemorySize, SMEM2);
    cudaFuncSetAttribute(gemm_dec_fused, cudaFuncAttributeMaxDynamicSharedMemorySize, SMEM2);

    // --- prep: sort edges by dst, split weights/activations ---
    cudaMemsetAsync(histp, 0, Nn * sizeof(int));
    k_detect_idx<<<1, 256>>>((const unsigned int*)eidx);
    k_convert_idx<<<(Ee + 255) / 256, 256>>>(eidx);      // also builds histogram
    k_scan<<<1, 1024>>>();
    k_scatter<<<(Ee + 255) / 256, 256>>>();
    {
        int mg = MB0 + MB1 + MB2 + MB3 + MB4 + MB5 + MB6;
        k_megaprep<<<mg, 256>>>(Ab, Bb, Db, Eb, fw, fb, Cw, d1w, hold, af);
    }
    {
        size_t tw = (size_t)Ll * 1024 * 256;
        k_split_abde<<<(int)((tw + 255) / 256), 256>>>(Aw, Bw, Dw, Ew);
    }
    k_w0prime<<<32, 256>>>(epw, epb, Cw, Cb);
    {
        dim3 grid(Hh / 128, (Nn + 127) / 128);
        gemm_tc2<2><<<grid, 256, SMEM3>>>(hh, hl, fw_hi, fw_lo, fbiasp,
                                          nullptr, xh, xl, Nn, Hh, Hh);
    }
    k_eproj<<<(int)(((size_t)Ee * Hh + 255) / 256), 256>>>(af, epw, epb);
    k_init_out<<<(Ee + 255) / 256, 256>>>((float*)d_out, d2b);

    for (int l = 0; l < Ll; l++) {
        cudaMemsetAsync(nump, 0, (size_t)Nn * Hh * sizeof(float));
        cudaMemsetAsync(denp, 0, (size_t)Nn * Hh * sizeof(float));
        cudaMemsetAsync(statsp, 0, 4 * Hh * sizeof(float));

        {   // fused A|B|D|E GEMM: [N,256] @ [256,1024]
            dim3 grid(4 * Hh / 128, (Nn + 127) / 128);
            gemm_tc2<0><<<grid, 256, SMEM3>>>(xh, xl,
                                              abde_hi + (size_t)l * 1024 * 256,
                                              abde_lo + (size_t)l * 1024 * 256,
                                              bpackp + l * 4 * Hh, abde, nullptr, nullptr,
                                              Nn, Hh, 4 * Hh);
        }
        {   // Ce GEMM + fused edge phase; layer 0 uses the rank-8 collapsed form (K=32)
            dim3 grid(2, (Ee + 127) / 128);
            if (l == 0)
                gemm_ce_fused<1><<<grid, 256, SMEM2>>>(afh, afl, w0p_hi, w0p_lo,
                                                       b0pp, ce, 32);
            else if (l < Ll - 1)
                gemm_ce_fused<1><<<grid, 256, SMEM2>>>(eh, el,
                                                       c_hi + (size_t)l * Hh * Hh,
                                                       c_lo + (size_t)l * Hh * Hh,
                                                       Cb + l * Hh, ce, 256);
            else
                gemm_ce_fused<0><<<grid, 256, SMEM2>>>(eh, el,
                                                       c_hi + (size_t)l * Hh * Hh,
                                                       c_lo + (size_t)l * Hh * Hh,
                                                       Cb + l * Hh, ce, 256);
        }
        k_node<<<Nn / 32, 256>>>();
        k_apply_x<<<(int)(((size_t)Nn * Hh + 255) / 256), 256>>>(bxg + l * Hh, bxb + l * Hh);
        if (l < Ll - 1)  // e dead after last layer
            k_apply_e<<<(int)(((size_t)Ee * Hh + 255) / 256), 256>>>(ce, beg + l * Hh, beb + l * Hh);
    }

    // --- decoder (dec1 GEMM with fused dec2 dot-product epilogue) ---
    {
        dim3 grid(2, (Ee + 127) / 128);
        gemm_dec_fused<<<grid, 256, SMEM2>>>(d1b, d2w, (float*)d_out);
    }
}

// round 13
// speedup vs baseline: 1.0092x; 1.0092x over previous
#include <cuda_runtime.h>
#include <cuda_bf16.h>
#include <math.h>
#include <stdint.h>

// Problem constants
#define Hh 256
#define Ll 4
#define Nn 100000
#define Ee 300000
#define BN_EPS 1e-5f
#define AGG_EPS 1e-6f
#define K_DEC 544   // 520 padded to multiple of 32

typedef __nv_bfloat16 bf16;

// ------------------------- static device scratch -------------------------
__device__ float g_ABDE[(size_t)Nn * 4 * Hh];   // [N,1024]: A|B|D|E
__device__ float g_Ce[(size_t)Ee * Hh];         // e_hat scratch (sorted edge order)
__device__ float g_num[(size_t)Nn * Hh];
__device__ float g_den[(size_t)Nn * Hh];
__device__ float g_stats[4 * Hh];
__device__ float g_bpack[Ll * 4 * Hh];
__device__ float g_fbias[Hh];
__device__ float g_b0p[Hh];                     // layer-0 collapsed Ce bias
__device__ int   g_src[Ee];     // sorted by dst
__device__ int   g_dst[Ee];     // sorted (non-decreasing)
__device__ int   g_eorig[Ee];   // sorted pos -> original edge id
__device__ int   g_srcO[Ee];
__device__ int   g_dstO[Ee];
__device__ int   g_hist[Nn];
__device__ int   g_idx64;

// split bf16 weights, transposed to [N][K]
__device__ bf16 g_abde_hi[(size_t)Ll * 1024 * 256];
__device__ bf16 g_abde_lo[(size_t)Ll * 1024 * 256];
__device__ bf16 g_c_hi[(size_t)Ll * 256 * 256];
__device__ bf16 g_c_lo[(size_t)Ll * 256 * 256];
__device__ bf16 g_fw_hi[256 * 256];
__device__ bf16 g_fw_lo[256 * 256];
__device__ bf16 g_d1_hi[256 * K_DEC];
__device__ bf16 g_d1_lo[256 * K_DEC];
__device__ bf16 g_w0p_hi[256 * 32];             // layer-0 collapsed Ce weight [n][32]
__device__ bf16 g_w0p_lo[256 * 32];

// split bf16 activations (x/e live ONLY here; e in sorted edge order)
__device__ bf16 g_xh[(size_t)Nn * Hh];
__device__ bf16 g_xl[(size_t)Nn * Hh];
__device__ bf16 g_eh[(size_t)Ee * Hh];
__device__ bf16 g_el[(size_t)Ee * Hh];
__device__ bf16 g_hh[(size_t)Nn * Hh];
__device__ bf16 g_hl[(size_t)Nn * Hh];
__device__ bf16 g_afh[(size_t)Ee * 32];
__device__ bf16 g_afl[(size_t)Ee * 32];

// ------------------------- prep kernels -------------------------
__global__ void k_detect_idx(const unsigned int* __restrict__ w) {
    unsigned int s = 0;
    for (int i = threadIdx.x; i < 1024; i += 256) s |= w[2 * i + 1];
#pragma unroll
    for (int off = 16; off; off >>= 1) s |= __shfl_xor_sync(0xFFFFFFFFu, s, off);
    __shared__ unsigned int red[8];
    if ((threadIdx.x & 31) == 0) red[threadIdx.x >> 5] = s;
    __syncthreads();
    if (threadIdx.x == 0) {
        unsigned int t = 0;
        for (int i = 0; i < 8; i++) t |= red[i];
        g_idx64 = (t == 0u) ? 1 : 0;
    }
}

__global__ void k_convert_idx(const void* __restrict__ eidx) {
    int i = blockIdx.x * blockDim.x + threadIdx.x;
    if (i < Ee) {
        int s, d;
        if (g_idx64) {
            const long long* p = (const long long*)eidx;
            s = (int)p[i];
            d = (int)p[(size_t)Ee + i];
        } else {
            const int* p = (const int*)eidx;
            s = p[i];
            d = p[Ee + i];
        }
        g_srcO[i] = s;
        g_dstO[i] = d;
        atomicAdd(&g_hist[d], 1);
    }
}

__global__ __launch_bounds__(1024) void k_scan() {
    __shared__ int part[1024];
    int t = threadIdx.x;
    const int CH = (Nn + 1023) / 1024;
    int base = t * CH;
    int s = 0;
    for (int j = 0; j < CH; j++) {
        int b = base + j;
        if (b < Nn) s += g_hist[b];
    }
    part[t] = s;
    __syncthreads();
    if (t == 0) {
        int acc = 0;
        for (int i = 0; i < 1024; i++) { int v = part[i]; part[i] = acc; acc += v; }
    }
    __syncthreads();
    int acc = part[t];
    for (int j = 0; j < CH; j++) {
        int b = base + j;
        if (b < Nn) { int v = g_hist[b]; g_hist[b] = acc; acc += v; }
    }
}

__global__ void k_scatter() {
    int i = blockIdx.x * blockDim.x + threadIdx.x;
    if (i < Ee) {
        int d = g_dstO[i];
        int pos = atomicAdd(&g_hist[d], 1);
        g_src[pos] = g_srcO[i];
        g_dst[pos] = d;
        g_eorig[pos] = i;
    }
}

__device__ __forceinline__ void split_write(float v, bf16* hi, bf16* lo, size_t i) {
    bf16 h = __float2bfloat16_rn(v);
    hi[i] = h;
    lo[i] = __float2bfloat16_rn(v - __bfloat162float(h));
}

__global__ void k_split_abde(const float* __restrict__ Aw, const float* __restrict__ Bw,
                             const float* __restrict__ Dw, const float* __restrict__ Ew) {
    size_t i = (size_t)blockIdx.x * 256 + threadIdx.x;
    if (i < (size_t)Ll * 1024 * 256) {
        int k = (int)(i & 255);
        int n = (int)((i >> 8) & 1023);
        int l = (int)(i >> 18);
        const float* W = (n < 256) ? Aw : (n < 512) ? Bw : (n < 768) ? Dw : Ew;
        float v = W[(size_t)l * 65536 + (size_t)k * 256 + (n & 255)];
        split_write(v, g_abde_hi, g_abde_lo, i);
    }
}

// layer-0 collapsed Ce: W0'[k8][n] = sum_m epw[k8][m] * C0[m][n]; b0' = epb@C0 + C0b
__global__ void k_w0prime(const float* __restrict__ epw, const float* __restrict__ epb,
                          const float* __restrict__ C0, const float* __restrict__ C0b) {
    int i = blockIdx.x * 256 + threadIdx.x;
    int n = i >> 5, k = i & 31;
    float v = 0.f;
    if (k < 8) {
        for (int m = 0; m < 256; m++) v += epw[k * 256 + m] * C0[(size_t)m * 256 + n];
    }
    split_write(v, g_w0p_hi, g_w0p_lo, (size_t)n * 32 + k);
    if (k == 0) {
        float b = C0b[n];
        for (int m = 0; m < 256; m++) b += epb[m] * C0[(size_t)m * 256 + n];
        g_b0p[n] = b;
    }
}

// block-range partitioned prep (af split uses g_eorig -> run AFTER scatter)
#define MB0 16
#define MB1 1
#define MB2 256
#define MB3 1024
#define MB4 576
#define MB5 100000
#define MB6 75000
__global__ void k_megaprep(
    const float* __restrict__ Ab, const float* __restrict__ Bb,
    const float* __restrict__ Db, const float* __restrict__ Eb,
    const float* __restrict__ fw, const float* __restrict__ fb,
    const float* __restrict__ Cw, const float* __restrict__ d1w,
    const float* __restrict__ hold, const float* __restrict__ af)
{
    int b = blockIdx.x, t = threadIdx.x;
    if (b < MB0) {
        int i = b * 256 + t;
        if (i < Ll * 4 * Hh) {
            int j4 = i % (4 * Hh);
            int l = i / (4 * Hh);
            int which = j4 >> 8, j = j4 & 255;
            const float* B = (which == 0) ? Ab : (which == 1) ? Bb : (which == 2) ? Db : Eb;
            g_bpack[i] = B[l * Hh + j];
        }
        return;
    }
    b -= MB0;
    if (b < MB1) {
        float s = fb[t];
        for (int k = 0; k < Hh; k++) s += fw[(size_t)k * Hh + t];
        g_fbias[t] = s;
        return;
    }
    b -= MB1;
    if (b < MB2) {
        int i = b * 256 + t;
        int k = i & 255, n = i >> 8;
        split_write(fw[(size_t)(Hh + k) * Hh + n], g_fw_hi, g_fw_lo, i);
        return;
    }
    b -= MB2;
    if (b < MB3) {
        size_t i = (size_t)b * 256 + t;
        int k = (int)(i & 255), n = (int)((i >> 8) & 255), l = (int)(i >> 16);
        split_write(Cw[(size_t)l * 65536 + (size_t)k * 256 + n], g_c_hi, g_c_lo, i);
        return;
    }
    b -= MB3;
    if (b < MB4) {
        int i = b * 256 + t;
        if (i < 256 * K_DEC) {
            int k = i % K_DEC, n = i / K_DEC;
            float v = (k < 520) ? d1w[(size_t)k * 256 + n] : 0.0f;
            split_write(v, g_d1_hi, g_d1_lo, i);
        }
        return;
    }
    b -= MB4;
    if (b < MB5) {
        size_t i = (size_t)b * 256 + t;
        if (i < (size_t)Nn * Hh) split_write(hold[i], g_hh, g_hl, i);
        return;
    }
    b -= MB5;
    {
        size_t i = (size_t)b * 256 + t;
        if (i < (size_t)Ee * 32) {
            int c = (int)(i & 31);
            size_t e = i >> 5;
            float v = (c < 8) ? af[(size_t)g_eorig[e] * 8 + c] : 0.0f;
            split_write(v, g_afh, g_afl, i);
        }
    }
}

__global__ void k_init_out(float* __restrict__ out, const float* __restrict__ b2) {
    int i = blockIdx.x * blockDim.x + threadIdx.x;
    if (i < Ee) out[i] = b2[0];
}

// ------------------------- tensor-core machinery -------------------------
__device__ __forceinline__ void mma16816(float* c, const uint32_t* a, const uint32_t* b) {
    asm volatile(
        "mma.sync.aligned.m16n8k16.row.col.f32.bf16.bf16.f32 "
        "{%0,%1,%2,%3}, {%4,%5,%6,%7}, {%8,%9}, {%0,%1,%2,%3};"
        : "+f"(c[0]), "+f"(c[1]), "+f"(c[2]), "+f"(c[3])
        : "r"(a[0]), "r"(a[1]), "r"(a[2]), "r"(a[3]), "r"(b[0]), "r"(b[1]));
}
__device__ __forceinline__ void ldm_x4(uint32_t* r, uint32_t addr) {
    asm volatile("ldmatrix.sync.aligned.m8n8.x4.shared.b16 {%0,%1,%2,%3}, [%4];"
                 : "=r"(r[0]), "=r"(r[1]), "=r"(r[2]), "=r"(r[3]) : "r"(addr));
}
__device__ __forceinline__ void ldm_x2(uint32_t* r, uint32_t addr) {
    asm volatile("ldmatrix.sync.aligned.m8n8.x2.shared.b16 {%0,%1}, [%2];"
                 : "=r"(r[0]), "=r"(r[1]) : "r"(addr));
}
__device__ __forceinline__ void cpa16(uint32_t s, const void* g) {
    asm volatile("cp.async.cg.shared.global [%0], [%1], 16;" :: "r"(s), "l"(g));
}
__device__ __forceinline__ void cpa_commit() { asm volatile("cp.async.commit_group;"); }
template<int N>
__device__ __forceinline__ void cpa_wait() { asm volatile("cp.async.wait_group %0;" :: "n"(N) : "memory"); }

__device__ __forceinline__ int sw_off(int row, int chunk) {
    return row * 64 + ((chunk ^ ((row >> 1) & 3)) << 4);
}

// pack/unpack two floats through one 64-bit shuffle
__device__ __forceinline__ unsigned long long pk2(float a, float b) {
    return (unsigned long long)__float_as_uint(a) | ((unsigned long long)__float_as_uint(b) << 32);
}
__device__ __forceinline__ void upk2(unsigned long long v, float& a, float& b) {
    a = __uint_as_float((unsigned int)v);
    b = __uint_as_float((unsigned int)(v >> 32));
}

#define ST_ALO 8192
#define ST_BHI 16384
#define ST_BLO 24576
#define ST_STRIDE 32768
#define SMEM3 (3 * ST_STRIDE)   // 96 KB (pure GEMM)
#define SMEM2 (2 * ST_STRIDE)   // 64 KB (gather kernels; keep L1)

// 3-pass bf16x3: one A fragment array reused
__device__ __forceinline__ void tile_compute(
    float acc[4][4][4], uint32_t sbase, int lane, int wr, int wc) {
    uint32_t sAhiB = sbase, sAloB = sbase + ST_ALO, sBhiB = sbase + ST_BHI, sBloB = sbase + ST_BLO;
#pragma unroll
    for (int kg = 0; kg < 2; kg++) {
        uint32_t ra[4][4], rbh[4][2], rbl[4][2];
#pragma unroll
        for (int tm = 0; tm < 4; tm++) {
            int row = wr * 64 + tm * 16 + (lane & 15);
            int ch = 2 * kg + (lane >> 4);
            ldm_x4(ra[tm], sAhiB + sw_off(row, ch));
        }
#pragma unroll
        for (int tn = 0; tn < 4; tn++) {
            int row = wc * 32 + tn * 8 + (lane & 7);
            int ch = 2 * kg + ((lane >> 3) & 1);
            uint32_t off = sw_off(row, ch);
            ldm_x2(rbh[tn], sBhiB + off);
            ldm_x2(rbl[tn], sBloB + off);
        }
#pragma unroll
        for (int tm = 0; tm < 4; tm++)
#pragma unroll
            for (int tn = 0; tn < 4; tn++) {
                mma16816(acc[tm][tn], ra[tm], rbh[tn]);
                mma16816(acc[tm][tn], ra[tm], rbl[tn]);
            }
#pragma unroll
        for (int tm = 0; tm < 4; tm++) {
            int row = wr * 64 + tm * 16 + (lane & 15);
            int ch = 2 * kg + (lane >> 4);
            ldm_x4(ra[tm], sAloB + sw_off(row, ch));
        }
#pragma unroll
        for (int tm = 0; tm < 4; tm++)
#pragma unroll
            for (int tn = 0; tn < 4; tn++)
                mma16816(acc[tm][tn], ra[tm], rbh[tn]);
    }
}

__device__ __forceinline__ uint32_t pack_bf2(float a, float b) {
    __nv_bfloat162 t = __floats2bfloat162_rn(a, b);
    return *(uint32_t*)&t;
}

// 3-stage mainloop (pure GEMM kernels)
#define PIPE_MAIN3(K, LOADER) do { \
    LOADER(sbase0, 0); \
    if ((K) > 32) LOADER(sbase0 + ST_STRIDE, 32); else cpa_commit(); \
    for (int k0 = 0, st = 0; k0 < (K); k0 += 32, st = (st == 2) ? 0 : st + 1) { \
        cpa_wait<1>(); \
        __syncthreads(); \
        if (k0 + 64 < (K)) { \
            int st2 = st + 2; if (st2 >= 3) st2 -= 3; \
            LOADER(sbase0 + st2 * ST_STRIDE, k0 + 64); \
        } else cpa_commit(); \
        tile_compute(acc, sbase0 + st * ST_STRIDE, lane, wr, wc); \
    } \
} while (0)

// 2-stage mainloop (gather kernels; 64 KB smem -> L1 preserved)
#define PIPE_MAIN2(K, LOADER) do { \
    LOADER(sbase0, 0); \
    int cur = 0; \
    for (int k0 = 0; k0 < (K); k0 += 32) { \
        cpa_wait<0>(); \
        __syncthreads(); \
        if (k0 + 32 < (K)) LOADER(sbase0 + (cur ^ 1) * ST_STRIDE, k0 + 32); \
        tile_compute(acc, sbase0 + cur * ST_STRIDE, lane, wr, wc); \
        cur ^= 1; \
    } \
} while (0)

// ------------------------- bf16x3 GEMM, 3-stage pipeline -------------------------
// EPI: 0 = bias -> fp32 C; 2 = bias+relu -> bf16 hi/lo ONLY
template<int EPI>
__global__ __launch_bounds__(256) void gemm_tc2(
    const bf16* __restrict__ Ahi, const bf16* __restrict__ Alo,
    const bf16* __restrict__ Bhi, const bf16* __restrict__ Blo,
    const float* __restrict__ bias, float* __restrict__ C,
    bf16* __restrict__ Chi, bf16* __restrict__ Clo,
    int M, int K, int Nc)
{
    extern __shared__ __align__(16) char smem[];
    uint32_t sbase0 = (uint32_t)__cvta_generic_to_shared(smem);

    int tid = threadIdx.x, lane = tid & 31, w = tid >> 5;
    int wr = w >> 2, wc = w & 3;
    int bm = blockIdx.y * 128, bn = blockIdx.x * 128;

    int r = tid >> 1, ch0 = (tid & 1) * 2;
    int gr = bm + r; if (gr >= M) gr = M - 1;
    size_t aRow = (size_t)gr * K;
    size_t bRow = (size_t)(bn + r) * K;

    float acc[4][4][4];
#pragma unroll
    for (int i = 0; i < 4; i++)
#pragma unroll
        for (int j = 0; j < 4; j++)
#pragma unroll
            for (int q = 0; q < 4; q++) acc[i][j][q] = 0.f;

    auto load_stage = [&](uint32_t sb, int k0) {
#pragma unroll
        for (int i = 0; i < 2; i++) {
            int ch = ch0 + i;
            uint32_t so = sw_off(r, ch);
            size_t go = (size_t)k0 + ch * 8;
            cpa16(sb + so,          Ahi + aRow + go);
            cpa16(sb + ST_ALO + so, Alo + aRow + go);
            cpa16(sb + ST_BHI + so, Bhi + bRow + go);
            cpa16(sb + ST_BLO + so, Blo + bRow + go);
        }
        cpa_commit();
    };

    PIPE_MAIN3(K, load_stage);

    int g = lane >> 2, tig = lane & 3;
#pragma unroll
    for (int tm = 0; tm < 4; tm++) {
        int r0 = bm + wr * 64 + tm * 16 + g;
#pragma unroll
        for (int tn = 0; tn < 4; tn++) {
            int col = bn + wc * 32 + tn * 8 + 2 * tig;
            float b0 = bias[col], b1 = bias[col + 1];
            float v0 = acc[tm][tn][0] + b0, v1 = acc[tm][tn][1] + b1;
            float v2 = acc[tm][tn][2] + b0, v3 = acc[tm][tn][3] + b1;
            if (EPI >= 1) {
                v0 = fmaxf(v0, 0.f); v1 = fmaxf(v1, 0.f);
                v2 = fmaxf(v2, 0.f); v3 = fmaxf(v3, 0.f);
            }
            if (r0 < M) {
                size_t o = (size_t)r0 * Nc + col;
                if (EPI != 2) { float2 t = {v0, v1}; *(float2*)&C[o] = t; }
                else {
                    bf16 h0 = __float2bfloat16_rn(v0), h1 = __float2bfloat16_rn(v1);
                    __nv_bfloat162 hp = __halves2bfloat162(h0, h1);
                    *(uint32_t*)&Chi[o] = *(uint32_t*)&hp;
                    *(uint32_t*)&Clo[o] = pack_bf2(v0 - __bfloat162float(h0), v1 - __bfloat162float(h1));
                }
            }
            if (r0 + 8 < M) {
                size_t o = (size_t)(r0 + 8) * Nc + col;
                if (EPI != 2) { float2 t = {v2, v3}; *(float2*)&C[o] = t; }
                else {
                    bf16 h2 = __float2bfloat16_rn(v2), h3 = __float2bfloat16_rn(v3);
                    __nv_bfloat162 hp = __halves2bfloat162(h2, h3);
                    *(uint32_t*)&Chi[o] = *(uint32_t*)&hp;
                    *(uint32_t*)&Clo[o] = pack_bf2(v2 - __bfloat162float(h2), v3 - __bfloat162float(h3));
                }
            }
        }
    }
}

// ------------------------- Ce GEMM with fused edge epilogue (2-stage, runtime K) -------------------------
// Epilogue uses warp-segmented aggregation over the dst-sorted edges to cut num/den atomics ~2.5x.
template<int WRITE_EH>
__global__ __launch_bounds__(256) void gemm_ce_fused(
    const bf16* __restrict__ Ahi, const bf16* __restrict__ Alo,
    const bf16* __restrict__ Bhi, const bf16* __restrict__ Blo,
    const float* __restrict__ bias, float* __restrict__ EHout, int K)
{
    const int M = Ee, Nc = 256;
    const unsigned FULL = 0xFFFFFFFFu;
    extern __shared__ __align__(16) char smem[];
    uint32_t sbase0 = (uint32_t)__cvta_generic_to_shared(smem);

    int tid = threadIdx.x, lane = tid & 31, w = tid >> 5;
    int wr = w >> 2, wc = w & 3;
    int bm = blockIdx.y * 128, bn = blockIdx.x * 128;

    int r = tid >> 1, ch0 = (tid & 1) * 2;
    int gr = bm + r; if (gr >= M) gr = M - 1;
    size_t aRow = (size_t)gr * K;
    size_t bRow = (size_t)(bn + r) * K;

    float acc[4][4][4];
#pragma unroll
    for (int i = 0; i < 4; i++)
#pragma unroll
        for (int j = 0; j < 4; j++)
#pragma unroll
            for (int q = 0; q < 4; q++) acc[i][j][q] = 0.f;

    auto load_stage = [&](uint32_t sb, int k0) {
#pragma unroll
        for (int i = 0; i < 2; i++) {
            int ch = ch0 + i;
            uint32_t so = sw_off(r, ch);
            size_t go = (size_t)k0 + ch * 8;
            cpa16(sb + so,          Ahi + aRow + go);
            cpa16(sb + ST_ALO + so, Alo + aRow + go);
            cpa16(sb + ST_BHI + so, Bhi + bRow + go);
            cpa16(sb + ST_BLO + so, Blo + bRow + go);
        }
        cpa_commit();
    };

    PIPE_MAIN2(K, load_stage);

    int g = lane >> 2, tig = lane & 3;
    float ls[4][2], lq[4][2];
    if (WRITE_EH) {
#pragma unroll
        for (int tn = 0; tn < 4; tn++) { ls[tn][0] = ls[tn][1] = lq[tn][0] = lq[tn][1] = 0.f; }
    }

#pragma unroll
    for (int tm = 0; tm < 4; tm++) {
#pragma unroll
        for (int half = 0; half < 2; half++) {
            int e = bm + wr * 64 + tm * 16 + g + 8 * half;
            bool ok = e < M;
            int ec = ok ? e : (M - 1);
            int sN = g_src[ec], dN = g_dst[ec];
            int dkey = ok ? dN : (-1 - g);   // unique keys for invalid lanes: no merging
            const float* Drow = g_ABDE + (size_t)dN * 1024 + 512;
            const float* Erow = g_ABDE + (size_t)sN * 1024 + 768;
            const float* Brow = g_ABDE + (size_t)sN * 1024 + 256;
            float* nrow = g_num + (size_t)dN * Hh;
            float* drow = g_den + (size_t)dN * Hh;

            // segmented-run topology over the 8 g-lanes (monotone dst keys)
            int od1 = __shfl_down_sync(FULL, dkey, 4);
            int od2 = __shfl_down_sync(FULL, dkey, 8);
            int od4 = __shfl_down_sync(FULL, dkey, 16);
            int dup = __shfl_up_sync(FULL, dkey, 4);
            bool t1 = (g + 1 < 8) && (od1 == dkey);
            bool t2 = (g + 2 < 8) && (od2 == dkey);
            bool t4 = (g + 4 < 8) && (od4 == dkey);
            bool leader = ok && (g == 0 || dup != dkey);

#pragma unroll
            for (int tn = 0; tn < 4; tn++) {
                int col = bn + wc * 32 + tn * 8 + 2 * tig;
                float2 dv = *(const float2*)&Drow[col];
                float2 ev = *(const float2*)&Erow[col];
                float2 bv = *(const float2*)&Brow[col];
                float eh0 = acc[tm][tn][2 * half + 0] + bias[col]     + dv.x + ev.x;
                float eh1 = acc[tm][tn][2 * half + 1] + bias[col + 1] + dv.y + ev.y;
                float sg0 = 1.f / (1.f + __expf(-eh0));
                float sg1 = 1.f / (1.f + __expf(-eh1));
                float n0 = ok ? sg0 * bv.x : 0.f;
                float n1 = ok ? sg1 * bv.y : 0.f;
                float s0 = ok ? sg0 : 0.f;
                float s1 = ok ? sg1 : 0.f;

                if (WRITE_EH && ok) {
                    float2 t = {eh0, eh1};
                    *(float2*)&EHout[(size_t)e * Nc + col] = t;
                    ls[tn][0] += eh0; ls[tn][1] += eh1;
                    lq[tn][0] += eh0 * eh0; lq[tn][1] += eh1 * eh1;
                }

                // segmented suffix-sum across g-lanes (packed 64-bit shuffles)
                {
                    unsigned long long on = __shfl_down_sync(FULL, pk2(n0, n1), 4);
                    unsigned long long os = __shfl_down_sync(FULL, pk2(s0, s1), 4);
                    if (t1) { float a, b; upk2(on, a, b); n0 += a; n1 += b; upk2(os, a, b); s0 += a; s1 += b; }
                }
                {
                    unsigned long long on = __shfl_down_sync(FULL, pk2(n0, n1), 8);
                    unsigned long long os = __shfl_down_sync(FULL, pk2(s0, s1), 8);
                    if (t2) { float a, b; upk2(on, a, b); n0 += a; n1 += b; upk2(os, a, b); s0 += a; s1 += b; }
                }
                {
                    unsigned long long on = __shfl_down_sync(FULL, pk2(n0, n1), 16);
                    unsigned long long os = __shfl_down_sync(FULL, pk2(s0, s1), 16);
                    if (t4) { float a, b; upk2(on, a, b); n0 += a; n1 += b; upk2(os, a, b); s0 += a; s1 += b; }
                }
                if (leader) {
                    atomicAdd(&nrow[col],     n0);
                    atomicAdd(&nrow[col + 1], n1);
                    atomicAdd(&drow[col],     s0);
                    atomicAdd(&drow[col + 1], s1);
                }
            }
        }
    }

    if (WRITE_EH) {
#pragma unroll
        for (int tn = 0; tn < 4; tn++) {
#pragma unroll
            for (int j = 0; j < 2; j++) {
                float v = ls[tn][j], q = lq[tn][j];
#pragma unroll
                for (int off = 4; off <= 16; off <<= 1) {
                    v += __shfl_xor_sync(0xFFFFFFFFu, v, off);
                    q += __shfl_xor_sync(0xFFFFFFFFu, q, off);
                }
                if (g == 0) {
                    int col = bn + wc * 32 + tn * 8 + 2 * tig + j;
                    atomicAdd(&g_stats[2 * Hh + col], v);
                    atomicAdd(&g_stats[3 * Hh + col], q);
                }
            }
        }
    }
}

// ------------------------- decoder gather-GEMM with fused dec2 (2-stage) -------------------------
__global__ __launch_bounds__(256) void gemm_dec_fused(
    const float* __restrict__ bias, const float* __restrict__ w2,
    float* __restrict__ out)
{
    const int K = K_DEC, M = Ee;
    extern __shared__ __align__(16) char smem[];
    uint32_t sbase0 = (uint32_t)__cvta_generic_to_shared(smem);

    int tid = threadIdx.x, lane = tid & 31, w = tid >> 5;
    int wr = w >> 2, wc = w & 3;
    int bm = blockIdx.y * 128, bn = blockIdx.x * 128;

    int r = tid >> 1, ch0 = (tid & 1) * 2;
    int e = bm + r; if (e >= M) e = M - 1;
    int sN = g_src[e], dN = g_dst[e];
    size_t bRow = (size_t)(bn + r) * K;

    float acc[4][4][4];
#pragma unroll
    for (int i = 0; i < 4; i++)
#pragma unroll
        for (int j = 0; j < 4; j++)
#pragma unroll
            for (int q = 0; q < 4; q++) acc[i][j][q] = 0.f;

    auto load_stage = [&](uint32_t sb, int k0) {
#pragma unroll
        for (int i = 0; i < 2; i++) {
            int ch = ch0 + i;
            uint32_t so = sw_off(r, ch);
            int c0 = k0 + ch * 8;
            const bf16 *ph, *pl;
            if (c0 < 256)      { ph = g_xh + (size_t)sN * Hh + c0;        pl = g_xl + (size_t)sN * Hh + c0; }
            else if (c0 < 512) { ph = g_xh + (size_t)dN * Hh + (c0-256);  pl = g_xl + (size_t)dN * Hh + (c0-256); }
            else               { ph = g_afh + (size_t)e * 32 + (c0-512);  pl = g_afl + (size_t)e * 32 + (c0-512); }
            cpa16(sb + so,          ph);
            cpa16(sb + ST_ALO + so, pl);
            cpa16(sb + ST_BHI + so, g_d1_hi + bRow + c0);
            cpa16(sb + ST_BLO + so, g_d1_lo + bRow + c0);
        }
        cpa_commit();
    };

    PIPE_MAIN2(K, load_stage);

    int g = lane >> 2, tig = lane & 3;
#pragma unroll
    for (int tm = 0; tm < 4; tm++) {
        int r0 = bm + wr * 64 + tm * 16 + g;
        float p0 = 0.f, p1 = 0.f;
#pragma unroll
        for (int tn = 0; tn < 4; tn++) {
            int col = bn + wc * 32 + tn * 8 + 2 * tig;
            float b0 = bias[col], b1 = bias[col + 1];
            float w0 = w2[col], w1 = w2[col + 1];
            p0 += fmaxf(acc[tm][tn][0] + b0, 0.f) * w0 + fmaxf(acc[tm][tn][1] + b1, 0.f) * w1;
            p1 += fmaxf(acc[tm][tn][2] + b0, 0.f) * w0 + fmaxf(acc[tm][tn][3] + b1, 0.f) * w1;
        }
        p0 += __shfl_xor_sync(0xFFFFFFFFu, p0, 1);
        p0 += __shfl_xor_sync(0xFFFFFFFFu, p0, 2);
        p1 += __shfl_xor_sync(0xFFFFFFFFu, p1, 1);
        p1 += __shfl_xor_sync(0xFFFFFFFFu, p1, 2);
        if (tig == 0) {
            if (r0 < M)     atomicAdd(&out[g_eorig[r0]], p0);
            if (r0 + 8 < M) atomicAdd(&out[g_eorig[r0 + 8]], p1);
        }
    }
}

// ------------------------- edge projection (K=8, sorted order) -------------------------
__global__ void k_eproj(const float* __restrict__ af, const float* __restrict__ W,
                        const float* __restrict__ b) {
    size_t idx = (size_t)blockIdx.x * blockDim.x + threadIdx.x;
    if (idx < (size_t)Ee * Hh) {
        int c = (int)(idx & 255);
        size_t e = idx >> 8;
        size_t eo = (size_t)g_eorig[e];
        float v = b[c];
#pragma unroll
        for (int k = 0; k < 8; k++) v += af[eo * 8 + k] * W[k * Hh + c];
        split_write(v, g_eh, g_el, idx);
    }
}

// ------------------------- per-layer node kernels -------------------------
__global__ __launch_bounds__(256) void k_node() {
    int c = threadIdx.x;
    int base = blockIdx.x * 32;
    float s = 0.f, sq = 0.f;
    for (int i = 0; i < 32; i++) {
        int n = base + i;
        size_t o = (size_t)n * Hh + c;
        float xc = g_ABDE[(size_t)n * 1024 + c] + g_num[o] / (g_den[o] + AGG_EPS);
        g_num[o] = xc;
        s += xc; sq += xc * xc;
    }
    atomicAdd(&g_stats[c], s);
    atomicAdd(&g_stats[Hh + c], sq);
}

__global__ void k_apply_x(const float* __restrict__ gam, const float* __restrict__ bet) {
    size_t idx = (size_t)blockIdx.x * blockDim.x + threadIdx.x;
    if (idx < (size_t)Nn * Hh) {
        int c = (int)(idx & 255);
        float mu = g_stats[c] * (1.f / Nn);
        float var = g_stats[Hh + c] * (1.f / Nn) - mu * mu;
        float v = gam[c] * (g_num[idx] - mu) * rsqrtf(var + BN_EPS) + bet[c];
        float old = __bfloat162float(g_xh[idx]) + __bfloat162float(g_xl[idx]);
        float o = old + fmaxf(v, 0.f);
        split_write(o, g_xh, g_xl, idx);
    }
}

__global__ void k_apply_e(const float* __restrict__ ehat,
                          const float* __restrict__ gam, const float* __restrict__ bet) {
    size_t idx = (size_t)blockIdx.x * blockDim.x + threadIdx.x;
    if (idx < (size_t)Ee * Hh) {
        int c = (int)(idx & 255);
        float mu = g_stats[2 * Hh + c] * (1.f / Ee);
        float var = g_stats[3 * Hh + c] * (1.f / Ee) - mu * mu;
        float v = gam[c] * (ehat[idx] - mu) * rsqrtf(var + BN_EPS) + bet[c];
        float old = __bfloat162float(g_eh[idx]) + __bfloat162float(g_el[idx]);
        float o = old + fmaxf(v, 0.f);
        split_write(o, g_eh, g_el, idx);
    }
}

// ------------------------- host launcher -------------------------
extern "C" void kernel_launch(void* const* d_in, const int* in_sizes, int n_in,
                              void* d_out, int out_size)
{
    int wb = 3;
    for (int i = 3; i < n_in && i < 6; i++) {
        if (in_sizes[i] == 2 * Hh * Hh) { wb = i; break; }
    }

    const void*  eidx = d_in[0];
    const float* af   = (const float*)d_in[1];
    const float* hold = (const float*)d_in[2];
    const float* fw   = (const float*)d_in[wb + 0];
    const float* fb   = (const float*)d_in[wb + 1];
    const float* epw  = (const float*)d_in[wb + 2];
    const float* epb  = (const float*)d_in[wb + 3];
    const float* Aw   = (const float*)d_in[wb + 4];
    const float* Ab   = (const float*)d_in[wb + 5];
    const float* Bw   = (const float*)d_in[wb + 6];
    const float* Bb   = (const float*)d_in[wb + 7];
    const float* Cw   = (const float*)d_in[wb + 8];
    const float* Cb   = (const float*)d_in[wb + 9];
    const float* Dw   = (const float*)d_in[wb + 10];
    const float* Db   = (const float*)d_in[wb + 11];
    const float* Ew   = (const float*)d_in[wb + 12];
    const float* Eb   = (const float*)d_in[wb + 13];
    const float* bxg  = (const float*)d_in[wb + 14];
    const float* bxb  = (const float*)d_in[wb + 15];
    const float* beg  = (const float*)d_in[wb + 16];
    const float* beb  = (const float*)d_in[wb + 17];
    const float* d1w  = (const float*)d_in[wb + 18];
    const float* d1b  = (const float*)d_in[wb + 19];
    const float* d2w  = (const float*)d_in[wb + 20];
    const float* d2b  = (const float*)d_in[wb + 21];

    float *abde, *ce, *nump, *denp, *statsp, *bpackp, *fbiasp, *b0pp;
    bf16 *abde_hi, *abde_lo, *c_hi, *c_lo, *fw_hi, *fw_lo, *w0p_hi, *w0p_lo;
    bf16 *xh, *xl, *eh, *el, *hh, *hl, *afh, *afl;
    int *histp;
    cudaGetSymbolAddress((void**)&abde, g_ABDE);
    cudaGetSymbolAddress((void**)&ce, g_Ce);
    cudaGetSymbolAddress((void**)&nump, g_num);
    cudaGetSymbolAddress((void**)&denp, g_den);
    cudaGetSymbolAddress((void**)&statsp, g_stats);
    cudaGetSymbolAddress((void**)&bpackp, g_bpack);
    cudaGetSymbolAddress((void**)&fbiasp, g_fbias);
    cudaGetSymbolAddress((void**)&b0pp, g_b0p);
    cudaGetSymbolAddress((void**)&abde_hi, g_abde_hi);
    cudaGetSymbolAddress((void**)&abde_lo, g_abde_lo);
    cudaGetSymbolAddress((void**)&c_hi, g_c_hi);
    cudaGetSymbolAddress((void**)&c_lo, g_c_lo);
    cudaGetSymbolAddress((void**)&fw_hi, g_fw_hi);
    cudaGetSymbolAddress((void**)&fw_lo, g_fw_lo);
    cudaGetSymbolAddress((void**)&w0p_hi, g_w0p_hi);
    cudaGetSymbolAddress((void**)&w0p_lo, g_w0p_lo);
    cudaGetSymbolAddress((void**)&xh, g_xh);
    cudaGetSymbolAddress((void**)&xl, g_xl);
    cudaGetSymbolAddress((void**)&eh, g_eh);
    cudaGetSymbolAddress((void**)&el, g_el);
    cudaGetSymbolAddress((void**)&hh, g_hh);
    cudaGetSymbolAddress((void**)&hl, g_hl);
    cudaGetSymbolAddress((void**)&afh, g_afh);
    cudaGetSymbolAddress((void**)&afl, g_afl);
    cudaGetSymbolAddress((void**)&histp, g_hist);

    cudaFuncSetAttribute(gemm_tc2<0>, cudaFuncAttributeMaxDynamicSharedMemorySize, SMEM3);
    cudaFuncSetAttribute(gemm_tc2<2>, cudaFuncAttributeMaxDynamicSharedMemorySize, SMEM3);
    cudaFuncSetAttribute(gemm_ce_fused<0>, cudaFuncAttributeMaxDynamicSharedMemorySize, SMEM2);
    cudaFuncSetAttribute(gemm_ce_fused<1>, cudaFuncAttributeMaxDynamicSharedMemorySize, SMEM2);
    cudaFuncSetAttribute(gemm_dec_fused, cudaFuncAttributeMaxDynamicSharedMemorySize, SMEM2);

    // --- prep: sort edges by dst, split weights/activations ---
    cudaMemsetAsync(histp, 0, Nn * sizeof(int));
    k_detect_idx<<<1, 256>>>((const unsigned int*)eidx);
    k_convert_idx<<<(Ee + 255) / 256, 256>>>(eidx);      // also builds histogram
    k_scan<<<1, 1024>>>();
    k_scatter<<<(Ee + 255) / 256, 256>>>();
    {
        int mg = MB0 + MB1 + MB2 + MB3 + MB4 + MB5 + MB6;
        k_megaprep<<<mg, 256>>>(Ab, Bb, Db, Eb, fw, fb, Cw, d1w, hold, af);
    }
    {
        size_t tw = (size_t)Ll * 1024 * 256;
        k_split_abde<<<(int)((tw + 255) / 256), 256>>>(Aw, Bw, Dw, Ew);
    }
    k_w0prime<<<32, 256>>>(epw, epb, Cw, Cb);
    {
        dim3 grid(Hh / 128, (Nn + 127) / 128);
        gemm_tc2<2><<<grid, 256, SMEM3>>>(hh, hl, fw_hi, fw_lo, fbiasp,
                                          nullptr, xh, xl, Nn, Hh, Hh);
    }
    k_eproj<<<(int)(((size_t)Ee * Hh + 255) / 256), 256>>>(af, epw, epb);
    k_init_out<<<(Ee + 255) / 256, 256>>>((float*)d_out, d2b);

    for (int l = 0; l < Ll; l++) {
        cudaMemsetAsync(nump, 0, (size_t)Nn * Hh * sizeof(float));
        cudaMemsetAsync(denp, 0, (size_t)Nn * Hh * sizeof(float));
        cudaMemsetAsync(statsp, 0, 4 * Hh * sizeof(float));

        {   // fused A|B|D|E GEMM: [N,256] @ [256,1024]
            dim3 grid(4 * Hh / 128, (Nn + 127) / 128);
            gemm_tc2<0><<<grid, 256, SMEM3>>>(xh, xl,
                                              abde_hi + (size_t)l * 1024 * 256,
                                              abde_lo + (size_t)l * 1024 * 256,
                                              bpackp + l * 4 * Hh, abde, nullptr, nullptr,
                                              Nn, Hh, 4 * Hh);
        }
        {   // Ce GEMM + fused edge phase; layer 0 uses the rank-8 collapsed form (K=32)
            dim3 grid(2, (Ee + 127) / 128);
            if (l == 0)
                gemm_ce_fused<1><<<grid, 256, SMEM2>>>(afh, afl, w0p_hi, w0p_lo,
                                                       b0pp, ce, 32);
            else if (l < Ll - 1)
                gemm_ce_fused<1><<<grid, 256, SMEM2>>>(eh, el,
                                                       c_hi + (size_t)l * Hh * Hh,
                                                       c_lo + (size_t)l * Hh * Hh,
                                                       Cb + l * Hh, ce, 256);
            else
                gemm_ce_fused<0><<<grid, 256, SMEM2>>>(eh, el,
                                                       c_hi + (size_t)l * Hh * Hh,
                                                       c_lo + (size_t)l * Hh * Hh,
                                                       Cb + l * Hh, ce, 256);
        }
        k_node<<<Nn / 32, 256>>>();
        k_apply_x<<<(int)(((size_t)Nn * Hh + 255) / 256), 256>>>(bxg + l * Hh, bxb + l * Hh);
        if (l < Ll - 1)  // e dead after last layer
            k_apply_e<<<(int)(((size_t)Ee * Hh + 255) / 256), 256>>>(ce, beg + l * Hh, beb + l * Hh);
    }

    // --- decoder (dec1 GEMM with fused dec2 dot-product epilogue) ---
    {
        dim3 grid(2, (Ee + 127) / 128);
        gemm_dec_fused<<<grid, 256, SMEM2>>>(d1b, d2w, (float*)d_out);
    }
}

// round 14
// speedup vs baseline: 1.1877x; 1.1769x over previous
#include <cuda_runtime.h>
#include <cuda_fp16.h>
#include <math.h>
#include <stdint.h>

// Problem constants
#define Hh 256
#define Ll 4
#define Nn 100000
#define Ee 300000
#define BN_EPS 1e-5f
#define AGG_EPS 1e-6f
#define K_DEC 544   // 520 padded to multiple of 32

typedef __half h16;

// ------------------------- static device scratch -------------------------
__device__ float g_ABDE[(size_t)Nn * 4 * Hh];   // [N,1024]: A|B|D|E
__device__ float g_Ce[(size_t)Ee * Hh];         // e_hat scratch (sorted edge order)
__device__ float g_num[(size_t)Nn * Hh];
__device__ float g_den[(size_t)Nn * Hh];
__device__ float g_stats[4 * Hh];
__device__ float g_bpack[Ll * 4 * Hh];
__device__ float g_fbias[Hh];
__device__ float g_b0p[Hh];
__device__ int   g_src[Ee];     // sorted by dst
__device__ int   g_dst[Ee];     // sorted (non-decreasing)
__device__ int   g_eorig[Ee];
__device__ int   g_srcO[Ee];
__device__ int   g_dstO[Ee];
__device__ int   g_hist[Nn];
__device__ int   g_idx64;

// fp16 weights (single precision stream), transposed to [N][K]
__device__ h16 g_abde_w[(size_t)Ll * 1024 * 256];
__device__ h16 g_c_w[(size_t)Ll * 256 * 256];
__device__ h16 g_fw_w[256 * 256];
__device__ h16 g_d1_w[256 * K_DEC];
__device__ h16 g_w0p_w[256 * 32];

// fp16 hi/lo activations (x/e live ONLY here; e in sorted edge order)
__device__ h16 g_xh[(size_t)Nn * Hh];
__device__ h16 g_xl[(size_t)Nn * Hh];
__device__ h16 g_eh[(size_t)Ee * Hh];
__device__ h16 g_el[(size_t)Ee * Hh];
__device__ h16 g_hh[(size_t)Nn * Hh];
__device__ h16 g_hl[(size_t)Nn * Hh];
__device__ h16 g_afh[(size_t)Ee * 32];
__device__ h16 g_afl[(size_t)Ee * 32];

// ------------------------- prep kernels -------------------------
__global__ void k_detect_idx(const unsigned int* __restrict__ w) {
    unsigned int s = 0;
    for (int i = threadIdx.x; i < 1024; i += 256) s |= w[2 * i + 1];
#pragma unroll
    for (int off = 16; off; off >>= 1) s |= __shfl_xor_sync(0xFFFFFFFFu, s, off);
    __shared__ unsigned int red[8];
    if ((threadIdx.x & 31) == 0) red[threadIdx.x >> 5] = s;
    __syncthreads();
    if (threadIdx.x == 0) {
        unsigned int t = 0;
        for (int i = 0; i < 8; i++) t |= red[i];
        g_idx64 = (t == 0u) ? 1 : 0;
    }
}

__global__ void k_convert_idx(const void* __restrict__ eidx) {
    int i = blockIdx.x * blockDim.x + threadIdx.x;
    if (i < Ee) {
        int s, d;
        if (g_idx64) {
            const long long* p = (const long long*)eidx;
            s = (int)p[i];
            d = (int)p[(size_t)Ee + i];
        } else {
            const int* p = (const int*)eidx;
            s = p[i];
            d = p[Ee + i];
        }
        g_srcO[i] = s;
        g_dstO[i] = d;
        atomicAdd(&g_hist[d], 1);
    }
}

__global__ __launch_bounds__(1024) void k_scan() {
    __shared__ int part[1024];
    int t = threadIdx.x;
    const int CH = (Nn + 1023) / 1024;
    int base = t * CH;
    int s = 0;
    for (int j = 0; j < CH; j++) {
        int b = base + j;
        if (b < Nn) s += g_hist[b];
    }
    part[t] = s;
    __syncthreads();
    if (t == 0) {
        int acc = 0;
        for (int i = 0; i < 1024; i++) { int v = part[i]; part[i] = acc; acc += v; }
    }
    __syncthreads();
    int acc = part[t];
    for (int j = 0; j < CH; j++) {
        int b = base + j;
        if (b < Nn) { int v = g_hist[b]; g_hist[b] = acc; acc += v; }
    }
}

__global__ void k_scatter() {
    int i = blockIdx.x * blockDim.x + threadIdx.x;
    if (i < Ee) {
        int d = g_dstO[i];
        int pos = atomicAdd(&g_hist[d], 1);
        g_src[pos] = g_srcO[i];
        g_dst[pos] = d;
        g_eorig[pos] = i;
    }
}

__device__ __forceinline__ void split_write(float v, h16* hi, h16* lo, size_t i) {
    h16 h = __float2half_rn(v);
    hi[i] = h;
    lo[i] = __float2half_rn(v - __half2float(h));
}

__global__ void k_split_abde(const float* __restrict__ Aw, const float* __restrict__ Bw,
                             const float* __restrict__ Dw, const float* __restrict__ Ew) {
    size_t i = (size_t)blockIdx.x * 256 + threadIdx.x;
    if (i < (size_t)Ll * 1024 * 256) {
        int k = (int)(i & 255);
        int n = (int)((i >> 8) & 1023);
        int l = (int)(i >> 18);
        const float* W = (n < 256) ? Aw : (n < 512) ? Bw : (n < 768) ? Dw : Ew;
        g_abde_w[i] = __float2half_rn(W[(size_t)l * 65536 + (size_t)k * 256 + (n & 255)]);
    }
}

// layer-0 collapsed Ce: W0'[k8][n] = epw@C0; b0' = epb@C0 + C0b
__global__ void k_w0prime(const float* __restrict__ epw, const float* __restrict__ epb,
                          const float* __restrict__ C0, const float* __restrict__ C0b) {
    int i = blockIdx.x * 256 + threadIdx.x;
    int n = i >> 5, k = i & 31;
    float v = 0.f;
    if (k < 8) {
        for (int m = 0; m < 256; m++) v += epw[k * 256 + m] * C0[(size_t)m * 256 + n];
    }
    g_w0p_w[(size_t)n * 32 + k] = __float2half_rn(v);
    if (k == 0) {
        float b = C0b[n];
        for (int m = 0; m < 256; m++) b += epb[m] * C0[(size_t)m * 256 + n];
        g_b0p[n] = b;
    }
}

// block-range partitioned prep (af split uses g_eorig -> run AFTER scatter)
#define MB0 16
#define MB1 1
#define MB2 256
#define MB3 1024
#define MB4 576
#define MB5 100000
#define MB6 75000
__global__ void k_megaprep(
    const float* __restrict__ Ab, const float* __restrict__ Bb,
    const float* __restrict__ Db, const float* __restrict__ Eb,
    const float* __restrict__ fw, const float* __restrict__ fb,
    const float* __restrict__ Cw, const float* __restrict__ d1w,
    const float* __restrict__ hold, const float* __restrict__ af)
{
    int b = blockIdx.x, t = threadIdx.x;
    if (b < MB0) {
        int i = b * 256 + t;
        if (i < Ll * 4 * Hh) {
            int j4 = i % (4 * Hh);
            int l = i / (4 * Hh);
            int which = j4 >> 8, j = j4 & 255;
            const float* B = (which == 0) ? Ab : (which == 1) ? Bb : (which == 2) ? Db : Eb;
            g_bpack[i] = B[l * Hh + j];
        }
        return;
    }
    b -= MB0;
    if (b < MB1) {
        float s = fb[t];
        for (int k = 0; k < Hh; k++) s += fw[(size_t)k * Hh + t];
        g_fbias[t] = s;
        return;
    }
    b -= MB1;
    if (b < MB2) {
        int i = b * 256 + t;
        int k = i & 255, n = i >> 8;
        g_fw_w[i] = __float2half_rn(fw[(size_t)(Hh + k) * Hh + n]);
        return;
    }
    b -= MB2;
    if (b < MB3) {
        size_t i = (size_t)b * 256 + t;
        int k = (int)(i & 255), n = (int)((i >> 8) & 255), l = (int)(i >> 16);
        g_c_w[i] = __float2half_rn(Cw[(size_t)l * 65536 + (size_t)k * 256 + n]);
        return;
    }
    b -= MB3;
    if (b < MB4) {
        int i = b * 256 + t;
        if (i < 256 * K_DEC) {
            int k = i % K_DEC, n = i / K_DEC;
            float v = (k < 520) ? d1w[(size_t)k * 256 + n] : 0.0f;
            g_d1_w[i] = __float2half_rn(v);
        }
        return;
    }
    b -= MB4;
    if (b < MB5) {
        size_t i = (size_t)b * 256 + t;
        if (i < (size_t)Nn * Hh) split_write(hold[i], g_hh, g_hl, i);
        return;
    }
    b -= MB5;
    {
        size_t i = (size_t)b * 256 + t;
        if (i < (size_t)Ee * 32) {
            int c = (int)(i & 31);
            size_t e = i >> 5;
            float v = (c < 8) ? af[(size_t)g_eorig[e] * 8 + c] : 0.0f;
            split_write(v, g_afh, g_afl, i);
        }
    }
}

__global__ void k_init_out(float* __restrict__ out, const float* __restrict__ b2) {
    int i = blockIdx.x * blockDim.x + threadIdx.x;
    if (i < Ee) out[i] = b2[0];
}

// ------------------------- tensor-core machinery -------------------------
__device__ __forceinline__ void mma16816(float* c, const uint32_t* a, const uint32_t* b) {
    asm volatile(
        "mma.sync.aligned.m16n8k16.row.col.f32.f16.f16.f32 "
        "{%0,%1,%2,%3}, {%4,%5,%6,%7}, {%8,%9}, {%0,%1,%2,%3};"
        : "+f"(c[0]), "+f"(c[1]), "+f"(c[2]), "+f"(c[3])
        : "r"(a[0]), "r"(a[1]), "r"(a[2]), "r"(a[3]), "r"(b[0]), "r"(b[1]));
}
__device__ __forceinline__ void ldm_x4(uint32_t* r, uint32_t addr) {
    asm volatile("ldmatrix.sync.aligned.m8n8.x4.shared.b16 {%0,%1,%2,%3}, [%4];"
                 : "=r"(r[0]), "=r"(r[1]), "=r"(r[2]), "=r"(r[3]) : "r"(addr));
}
__device__ __forceinline__ void ldm_x2(uint32_t* r, uint32_t addr) {
    asm volatile("ldmatrix.sync.aligned.m8n8.x2.shared.b16 {%0,%1}, [%2];"
                 : "=r"(r[0]), "=r"(r[1]) : "r"(addr));
}
__device__ __forceinline__ void cpa16(uint32_t s, const void* g) {
    asm volatile("cp.async.cg.shared.global [%0], [%1], 16;" :: "r"(s), "l"(g));
}
__device__ __forceinline__ void cpa_commit() { asm volatile("cp.async.commit_group;"); }
template<int N>
__device__ __forceinline__ void cpa_wait() { asm volatile("cp.async.wait_group %0;" :: "n"(N) : "memory"); }

__device__ __forceinline__ int sw_off(int row, int chunk) {
    return row * 64 + ((chunk ^ ((row >> 1) & 3)) << 4);
}

__device__ __forceinline__ unsigned long long pk2(float a, float b) {
    return (unsigned long long)__float_as_uint(a) | ((unsigned long long)__float_as_uint(b) << 32);
}
__device__ __forceinline__ void upk2(unsigned long long v, float& a, float& b) {
    a = __uint_as_float((unsigned int)v);
    b = __uint_as_float((unsigned int)(v >> 32));
}
__device__ __forceinline__ uint32_t pack_h2(float a, float b) {
    __half2 t = __floats2half2_rn(a, b);
    return *(uint32_t*)&t;
}

// stage: A-hi @0, A-lo @8192, B @16384; stride 24 KB
#define ST_ALO 8192
#define ST_B   16384
#define ST_STRIDE 24576
#define SMEM3 (3 * ST_STRIDE)   // 72 KB (pure GEMM)
#define SMEM2 (2 * ST_STRIDE)   // 48 KB (gather kernels; keep L1)

// fp16x2: 2 passes (A-hi x B, A-lo x B); B single stream
__device__ __forceinline__ void tile_compute(
    float acc[4][4][4], uint32_t sbase, int lane, int wr, int wc) {
    uint32_t sAhiB = sbase, sAloB = sbase + ST_ALO, sBB = sbase + ST_B;
#pragma unroll
    for (int kg = 0; kg < 2; kg++) {
        uint32_t ra[4][4], rb[4][2];
#pragma unroll
        for (int tm = 0; tm < 4; tm++) {
            int row = wr * 64 + tm * 16 + (lane & 15);
            int ch = 2 * kg + (lane >> 4);
            ldm_x4(ra[tm], sAhiB + sw_off(row, ch));
        }
#pragma unroll
        for (int tn = 0; tn < 4; tn++) {
            int row = wc * 32 + tn * 8 + (lane & 7);
            int ch = 2 * kg + ((lane >> 3) & 1);
            ldm_x2(rb[tn], sBB + sw_off(row, ch));
        }
#pragma unroll
        for (int tm = 0; tm < 4; tm++)
#pragma unroll
            for (int tn = 0; tn < 4; tn++)
                mma16816(acc[tm][tn], ra[tm], rb[tn]);
#pragma unroll
        for (int tm = 0; tm < 4; tm++) {
            int row = wr * 64 + tm * 16 + (lane & 15);
            int ch = 2 * kg + (lane >> 4);
            ldm_x4(ra[tm], sAloB + sw_off(row, ch));
        }
#pragma unroll
        for (int tm = 0; tm < 4; tm++)
#pragma unroll
            for (int tn = 0; tn < 4; tn++)
                mma16816(acc[tm][tn], ra[tm], rb[tn]);
    }
}

// 3-stage mainloop (pure GEMM kernels)
#define PIPE_MAIN3(K, LOADER) do { \
    LOADER(sbase0, 0); \
    if ((K) > 32) LOADER(sbase0 + ST_STRIDE, 32); else cpa_commit(); \
    for (int k0 = 0, st = 0; k0 < (K); k0 += 32, st = (st == 2) ? 0 : st + 1) { \
        cpa_wait<1>(); \
        __syncthreads(); \
        if (k0 + 64 < (K)) { \
            int st2 = st + 2; if (st2 >= 3) st2 -= 3; \
            LOADER(sbase0 + st2 * ST_STRIDE, k0 + 64); \
        } else cpa_commit(); \
        tile_compute(acc, sbase0 + st * ST_STRIDE, lane, wr, wc); \
    } \
} while (0)

// 2-stage mainloop (gather kernels)
#define PIPE_MAIN2(K, LOADER) do { \
    LOADER(sbase0, 0); \
    int cur = 0; \
    for (int k0 = 0; k0 < (K); k0 += 32) { \
        cpa_wait<0>(); \
        __syncthreads(); \
        if (k0 + 32 < (K)) LOADER(sbase0 + (cur ^ 1) * ST_STRIDE, k0 + 32); \
        tile_compute(acc, sbase0 + cur * ST_STRIDE, lane, wr, wc); \
        cur ^= 1; \
    } \
} while (0)

// ------------------------- fp16x2 GEMM, 3-stage pipeline -------------------------
// EPI: 0 = bias -> fp32 C; 2 = bias+relu -> fp16 hi/lo ONLY
template<int EPI>
__global__ __launch_bounds__(256) void gemm_tc2(
    const h16* __restrict__ Ahi, const h16* __restrict__ Alo,
    const h16* __restrict__ Bw,
    const float* __restrict__ bias, float* __restrict__ C,
    h16* __restrict__ Chi, h16* __restrict__ Clo,
    int M, int K, int Nc)
{
    extern __shared__ __align__(16) char smem[];
    uint32_t sbase0 = (uint32_t)__cvta_generic_to_shared(smem);

    int tid = threadIdx.x, lane = tid & 31, w = tid >> 5;
    int wr = w >> 2, wc = w & 3;
    int bm = blockIdx.y * 128, bn = blockIdx.x * 128;

    int r = tid >> 1, ch0 = (tid & 1) * 2;
    int gr = bm + r; if (gr >= M) gr = M - 1;
    size_t aRow = (size_t)gr * K;
    size_t bRow = (size_t)(bn + r) * K;

    float acc[4][4][4];
#pragma unroll
    for (int i = 0; i < 4; i++)
#pragma unroll
        for (int j = 0; j < 4; j++)
#pragma unroll
            for (int q = 0; q < 4; q++) acc[i][j][q] = 0.f;

    auto load_stage = [&](uint32_t sb, int k0) {
#pragma unroll
        for (int i = 0; i < 2; i++) {
            int ch = ch0 + i;
            uint32_t so = sw_off(r, ch);
            size_t go = (size_t)k0 + ch * 8;
            cpa16(sb + so,          Ahi + aRow + go);
            cpa16(sb + ST_ALO + so, Alo + aRow + go);
            cpa16(sb + ST_B + so,   Bw + bRow + go);
        }
        cpa_commit();
    };

    PIPE_MAIN3(K, load_stage);

    int g = lane >> 2, tig = lane & 3;
#pragma unroll
    for (int tm = 0; tm < 4; tm++) {
        int r0 = bm + wr * 64 + tm * 16 + g;
#pragma unroll
        for (int tn = 0; tn < 4; tn++) {
            int col = bn + wc * 32 + tn * 8 + 2 * tig;
            float b0 = bias[col], b1 = bias[col + 1];
            float v0 = acc[tm][tn][0] + b0, v1 = acc[tm][tn][1] + b1;
            float v2 = acc[tm][tn][2] + b0, v3 = acc[tm][tn][3] + b1;
            if (EPI >= 1) {
                v0 = fmaxf(v0, 0.f); v1 = fmaxf(v1, 0.f);
                v2 = fmaxf(v2, 0.f); v3 = fmaxf(v3, 0.f);
            }
            if (r0 < M) {
                size_t o = (size_t)r0 * Nc + col;
                if (EPI != 2) { float2 t = {v0, v1}; *(float2*)&C[o] = t; }
                else {
                    h16 h0 = __float2half_rn(v0), h1 = __float2half_rn(v1);
                    __half2 hp = __halves2half2(h0, h1);
                    *(uint32_t*)&Chi[o] = *(uint32_t*)&hp;
                    *(uint32_t*)&Clo[o] = pack_h2(v0 - __half2float(h0), v1 - __half2float(h1));
                }
            }
            if (r0 + 8 < M) {
                size_t o = (size_t)(r0 + 8) * Nc + col;
                if (EPI != 2) { float2 t = {v2, v3}; *(float2*)&C[o] = t; }
                else {
                    h16 h2 = __float2half_rn(v2), h3 = __float2half_rn(v3);
                    __half2 hp = __halves2half2(h2, h3);
                    *(uint32_t*)&Chi[o] = *(uint32_t*)&hp;
                    *(uint32_t*)&Clo[o] = pack_h2(v2 - __half2float(h2), v3 - __half2float(h3));
                }
            }
        }
    }
}

// ------------------------- Ce GEMM with fused edge epilogue (2-stage, runtime K) -------------------------
template<int WRITE_EH>
__global__ __launch_bounds__(256) void gemm_ce_fused(
    const h16* __restrict__ Ahi, const h16* __restrict__ Alo,
    const h16* __restrict__ Bw,
    const float* __restrict__ bias, float* __restrict__ EHout, int K)
{
    const int M = Ee, Nc = 256;
    const unsigned FULL = 0xFFFFFFFFu;
    extern __shared__ __align__(16) char smem[];
    uint32_t sbase0 = (uint32_t)__cvta_generic_to_shared(smem);

    int tid = threadIdx.x, lane = tid & 31, w = tid >> 5;
    int wr = w >> 2, wc = w & 3;
    int bm = blockIdx.y * 128, bn = blockIdx.x * 128;

    int r = tid >> 1, ch0 = (tid & 1) * 2;
    int gr = bm + r; if (gr >= M) gr = M - 1;
    size_t aRow = (size_t)gr * K;
    size_t bRow = (size_t)(bn + r) * K;

    float acc[4][4][4];
#pragma unroll
    for (int i = 0; i < 4; i++)
#pragma unroll
        for (int j = 0; j < 4; j++)
#pragma unroll
            for (int q = 0; q < 4; q++) acc[i][j][q] = 0.f;

    auto load_stage = [&](uint32_t sb, int k0) {
#pragma unroll
        for (int i = 0; i < 2; i++) {
            int ch = ch0 + i;
            uint32_t so = sw_off(r, ch);
            size_t go = (size_t)k0 + ch * 8;
            cpa16(sb + so,          Ahi + aRow + go);
            cpa16(sb + ST_ALO + so, Alo + aRow + go);
            cpa16(sb + ST_B + so,   Bw + bRow + go);
        }
        cpa_commit();
    };

    PIPE_MAIN2(K, load_stage);

    int g = lane >> 2, tig = lane & 3;
    float ls[4][2], lq[4][2];
    if (WRITE_EH) {
#pragma unroll
        for (int tn = 0; tn < 4; tn++) { ls[tn][0] = ls[tn][1] = lq[tn][0] = lq[tn][1] = 0.f; }
    }

#pragma unroll
    for (int tm = 0; tm < 4; tm++) {
#pragma unroll
        for (int half = 0; half < 2; half++) {
            int e = bm + wr * 64 + tm * 16 + g + 8 * half;
            bool ok = e < M;
            int ec = ok ? e : (M - 1);
            int sN = g_src[ec], dN = g_dst[ec];
            int dkey = ok ? dN : (-1 - g);
            const float* Drow = g_ABDE + (size_t)dN * 1024 + 512;
            const float* Erow = g_ABDE + (size_t)sN * 1024 + 768;
            const float* Brow = g_ABDE + (size_t)sN * 1024 + 256;
            float* nrow = g_num + (size_t)dN * Hh;
            float* drow = g_den + (size_t)dN * Hh;

            int od1 = __shfl_down_sync(FULL, dkey, 4);
            int od2 = __shfl_down_sync(FULL, dkey, 8);
            int od4 = __shfl_down_sync(FULL, dkey, 16);
            int dup = __shfl_up_sync(FULL, dkey, 4);
            bool t1 = (g + 1 < 8) && (od1 == dkey);
            bool t2 = (g + 2 < 8) && (od2 == dkey);
            bool t4 = (g + 4 < 8) && (od4 == dkey);
            bool leader = ok && (g == 0 || dup != dkey);

#pragma unroll
            for (int tn = 0; tn < 4; tn++) {
                int col = bn + wc * 32 + tn * 8 + 2 * tig;
                float2 dv = *(const float2*)&Drow[col];
                float2 ev = *(const float2*)&Erow[col];
                float2 bv = *(const float2*)&Brow[col];
                float eh0 = acc[tm][tn][2 * half + 0] + bias[col]     + dv.x + ev.x;
                float eh1 = acc[tm][tn][2 * half + 1] + bias[col + 1] + dv.y + ev.y;
                float sg0 = 1.f / (1.f + __expf(-eh0));
                float sg1 = 1.f / (1.f + __expf(-eh1));
                float n0 = ok ? sg0 * bv.x : 0.f;
                float n1 = ok ? sg1 * bv.y : 0.f;
                float s0 = ok ? sg0 : 0.f;
                float s1 = ok ? sg1 : 0.f;

                if (WRITE_EH && ok) {
                    float2 t = {eh0, eh1};
                    *(float2*)&EHout[(size_t)e * Nc + col] = t;
                    ls[tn][0] += eh0; ls[tn][1] += eh1;
                    lq[tn][0] += eh0 * eh0; lq[tn][1] += eh1 * eh1;
                }

                {
                    unsigned long long on = __shfl_down_sync(FULL, pk2(n0, n1), 4);
                    unsigned long long os = __shfl_down_sync(FULL, pk2(s0, s1), 4);
                    if (t1) { float a, b; upk2(on, a, b); n0 += a; n1 += b; upk2(os, a, b); s0 += a; s1 += b; }
                }
                {
                    unsigned long long on = __shfl_down_sync(FULL, pk2(n0, n1), 8);
                    unsigned long long os = __shfl_down_sync(FULL, pk2(s0, s1), 8);
                    if (t2) { float a, b; upk2(on, a, b); n0 += a; n1 += b; upk2(os, a, b); s0 += a; s1 += b; }
                }
                {
                    unsigned long long on = __shfl_down_sync(FULL, pk2(n0, n1), 16);
                    unsigned long long os = __shfl_down_sync(FULL, pk2(s0, s1), 16);
                    if (t4) { float a, b; upk2(on, a, b); n0 += a; n1 += b; upk2(os, a, b); s0 += a; s1 += b; }
                }
                if (leader) {
                    atomicAdd(&nrow[col],     n0);
                    atomicAdd(&nrow[col + 1], n1);
                    atomicAdd(&drow[col],     s0);
                    atomicAdd(&drow[col + 1], s1);
                }
            }
        }
    }

    if (WRITE_EH) {
#pragma unroll
        for (int tn = 0; tn < 4; tn++) {
#pragma unroll
            for (int j = 0; j < 2; j++) {
                float v = ls[tn][j], q = lq[tn][j];
#pragma unroll
                for (int off = 4; off <= 16; off <<= 1) {
                    v += __shfl_xor_sync(0xFFFFFFFFu, v, off);
                    q += __shfl_xor_sync(0xFFFFFFFFu, q, off);
                }
                if (g == 0) {
                    int col = bn + wc * 32 + tn * 8 + 2 * tig + j;
                    atomicAdd(&g_stats[2 * Hh + col], v);
                    atomicAdd(&g_stats[3 * Hh + col], q);
                }
            }
        }
    }
}

// ------------------------- decoder gather-GEMM with fused dec2 (2-stage) -------------------------
__global__ __launch_bounds__(256) void gemm_dec_fused(
    const float* __restrict__ bias, const float* __restrict__ w2,
    float* __restrict__ out)
{
    const int K = K_DEC, M = Ee;
    extern __shared__ __align__(16) char smem[];
    uint32_t sbase0 = (uint32_t)__cvta_generic_to_shared(smem);

    int tid = threadIdx.x, lane = tid & 31, w = tid >> 5;
    int wr = w >> 2, wc = w & 3;
    int bm = blockIdx.y * 128, bn = blockIdx.x * 128;

    int r = tid >> 1, ch0 = (tid & 1) * 2;
    int e = bm + r; if (e >= M) e = M - 1;
    int sN = g_src[e], dN = g_dst[e];
    size_t bRow = (size_t)(bn + r) * K;

    float acc[4][4][4];
#pragma unroll
    for (int i = 0; i < 4; i++)
#pragma unroll
        for (int j = 0; j < 4; j++)
#pragma unroll
            for (int q = 0; q < 4; q++) acc[i][j][q] = 0.f;

    auto load_stage = [&](uint32_t sb, int k0) {
#pragma unroll
        for (int i = 0; i < 2; i++) {
            int ch = ch0 + i;
            uint32_t so = sw_off(r, ch);
            int c0 = k0 + ch * 8;
            const h16 *ph, *pl;
            if (c0 < 256)      { ph = g_xh + (size_t)sN * Hh + c0;        pl = g_xl + (size_t)sN * Hh + c0; }
            else if (c0 < 512) { ph = g_xh + (size_t)dN * Hh + (c0-256);  pl = g_xl + (size_t)dN * Hh + (c0-256); }
            else               { ph = g_afh + (size_t)e * 32 + (c0-512);  pl = g_afl + (size_t)e * 32 + (c0-512); }
            cpa16(sb + so,          ph);
            cpa16(sb + ST_ALO + so, pl);
            cpa16(sb + ST_B + so,   g_d1_w + bRow + c0);
        }
        cpa_commit();
    };

    PIPE_MAIN2(K, load_stage);

    int g = lane >> 2, tig = lane & 3;
#pragma unroll
    for (int tm = 0; tm < 4; tm++) {
        int r0 = bm + wr * 64 + tm * 16 + g;
        float p0 = 0.f, p1 = 0.f;
#pragma unroll
        for (int tn = 0; tn < 4; tn++) {
            int col = bn + wc * 32 + tn * 8 + 2 * tig;
            float b0 = bias[col], b1 = bias[col + 1];
            float w0 = w2[col], w1 = w2[col + 1];
            p0 += fmaxf(acc[tm][tn][0] + b0, 0.f) * w0 + fmaxf(acc[tm][tn][1] + b1, 0.f) * w1;
            p1 += fmaxf(acc[tm][tn][2] + b0, 0.f) * w0 + fmaxf(acc[tm][tn][3] + b1, 0.f) * w1;
        }
        p0 += __shfl_xor_sync(0xFFFFFFFFu, p0, 1);
        p0 += __shfl_xor_sync(0xFFFFFFFFu, p0, 2);
        p1 += __shfl_xor_sync(0xFFFFFFFFu, p1, 1);
        p1 += __shfl_xor_sync(0xFFFFFFFFu, p1, 2);
        if (tig == 0) {
            if (r0 < M)     atomicAdd(&out[g_eorig[r0]], p0);
            if (r0 + 8 < M) atomicAdd(&out[g_eorig[r0 + 8]], p1);
        }
    }
}

// ------------------------- edge projection (K=8, sorted order) -------------------------
__global__ void k_eproj(const float* __restrict__ af, const float* __restrict__ W,
                        const float* __restrict__ b) {
    size_t idx = (size_t)blockIdx.x * blockDim.x + threadIdx.x;
    if (idx < (size_t)Ee * Hh) {
        int c = (int)(idx & 255);
        size_t e = idx >> 8;
        size_t eo = (size_t)g_eorig[e];
        float v = b[c];
#pragma unroll
        for (int k = 0; k < 8; k++) v += af[eo * 8 + k] * W[k * Hh + c];
        split_write(v, g_eh, g_el, idx);
    }
}

// ------------------------- per-layer node kernels -------------------------
__global__ __launch_bounds__(256) void k_node() {
    int c = threadIdx.x;
    int base = blockIdx.x * 32;
    float s = 0.f, sq = 0.f;
    for (int i = 0; i < 32; i++) {
        int n = base + i;
        size_t o = (size_t)n * Hh + c;
        float xc = g_ABDE[(size_t)n * 1024 + c] + g_num[o] / (g_den[o] + AGG_EPS);
        g_num[o] = xc;
        s += xc; sq += xc * xc;
    }
    atomicAdd(&g_stats[c], s);
    atomicAdd(&g_stats[Hh + c], sq);
}

__global__ void k_apply_x(const float* __restrict__ gam, const float* __restrict__ bet) {
    size_t idx = (size_t)blockIdx.x * blockDim.x + threadIdx.x;
    if (idx < (size_t)Nn * Hh) {
        int c = (int)(idx & 255);
        float mu = g_stats[c] * (1.f / Nn);
        float var = g_stats[Hh + c] * (1.f / Nn) - mu * mu;
        float v = gam[c] * (g_num[idx] - mu) * rsqrtf(var + BN_EPS) + bet[c];
        float old = __half2float(g_xh[idx]) + __half2float(g_xl[idx]);
        float o = old + fmaxf(v, 0.f);
        split_write(o, g_xh, g_xl, idx);
    }
}

__global__ void k_apply_e(const float* __restrict__ ehat,
                          const float* __restrict__ gam, const float* __restrict__ bet) {
    size_t idx = (size_t)blockIdx.x * blockDim.x + threadIdx.x;
    if (idx < (size_t)Ee * Hh) {
        int c = (int)(idx & 255);
        float mu = g_stats[2 * Hh + c] * (1.f / Ee);
        float var = g_stats[3 * Hh + c] * (1.f / Ee) - mu * mu;
        float v = gam[c] * (ehat[idx] - mu) * rsqrtf(var + BN_EPS) + bet[c];
        float old = __half2float(g_eh[idx]) + __half2float(g_el[idx]);
        float o = old + fmaxf(v, 0.f);
        split_write(o, g_eh, g_el, idx);
    }
}

// ------------------------- host launcher -------------------------
extern "C" void kernel_launch(void* const* d_in, const int* in_sizes, int n_in,
                              void* d_out, int out_size)
{
    int wb = 3;
    for (int i = 3; i < n_in && i < 6; i++) {
        if (in_sizes[i] == 2 * Hh * Hh) { wb = i; break; }
    }

    const void*  eidx = d_in[0];
    const float* af   = (const float*)d_in[1];
    const float* hold = (const float*)d_in[2];
    const float* fw   = (const float*)d_in[wb + 0];
    const float* fb   = (const float*)d_in[wb + 1];
    const float* epw  = (const float*)d_in[wb + 2];
    const float* epb  = (const float*)d_in[wb + 3];
    const float* Aw   = (const float*)d_in[wb + 4];
    const float* Ab   = (const float*)d_in[wb + 5];
    const float* Bw   = (const float*)d_in[wb + 6];
    const float* Bb   = (const float*)d_in[wb + 7];
    const float* Cw   = (const float*)d_in[wb + 8];
    const float* Cb   = (const float*)d_in[wb + 9];
    const float* Dw   = (const float*)d_in[wb + 10];
    const float* Db   = (const float*)d_in[wb + 11];
    const float* Ew   = (const float*)d_in[wb + 12];
    const float* Eb   = (const float*)d_in[wb + 13];
    const float* bxg  = (const float*)d_in[wb + 14];
    const float* bxb  = (const float*)d_in[wb + 15];
    const float* beg  = (const float*)d_in[wb + 16];
    const float* beb  = (const float*)d_in[wb + 17];
    const float* d1w  = (const float*)d_in[wb + 18];
    const float* d1b  = (const float*)d_in[wb + 19];
    const float* d2w  = (const float*)d_in[wb + 20];
    const float* d2b  = (const float*)d_in[wb + 21];

    float *abde, *ce, *nump, *denp, *statsp, *bpackp, *fbiasp, *b0pp;
    h16 *abde_w, *c_w, *fw_w, *w0p_w;
    h16 *xh, *xl, *eh, *el, *hh, *hl, *afh, *afl;
    int *histp;
    cudaGetSymbolAddress((void**)&abde, g_ABDE);
    cudaGetSymbolAddress((void**)&ce, g_Ce);
    cudaGetSymbolAddress((void**)&nump, g_num);
    cudaGetSymbolAddress((void**)&denp, g_den);
    cudaGetSymbolAddress((void**)&statsp, g_stats);
    cudaGetSymbolAddress((void**)&bpackp, g_bpack);
    cudaGetSymbolAddress((void**)&fbiasp, g_fbias);
    cudaGetSymbolAddress((void**)&b0pp, g_b0p);
    cudaGetSymbolAddress((void**)&abde_w, g_abde_w);
    cudaGetSymbolAddress((void**)&c_w, g_c_w);
    cudaGetSymbolAddress((void**)&fw_w, g_fw_w);
    cudaGetSymbolAddress((void**)&w0p_w, g_w0p_w);
    cudaGetSymbolAddress((void**)&xh, g_xh);
    cudaGetSymbolAddress((void**)&xl, g_xl);
    cudaGetSymbolAddress((void**)&eh, g_eh);
    cudaGetSymbolAddress((void**)&el, g_el);
    cudaGetSymbolAddress((void**)&hh, g_hh);
    cudaGetSymbolAddress((void**)&hl, g_hl);
    cudaGetSymbolAddress((void**)&afh, g_afh);
    cudaGetSymbolAddress((void**)&afl, g_afl);
    cudaGetSymbolAddress((void**)&histp, g_hist);

    cudaFuncSetAttribute(gemm_tc2<0>, cudaFuncAttributeMaxDynamicSharedMemorySize, SMEM3);
    cudaFuncSetAttribute(gemm_tc2<2>, cudaFuncAttributeMaxDynamicSharedMemorySize, SMEM3);
    cudaFuncSetAttribute(gemm_ce_fused<0>, cudaFuncAttributeMaxDynamicSharedMemorySize, SMEM2);
    cudaFuncSetAttribute(gemm_ce_fused<1>, cudaFuncAttributeMaxDynamicSharedMemorySize, SMEM2);
    cudaFuncSetAttribute(gemm_dec_fused, cudaFuncAttributeMaxDynamicSharedMemorySize, SMEM2);

    // --- prep: sort edges by dst, convert weights/activations ---
    cudaMemsetAsync(histp, 0, Nn * sizeof(int));
    k_detect_idx<<<1, 256>>>((const unsigned int*)eidx);
    k_convert_idx<<<(Ee + 255) / 256, 256>>>(eidx);
    k_scan<<<1, 1024>>>();
    k_scatter<<<(Ee + 255) / 256, 256>>>();
    {
        int mg = MB0 + MB1 + MB2 + MB3 + MB4 + MB5 + MB6;
        k_megaprep<<<mg, 256>>>(Ab, Bb, Db, Eb, fw, fb, Cw, d1w, hold, af);
    }
    {
        size_t tw = (size_t)Ll * 1024 * 256;
        k_split_abde<<<(int)((tw + 255) / 256), 256>>>(Aw, Bw, Dw, Ew);
    }
    k_w0prime<<<32, 256>>>(epw, epb, Cw, Cb);
    {
        dim3 grid(Hh / 128, (Nn + 127) / 128);
        gemm_tc2<2><<<grid, 256, SMEM3>>>(hh, hl, fw_w, fbiasp,
                                          nullptr, xh, xl, Nn, Hh, Hh);
    }
    k_eproj<<<(int)(((size_t)Ee * Hh + 255) / 256), 256>>>(af, epw, epb);
    k_init_out<<<(Ee + 255) / 256, 256>>>((float*)d_out, d2b);

    for (int l = 0; l < Ll; l++) {
        cudaMemsetAsync(nump, 0, (size_t)Nn * Hh * sizeof(float));
        cudaMemsetAsync(denp, 0, (size_t)Nn * Hh * sizeof(float));
        cudaMemsetAsync(statsp, 0, 4 * Hh * sizeof(float));

        {   // fused A|B|D|E GEMM: [N,256] @ [256,1024]
            dim3 grid(4 * Hh / 128, (Nn + 127) / 128);
            gemm_tc2<0><<<grid, 256, SMEM3>>>(xh, xl,
                                              abde_w + (size_t)l * 1024 * 256,
                                              bpackp + l * 4 * Hh, abde, nullptr, nullptr,
                                              Nn, Hh, 4 * Hh);
        }
        {   // Ce GEMM + fused edge phase; layer 0 uses rank-8 collapsed form (K=32)
            dim3 grid(2, (Ee + 127) / 128);
            if (l == 0)
                gemm_ce_fused<1><<<grid, 256, SMEM2>>>(afh, afl, w0p_w, b0pp, ce, 32);
            else if (l < Ll - 1)
                gemm_ce_fused<1><<<grid, 256, SMEM2>>>(eh, el,
                                                       c_w + (size_t)l * Hh * Hh,
                                                       Cb + l * Hh, ce, 256);
            else
                gemm_ce_fused<0><<<grid, 256, SMEM2>>>(eh, el,
                                                       c_w + (size_t)l * Hh * Hh,
                                                       Cb + l * Hh, ce, 256);
        }
        k_node<<<Nn / 32, 256>>>();
        k_apply_x<<<(int)(((size_t)Nn * Hh + 255) / 256), 256>>>(bxg + l * Hh, bxb + l * Hh);
        if (l < Ll - 1)  // e dead after last layer
            k_apply_e<<<(int)(((size_t)Ee * Hh + 255) / 256), 256>>>(ce, beg + l * Hh, beb + l * Hh);
    }

    // --- decoder (dec1 GEMM with fused dec2 dot-product epilogue) ---
    {
        dim3 grid(2, (Ee + 127) / 128);
        gemm_dec_fused<<<grid, 256, SMEM2>>>(d1b, d2w, (float*)d_out);
    }
}

// round 15
// speedup vs baseline: 1.3860x; 1.1669x over previous
#include <cuda_runtime.h>
#include <cuda_fp16.h>
#include <math.h>
#include <stdint.h>

// Problem constants
#define Hh 256
#define Ll 4
#define Nn 100000
#define Ee 300000
#define BN_EPS 1e-5f
#define AGG_EPS 1e-6f
#define K_DEC 544   // 520 padded to multiple of 32

typedef __half h16;

// ------------------------- static device scratch -------------------------
__device__ float g_ABDE[(size_t)Nn * 4 * Hh];   // [N,1024]: A|B|D|E
__device__ float g_Ce[(size_t)Ee * Hh];         // e_hat scratch (sorted edge order)
__device__ float g_num[(size_t)Nn * Hh];
__device__ float g_den[(size_t)Nn * Hh];
__device__ float g_stats[4 * Hh];
__device__ float g_bpack[Ll * 4 * Hh];
__device__ float g_fbias[Hh];
__device__ float g_b0p[Hh];
__device__ int   g_src[Ee];     // sorted by dst
__device__ int   g_dst[Ee];     // sorted (non-decreasing)
__device__ int   g_eorig[Ee];
__device__ int   g_srcO[Ee];
__device__ int   g_dstO[Ee];
__device__ int   g_hist[Nn];
__device__ int   g_idx64;

// fp16 weights, transposed to [N][K]
__device__ h16 g_abde_w[(size_t)Ll * 1024 * 256];
__device__ h16 g_c_w[(size_t)Ll * 256 * 256];
__device__ h16 g_fw_w[256 * 256];
__device__ h16 g_d1_w[256 * K_DEC];
__device__ h16 g_w0p_w[256 * 32];

// fp16 hi/lo activations (residual stream reconstructed as hi+lo; GEMMs read hi only)
__device__ h16 g_xh[(size_t)Nn * Hh];
__device__ h16 g_xl[(size_t)Nn * Hh];
__device__ h16 g_eh[(size_t)Ee * Hh];
__device__ h16 g_el[(size_t)Ee * Hh];
__device__ h16 g_hh[(size_t)Nn * Hh];
__device__ h16 g_afh[(size_t)Ee * 32];

// ------------------------- prep kernels -------------------------
__global__ void k_detect_idx(const unsigned int* __restrict__ w) {
    unsigned int s = 0;
    for (int i = threadIdx.x; i < 1024; i += 256) s |= w[2 * i + 1];
#pragma unroll
    for (int off = 16; off; off >>= 1) s |= __shfl_xor_sync(0xFFFFFFFFu, s, off);
    __shared__ unsigned int red[8];
    if ((threadIdx.x & 31) == 0) red[threadIdx.x >> 5] = s;
    __syncthreads();
    if (threadIdx.x == 0) {
        unsigned int t = 0;
        for (int i = 0; i < 8; i++) t |= red[i];
        g_idx64 = (t == 0u) ? 1 : 0;
    }
}

__global__ void k_convert_idx(const void* __restrict__ eidx) {
    int i = blockIdx.x * blockDim.x + threadIdx.x;
    if (i < Ee) {
        int s, d;
        if (g_idx64) {
            const long long* p = (const long long*)eidx;
            s = (int)p[i];
            d = (int)p[(size_t)Ee + i];
        } else {
            const int* p = (const int*)eidx;
            s = p[i];
            d = p[Ee + i];
        }
        g_srcO[i] = s;
        g_dstO[i] = d;
        atomicAdd(&g_hist[d], 1);
    }
}

__global__ __launch_bounds__(1024) void k_scan() {
    __shared__ int part[1024];
    int t = threadIdx.x;
    const int CH = (Nn + 1023) / 1024;
    int base = t * CH;
    int s = 0;
    for (int j = 0; j < CH; j++) {
        int b = base + j;
        if (b < Nn) s += g_hist[b];
    }
    part[t] = s;
    __syncthreads();
    if (t == 0) {
        int acc = 0;
        for (int i = 0; i < 1024; i++) { int v = part[i]; part[i] = acc; acc += v; }
    }
    __syncthreads();
    int acc = part[t];
    for (int j = 0; j < CH; j++) {
        int b = base + j;
        if (b < Nn) { int v = g_hist[b]; g_hist[b] = acc; acc += v; }
    }
}

__global__ void k_scatter() {
    int i = blockIdx.x * blockDim.x + threadIdx.x;
    if (i < Ee) {
        int d = g_dstO[i];
        int pos = atomicAdd(&g_hist[d], 1);
        g_src[pos] = g_srcO[i];
        g_dst[pos] = d;
        g_eorig[pos] = i;
    }
}

__device__ __forceinline__ void split_write(float v, h16* hi, h16* lo, size_t i) {
    h16 h = __float2half_rn(v);
    hi[i] = h;
    lo[i] = __float2half_rn(v - __half2float(h));
}

__global__ void k_split_abde(const float* __restrict__ Aw, const float* __restrict__ Bw,
                             const float* __restrict__ Dw, const float* __restrict__ Ew) {
    size_t i = (size_t)blockIdx.x * 256 + threadIdx.x;
    if (i < (size_t)Ll * 1024 * 256) {
        int k = (int)(i & 255);
        int n = (int)((i >> 8) & 1023);
        int l = (int)(i >> 18);
        const float* W = (n < 256) ? Aw : (n < 512) ? Bw : (n < 768) ? Dw : Ew;
        g_abde_w[i] = __float2half_rn(W[(size_t)l * 65536 + (size_t)k * 256 + (n & 255)]);
    }
}

// layer-0 collapsed Ce: W0'[k8][n] = epw@C0; b0' = epb@C0 + C0b
__global__ void k_w0prime(const float* __restrict__ epw, const float* __restrict__ epb,
                          const float* __restrict__ C0, const float* __restrict__ C0b) {
    int i = blockIdx.x * 256 + threadIdx.x;
    int n = i >> 5, k = i & 31;
    float v = 0.f;
    if (k < 8) {
        for (int m = 0; m < 256; m++) v += epw[k * 256 + m] * C0[(size_t)m * 256 + n];
    }
    g_w0p_w[(size_t)n * 32 + k] = __float2half_rn(v);
    if (k == 0) {
        float b = C0b[n];
        for (int m = 0; m < 256; m++) b += epb[m] * C0[(size_t)m * 256 + n];
        g_b0p[n] = b;
    }
}

// block-range partitioned prep (af uses g_eorig -> run AFTER scatter)
#define MB0 16
#define MB1 1
#define MB2 256
#define MB3 1024
#define MB4 576
#define MB5 100000
#define MB6 75000
__global__ void k_megaprep(
    const float* __restrict__ Ab, const float* __restrict__ Bb,
    const float* __restrict__ Db, const float* __restrict__ Eb,
    const float* __restrict__ fw, const float* __restrict__ fb,
    const float* __restrict__ Cw, const float* __restrict__ d1w,
    const float* __restrict__ hold, const float* __restrict__ af)
{
    int b = blockIdx.x, t = threadIdx.x;
    if (b < MB0) {
        int i = b * 256 + t;
        if (i < Ll * 4 * Hh) {
            int j4 = i % (4 * Hh);
            int l = i / (4 * Hh);
            int which = j4 >> 8, j = j4 & 255;
            const float* B = (which == 0) ? Ab : (which == 1) ? Bb : (which == 2) ? Db : Eb;
            g_bpack[i] = B[l * Hh + j];
        }
        return;
    }
    b -= MB0;
    if (b < MB1) {
        float s = fb[t];
        for (int k = 0; k < Hh; k++) s += fw[(size_t)k * Hh + t];
        g_fbias[t] = s;
        return;
    }
    b -= MB1;
    if (b < MB2) {
        int i = b * 256 + t;
        int k = i & 255, n = i >> 8;
        g_fw_w[i] = __float2half_rn(fw[(size_t)(Hh + k) * Hh + n]);
        return;
    }
    b -= MB2;
    if (b < MB3) {
        size_t i = (size_t)b * 256 + t;
        int k = (int)(i & 255), n = (int)((i >> 8) & 255), l = (int)(i >> 16);
        g_c_w[i] = __float2half_rn(Cw[(size_t)l * 65536 + (size_t)k * 256 + n]);
        return;
    }
    b -= MB3;
    if (b < MB4) {
        int i = b * 256 + t;
        if (i < 256 * K_DEC) {
            int k = i % K_DEC, n = i / K_DEC;
            float v = (k < 520) ? d1w[(size_t)k * 256 + n] : 0.0f;
            g_d1_w[i] = __float2half_rn(v);
        }
        return;
    }
    b -= MB4;
    if (b < MB5) {
        size_t i = (size_t)b * 256 + t;
        if (i < (size_t)Nn * Hh) g_hh[i] = __float2half_rn(hold[i]);
        return;
    }
    b -= MB5;
    {
        size_t i = (size_t)b * 256 + t;
        if (i < (size_t)Ee * 32) {
            int c = (int)(i & 31);
            size_t e = i >> 5;
            float v = (c < 8) ? af[(size_t)g_eorig[e] * 8 + c] : 0.0f;
            g_afh[i] = __float2half_rn(v);
        }
    }
}

__global__ void k_init_out(float* __restrict__ out, const float* __restrict__ b2) {
    int i = blockIdx.x * blockDim.x + threadIdx.x;
    if (i < Ee) out[i] = b2[0];
}

// ------------------------- tensor-core machinery -------------------------
__device__ __forceinline__ void mma16816(float* c, const uint32_t* a, const uint32_t* b) {
    asm volatile(
        "mma.sync.aligned.m16n8k16.row.col.f32.f16.f16.f32 "
        "{%0,%1,%2,%3}, {%4,%5,%6,%7}, {%8,%9}, {%0,%1,%2,%3};"
        : "+f"(c[0]), "+f"(c[1]), "+f"(c[2]), "+f"(c[3])
        : "r"(a[0]), "r"(a[1]), "r"(a[2]), "r"(a[3]), "r"(b[0]), "r"(b[1]));
}
__device__ __forceinline__ void ldm_x4(uint32_t* r, uint32_t addr) {
    asm volatile("ldmatrix.sync.aligned.m8n8.x4.shared.b16 {%0,%1,%2,%3}, [%4];"
                 : "=r"(r[0]), "=r"(r[1]), "=r"(r[2]), "=r"(r[3]) : "r"(addr));
}
__device__ __forceinline__ void ldm_x2(uint32_t* r, uint32_t addr) {
    asm volatile("ldmatrix.sync.aligned.m8n8.x2.shared.b16 {%0,%1}, [%2];"
                 : "=r"(r[0]), "=r"(r[1]) : "r"(addr));
}
__device__ __forceinline__ void cpa16(uint32_t s, const void* g) {
    asm volatile("cp.async.cg.shared.global [%0], [%1], 16;" :: "r"(s), "l"(g));
}
__device__ __forceinline__ void cpa_commit() { asm volatile("cp.async.commit_group;"); }
template<int N>
__device__ __forceinline__ void cpa_wait() { asm volatile("cp.async.wait_group %0;" :: "n"(N) : "memory"); }

__device__ __forceinline__ int sw_off(int row, int chunk) {
    return row * 64 + ((chunk ^ ((row >> 1) & 3)) << 4);
}

__device__ __forceinline__ unsigned long long pk2(float a, float b) {
    return (unsigned long long)__float_as_uint(a) | ((unsigned long long)__float_as_uint(b) << 32);
}
__device__ __forceinline__ void upk2(unsigned long long v, float& a, float& b) {
    a = __uint_as_float((unsigned int)v);
    b = __uint_as_float((unsigned int)(v >> 32));
}
__device__ __forceinline__ uint32_t pack_h2(float a, float b) {
    __half2 t = __floats2half2_rn(a, b);
    return *(uint32_t*)&t;
}

// stage: A @0, B @8192; stride 16 KB
#define ST_B   8192
#define ST_STRIDE 16384
#define SMEM3 (3 * ST_STRIDE)   // 48 KB (pure GEMM)
#define SMEM2 (2 * ST_STRIDE)   // 32 KB (gather kernels)

// fp16x1: single pass A x B
__device__ __forceinline__ void tile_compute(
    float acc[4][4][4], uint32_t sbase, int lane, int wr, int wc) {
    uint32_t sAB = sbase, sBB = sbase + ST_B;
#pragma unroll
    for (int kg = 0; kg < 2; kg++) {
        uint32_t ra[4][4], rb[4][2];
#pragma unroll
        for (int tm = 0; tm < 4; tm++) {
            int row = wr * 64 + tm * 16 + (lane & 15);
            int ch = 2 * kg + (lane >> 4);
            ldm_x4(ra[tm], sAB + sw_off(row, ch));
        }
#pragma unroll
        for (int tn = 0; tn < 4; tn++) {
            int row = wc * 32 + tn * 8 + (lane & 7);
            int ch = 2 * kg + ((lane >> 3) & 1);
            ldm_x2(rb[tn], sBB + sw_off(row, ch));
        }
#pragma unroll
        for (int tm = 0; tm < 4; tm++)
#pragma unroll
            for (int tn = 0; tn < 4; tn++)
                mma16816(acc[tm][tn], ra[tm], rb[tn]);
    }
}

// 3-stage mainloop (pure GEMM kernels)
#define PIPE_MAIN3(K, LOADER) do { \
    LOADER(sbase0, 0); \
    if ((K) > 32) LOADER(sbase0 + ST_STRIDE, 32); else cpa_commit(); \
    for (int k0 = 0, st = 0; k0 < (K); k0 += 32, st = (st == 2) ? 0 : st + 1) { \
        cpa_wait<1>(); \
        __syncthreads(); \
        if (k0 + 64 < (K)) { \
            int st2 = st + 2; if (st2 >= 3) st2 -= 3; \
            LOADER(sbase0 + st2 * ST_STRIDE, k0 + 64); \
        } else cpa_commit(); \
        tile_compute(acc, sbase0 + st * ST_STRIDE, lane, wr, wc); \
    } \
} while (0)

// 2-stage mainloop (gather kernels)
#define PIPE_MAIN2(K, LOADER) do { \
    LOADER(sbase0, 0); \
    int cur = 0; \
    for (int k0 = 0; k0 < (K); k0 += 32) { \
        cpa_wait<0>(); \
        __syncthreads(); \
        if (k0 + 32 < (K)) LOADER(sbase0 + (cur ^ 1) * ST_STRIDE, k0 + 32); \
        tile_compute(acc, sbase0 + cur * ST_STRIDE, lane, wr, wc); \
        cur ^= 1; \
    } \
} while (0)

// ------------------------- fp16 GEMM, 3-stage pipeline -------------------------
// EPI: 0 = bias -> fp32 C; 2 = bias+relu -> fp16 hi/lo ONLY
template<int EPI>
__global__ __launch_bounds__(256) void gemm_tc2(
    const h16* __restrict__ A, const h16* __restrict__ Bw,
    const float* __restrict__ bias, float* __restrict__ C,
    h16* __restrict__ Chi, h16* __restrict__ Clo,
    int M, int K, int Nc)
{
    extern __shared__ __align__(16) char smem[];
    uint32_t sbase0 = (uint32_t)__cvta_generic_to_shared(smem);

    int tid = threadIdx.x, lane = tid & 31, w = tid >> 5;
    int wr = w >> 2, wc = w & 3;
    int bm = blockIdx.y * 128, bn = blockIdx.x * 128;

    int r = tid >> 1, ch0 = (tid & 1) * 2;
    int gr = bm + r; if (gr >= M) gr = M - 1;
    size_t aRow = (size_t)gr * K;
    size_t bRow = (size_t)(bn + r) * K;

    float acc[4][4][4];
#pragma unroll
    for (int i = 0; i < 4; i++)
#pragma unroll
        for (int j = 0; j < 4; j++)
#pragma unroll
            for (int q = 0; q < 4; q++) acc[i][j][q] = 0.f;

    auto load_stage = [&](uint32_t sb, int k0) {
#pragma unroll
        for (int i = 0; i < 2; i++) {
            int ch = ch0 + i;
            uint32_t so = sw_off(r, ch);
            size_t go = (size_t)k0 + ch * 8;
            cpa16(sb + so,        A + aRow + go);
            cpa16(sb + ST_B + so, Bw + bRow + go);
        }
        cpa_commit();
    };

    PIPE_MAIN3(K, load_stage);

    int g = lane >> 2, tig = lane & 3;
#pragma unroll
    for (int tm = 0; tm < 4; tm++) {
        int r0 = bm + wr * 64 + tm * 16 + g;
#pragma unroll
        for (int tn = 0; tn < 4; tn++) {
            int col = bn + wc * 32 + tn * 8 + 2 * tig;
            float b0 = bias[col], b1 = bias[col + 1];
            float v0 = acc[tm][tn][0] + b0, v1 = acc[tm][tn][1] + b1;
            float v2 = acc[tm][tn][2] + b0, v3 = acc[tm][tn][3] + b1;
            if (EPI >= 1) {
                v0 = fmaxf(v0, 0.f); v1 = fmaxf(v1, 0.f);
                v2 = fmaxf(v2, 0.f); v3 = fmaxf(v3, 0.f);
            }
            if (r0 < M) {
                size_t o = (size_t)r0 * Nc + col;
                if (EPI != 2) { float2 t = {v0, v1}; *(float2*)&C[o] = t; }
                else {
                    h16 h0 = __float2half_rn(v0), h1 = __float2half_rn(v1);
                    __half2 hp = __halves2half2(h0, h1);
                    *(uint32_t*)&Chi[o] = *(uint32_t*)&hp;
                    *(uint32_t*)&Clo[o] = pack_h2(v0 - __half2float(h0), v1 - __half2float(h1));
                }
            }
            if (r0 + 8 < M) {
                size_t o = (size_t)(r0 + 8) * Nc + col;
                if (EPI != 2) { float2 t = {v2, v3}; *(float2*)&C[o] = t; }
                else {
                    h16 h2 = __float2half_rn(v2), h3 = __float2half_rn(v3);
                    __half2 hp = __halves2half2(h2, h3);
                    *(uint32_t*)&Chi[o] = *(uint32_t*)&hp;
                    *(uint32_t*)&Clo[o] = pack_h2(v2 - __half2float(h2), v3 - __half2float(h3));
                }
            }
        }
    }
}

// ------------------------- Ce GEMM with fused edge epilogue (2-stage, runtime K) -------------------------
template<int WRITE_EH>
__global__ __launch_bounds__(256) void gemm_ce_fused(
    const h16* __restrict__ A, const h16* __restrict__ Bw,
    const float* __restrict__ bias, float* __restrict__ EHout, int K)
{
    const int M = Ee, Nc = 256;
    const unsigned FULL = 0xFFFFFFFFu;
    extern __shared__ __align__(16) char smem[];
    uint32_t sbase0 = (uint32_t)__cvta_generic_to_shared(smem);

    int tid = threadIdx.x, lane = tid & 31, w = tid >> 5;
    int wr = w >> 2, wc = w & 3;
    int bm = blockIdx.y * 128, bn = blockIdx.x * 128;

    int r = tid >> 1, ch0 = (tid & 1) * 2;
    int gr = bm + r; if (gr >= M) gr = M - 1;
    size_t aRow = (size_t)gr * K;
    size_t bRow = (size_t)(bn + r) * K;

    float acc[4][4][4];
#pragma unroll
    for (int i = 0; i < 4; i++)
#pragma unroll
        for (int j = 0; j < 4; j++)
#pragma unroll
            for (int q = 0; q < 4; q++) acc[i][j][q] = 0.f;

    auto load_stage = [&](uint32_t sb, int k0) {
#pragma unroll
        for (int i = 0; i < 2; i++) {
            int ch = ch0 + i;
            uint32_t so = sw_off(r, ch);
            size_t go = (size_t)k0 + ch * 8;
            cpa16(sb + so,        A + aRow + go);
            cpa16(sb + ST_B + so, Bw + bRow + go);
        }
        cpa_commit();
    };

    PIPE_MAIN2(K, load_stage);

    int g = lane >> 2, tig = lane & 3;
    float ls[4][2], lq[4][2];
    if (WRITE_EH) {
#pragma unroll
        for (int tn = 0; tn < 4; tn++) { ls[tn][0] = ls[tn][1] = lq[tn][0] = lq[tn][1] = 0.f; }
    }

#pragma unroll
    for (int tm = 0; tm < 4; tm++) {
#pragma unroll
        for (int half = 0; half < 2; half++) {
            int e = bm + wr * 64 + tm * 16 + g + 8 * half;
            bool ok = e < M;
            int ec = ok ? e : (M - 1);
            int sN = g_src[ec], dN = g_dst[ec];
            int dkey = ok ? dN : (-1 - g);
            const float* Drow = g_ABDE + (size_t)dN * 1024 + 512;
            const float* Erow = g_ABDE + (size_t)sN * 1024 + 768;
            const float* Brow = g_ABDE + (size_t)sN * 1024 + 256;
            float* nrow = g_num + (size_t)dN * Hh;
            float* drow = g_den + (size_t)dN * Hh;

            int od1 = __shfl_down_sync(FULL, dkey, 4);
            int od2 = __shfl_down_sync(FULL, dkey, 8);
            int od4 = __shfl_down_sync(FULL, dkey, 16);
            int dup = __shfl_up_sync(FULL, dkey, 4);
            bool t1 = (g + 1 < 8) && (od1 == dkey);
            bool t2 = (g + 2 < 8) && (od2 == dkey);
            bool t4 = (g + 4 < 8) && (od4 == dkey);
            bool leader = ok && (g == 0 || dup != dkey);

#pragma unroll
            for (int tn = 0; tn < 4; tn++) {
                int col = bn + wc * 32 + tn * 8 + 2 * tig;
                float2 dv = *(const float2*)&Drow[col];
                float2 ev = *(const float2*)&Erow[col];
                float2 bv = *(const float2*)&Brow[col];
                float eh0 = acc[tm][tn][2 * half + 0] + bias[col]     + dv.x + ev.x;
                float eh1 = acc[tm][tn][2 * half + 1] + bias[col + 1] + dv.y + ev.y;
                float sg0 = 1.f / (1.f + __expf(-eh0));
                float sg1 = 1.f / (1.f + __expf(-eh1));
                float n0 = ok ? sg0 * bv.x : 0.f;
                float n1 = ok ? sg1 * bv.y : 0.f;
                float s0 = ok ? sg0 : 0.f;
                float s1 = ok ? sg1 : 0.f;

                if (WRITE_EH && ok) {
                    float2 t = {eh0, eh1};
                    *(float2*)&EHout[(size_t)e * Nc + col] = t;
                    ls[tn][0] += eh0; ls[tn][1] += eh1;
                    lq[tn][0] += eh0 * eh0; lq[tn][1] += eh1 * eh1;
                }

                {
                    unsigned long long on = __shfl_down_sync(FULL, pk2(n0, n1), 4);
                    unsigned long long os = __shfl_down_sync(FULL, pk2(s0, s1), 4);
                    if (t1) { float a, b; upk2(on, a, b); n0 += a; n1 += b; upk2(os, a, b); s0 += a; s1 += b; }
                }
                {
                    unsigned long long on = __shfl_down_sync(FULL, pk2(n0, n1), 8);
                    unsigned long long os = __shfl_down_sync(FULL, pk2(s0, s1), 8);
                    if (t2) { float a, b; upk2(on, a, b); n0 += a; n1 += b; upk2(os, a, b); s0 += a; s1 += b; }
                }
                {
                    unsigned long long on = __shfl_down_sync(FULL, pk2(n0, n1), 16);
                    unsigned long long os = __shfl_down_sync(FULL, pk2(s0, s1), 16);
                    if (t4) { float a, b; upk2(on, a, b); n0 += a; n1 += b; upk2(os, a, b); s0 += a; s1 += b; }
                }
                if (leader) {
                    atomicAdd(&nrow[col],     n0);
                    atomicAdd(&nrow[col + 1], n1);
                    atomicAdd(&drow[col],     s0);
                    atomicAdd(&drow[col + 1], s1);
                }
            }
        }
    }

    if (WRITE_EH) {
#pragma unroll
        for (int tn = 0; tn < 4; tn++) {
#pragma unroll
            for (int j = 0; j < 2; j++) {
                float v = ls[tn][j], q = lq[tn][j];
#pragma unroll
                for (int off = 4; off <= 16; off <<= 1) {
                    v += __shfl_xor_sync(0xFFFFFFFFu, v, off);
                    q += __shfl_xor_sync(0xFFFFFFFFu, q, off);
                }
                if (g == 0) {
                    int col = bn + wc * 32 + tn * 8 + 2 * tig + j;
                    atomicAdd(&g_stats[2 * Hh + col], v);
                    atomicAdd(&g_stats[3 * Hh + col], q);
                }
            }
        }
    }
}

// ------------------------- decoder gather-GEMM with fused dec2 (2-stage) -------------------------
__global__ __launch_bounds__(256) void gemm_dec_fused(
    const float* __restrict__ bias, const float* __restrict__ w2,
    float* __restrict__ out)
{
    const int K = K_DEC, M = Ee;
    extern __shared__ __align__(16) char smem[];
    uint32_t sbase0 = (uint32_t)__cvta_generic_to_shared(smem);

    int tid = threadIdx.x, lane = tid & 31, w = tid >> 5;
    int wr = w >> 2, wc = w & 3;
    int bm = blockIdx.y * 128, bn = blockIdx.x * 128;

    int r = tid >> 1, ch0 = (tid & 1) * 2;
    int e = bm + r; if (e >= M) e = M - 1;
    int sN = g_src[e], dN = g_dst[e];
    size_t bRow = (size_t)(bn + r) * K;

    float acc[4][4][4];
#pragma unroll
    for (int i = 0; i < 4; i++)
#pragma unroll
        for (int j = 0; j < 4; j++)
#pragma unroll
            for (int q = 0; q < 4; q++) acc[i][j][q] = 0.f;

    auto load_stage = [&](uint32_t sb, int k0) {
#pragma unroll
        for (int i = 0; i < 2; i++) {
            int ch = ch0 + i;
            uint32_t so = sw_off(r, ch);
            int c0 = k0 + ch * 8;
            const h16* ph;
            if (c0 < 256)      ph = g_xh + (size_t)sN * Hh + c0;
            else if (c0 < 512) ph = g_xh + (size_t)dN * Hh + (c0 - 256);
            else               ph = g_afh + (size_t)e * 32 + (c0 - 512);
            cpa16(sb + so,        ph);
            cpa16(sb + ST_B + so, g_d1_w + bRow + c0);
        }
        cpa_commit();
    };

    PIPE_MAIN2(K, load_stage);

    int g = lane >> 2, tig = lane & 3;
#pragma unroll
    for (int tm = 0; tm < 4; tm++) {
        int r0 = bm + wr * 64 + tm * 16 + g;
        float p0 = 0.f, p1 = 0.f;
#pragma unroll
        for (int tn = 0; tn < 4; tn++) {
            int col = bn + wc * 32 + tn * 8 + 2 * tig;
            float b0 = bias[col], b1 = bias[col + 1];
            float w0 = w2[col], w1 = w2[col + 1];
            p0 += fmaxf(acc[tm][tn][0] + b0, 0.f) * w0 + fmaxf(acc[tm][tn][1] + b1, 0.f) * w1;
            p1 += fmaxf(acc[tm][tn][2] + b0, 0.f) * w0 + fmaxf(acc[tm][tn][3] + b1, 0.f) * w1;
        }
        p0 += __shfl_xor_sync(0xFFFFFFFFu, p0, 1);
        p0 += __shfl_xor_sync(0xFFFFFFFFu, p0, 2);
        p1 += __shfl_xor_sync(0xFFFFFFFFu, p1, 1);
        p1 += __shfl_xor_sync(0xFFFFFFFFu, p1, 2);
        if (tig == 0) {
            if (r0 < M)     atomicAdd(&out[g_eorig[r0]], p0);
            if (r0 + 8 < M) atomicAdd(&out[g_eorig[r0 + 8]], p1);
        }
    }
}

// ------------------------- edge projection (K=8, sorted order) -------------------------
__global__ void k_eproj(const float* __restrict__ af, const float* __restrict__ W,
                        const float* __restrict__ b) {
    size_t idx = (size_t)blockIdx.x * blockDim.x + threadIdx.x;
    if (idx < (size_t)Ee * Hh) {
        int c = (int)(idx & 255);
        size_t e = idx >> 8;
        size_t eo = (size_t)g_eorig[e];
        float v = b[c];
#pragma unroll
        for (int k = 0; k < 8; k++) v += af[eo * 8 + k] * W[k * Hh + c];
        split_write(v, g_eh, g_el, idx);
    }
}

// ------------------------- per-layer node kernels -------------------------
__global__ __launch_bounds__(256) void k_node() {
    int c = threadIdx.x;
    int base = blockIdx.x * 32;
    float s = 0.f, sq = 0.f;
    for (int i = 0; i < 32; i++) {
        int n = base + i;
        size_t o = (size_t)n * Hh + c;
        float xc = g_ABDE[(size_t)n * 1024 + c] + g_num[o] / (g_den[o] + AGG_EPS);
        g_num[o] = xc;
        s += xc; sq += xc * xc;
    }
    atomicAdd(&g_stats[c], s);
    atomicAdd(&g_stats[Hh + c], sq);
}

__global__ void k_apply_x(const float* __restrict__ gam, const float* __restrict__ bet) {
    size_t idx = (size_t)blockIdx.x * blockDim.x + threadIdx.x;
    if (idx < (size_t)Nn * Hh) {
        int c = (int)(idx & 255);
        float mu = g_stats[c] * (1.f / Nn);
        float var = g_stats[Hh + c] * (1.f / Nn) - mu * mu;
        float v = gam[c] * (g_num[idx] - mu) * rsqrtf(var + BN_EPS) + bet[c];
        float old = __half2float(g_xh[idx]) + __half2float(g_xl[idx]);
        float o = old + fmaxf(v, 0.f);
        split_write(o, g_xh, g_xl, idx);
    }
}

__global__ void k_apply_e(const float* __restrict__ ehat,
                          const float* __restrict__ gam, const float* __restrict__ bet) {
    size_t idx = (size_t)blockIdx.x * blockDim.x + threadIdx.x;
    if (idx < (size_t)Ee * Hh) {
        int c = (int)(idx & 255);
        float mu = g_stats[2 * Hh + c] * (1.f / Ee);
        float var = g_stats[3 * Hh + c] * (1.f / Ee) - mu * mu;
        float v = gam[c] * (ehat[idx] - mu) * rsqrtf(var + BN_EPS) + bet[c];
        float old = __half2float(g_eh[idx]) + __half2float(g_el[idx]);
        float o = old + fmaxf(v, 0.f);
        split_write(o, g_eh, g_el, idx);
    }
}

// ------------------------- host launcher -------------------------
extern "C" void kernel_launch(void* const* d_in, const int* in_sizes, int n_in,
                              void* d_out, int out_size)
{
    int wb = 3;
    for (int i = 3; i < n_in && i < 6; i++) {
        if (in_sizes[i] == 2 * Hh * Hh) { wb = i; break; }
    }

    const void*  eidx = d_in[0];
    const float* af   = (const float*)d_in[1];
    const float* hold = (const float*)d_in[2];
    const float* fw   = (const float*)d_in[wb + 0];
    const float* fb   = (const float*)d_in[wb + 1];
    const float* epw  = (const float*)d_in[wb + 2];
    const float* epb  = (const float*)d_in[wb + 3];
    const float* Aw   = (const float*)d_in[wb + 4];
    const float* Ab   = (const float*)d_in[wb + 5];
    const float* Bw   = (const float*)d_in[wb + 6];
    const float* Bb   = (const float*)d_in[wb + 7];
    const float* Cw   = (const float*)d_in[wb + 8];
    const float* Cb   = (const float*)d_in[wb + 9];
    const float* Dw   = (const float*)d_in[wb + 10];
    const float* Db   = (const float*)d_in[wb + 11];
    const float* Ew   = (const float*)d_in[wb + 12];
    const float* Eb   = (const float*)d_in[wb + 13];
    const float* bxg  = (const float*)d_in[wb + 14];
    const float* bxb  = (const float*)d_in[wb + 15];
    const float* beg  = (const float*)d_in[wb + 16];
    const float* beb  = (const float*)d_in[wb + 17];
    const float* d1w  = (const float*)d_in[wb + 18];
    const float* d1b  = (const float*)d_in[wb + 19];
    const float* d2w  = (const float*)d_in[wb + 20];
    const float* d2b  = (const float*)d_in[wb + 21];

    float *abde, *ce, *nump, *denp, *statsp, *bpackp, *fbiasp, *b0pp;
    h16 *abde_w, *c_w, *fw_w, *w0p_w;
    h16 *xh, *xl, *eh, *el, *hh, *afh;
    int *histp;
    cudaGetSymbolAddress((void**)&abde, g_ABDE);
    cudaGetSymbolAddress((void**)&ce, g_Ce);
    cudaGetSymbolAddress((void**)&nump, g_num);
    cudaGetSymbolAddress((void**)&denp, g_den);
    cudaGetSymbolAddress((void**)&statsp, g_stats);
    cudaGetSymbolAddress((void**)&bpackp, g_bpack);
    cudaGetSymbolAddress((void**)&fbiasp, g_fbias);
    cudaGetSymbolAddress((void**)&b0pp, g_b0p);
    cudaGetSymbolAddress((void**)&abde_w, g_abde_w);
    cudaGetSymbolAddress((void**)&c_w, g_c_w);
    cudaGetSymbolAddress((void**)&fw_w, g_fw_w);
    cudaGetSymbolAddress((void**)&w0p_w, g_w0p_w);
    cudaGetSymbolAddress((void**)&xh, g_xh);
    cudaGetSymbolAddress((void**)&xl, g_xl);
    cudaGetSymbolAddress((void**)&eh, g_eh);
    cudaGetSymbolAddress((void**)&el, g_el);
    cudaGetSymbolAddress((void**)&hh, g_hh);
    cudaGetSymbolAddress((void**)&afh, g_afh);
    cudaGetSymbolAddress((void**)&histp, g_hist);

    cudaFuncSetAttribute(gemm_tc2<0>, cudaFuncAttributeMaxDynamicSharedMemorySize, SMEM3);
    cudaFuncSetAttribute(gemm_tc2<2>, cudaFuncAttributeMaxDynamicSharedMemorySize, SMEM3);
    cudaFuncSetAttribute(gemm_ce_fused<0>, cudaFuncAttributeMaxDynamicSharedMemorySize, SMEM2);
    cudaFuncSetAttribute(gemm_ce_fused<1>, cudaFuncAttributeMaxDynamicSharedMemorySize, SMEM2);
    cudaFuncSetAttribute(gemm_dec_fused, cudaFuncAttributeMaxDynamicSharedMemorySize, SMEM2);

    // --- prep: sort edges by dst, convert weights/activations ---
    cudaMemsetAsync(histp, 0, Nn * sizeof(int));
    k_detect_idx<<<1, 256>>>((const unsigned int*)eidx);
    k_convert_idx<<<(Ee + 255) / 256, 256>>>(eidx);
    k_scan<<<1, 1024>>>();
    k_scatter<<<(Ee + 255) / 256, 256>>>();
    {
        int mg = MB0 + MB1 + MB2 + MB3 + MB4 + MB5 + MB6;
        k_megaprep<<<mg, 256>>>(Ab, Bb, Db, Eb, fw, fb, Cw, d1w, hold, af);
    }
    {
        size_t tw = (size_t)Ll * 1024 * 256;
        k_split_abde<<<(int)((tw + 255) / 256), 256>>>(Aw, Bw, Dw, Ew);
    }
    k_w0prime<<<32, 256>>>(epw, epb, Cw, Cb);
    {
        dim3 grid(Hh / 128, (Nn + 127) / 128);
        gemm_tc2<2><<<grid, 256, SMEM3>>>(hh, fw_w, fbiasp,
                                          nullptr, xh, xl, Nn, Hh, Hh);
    }
    k_eproj<<<(int)(((size_t)Ee * Hh + 255) / 256), 256>>>(af, epw, epb);
    k_init_out<<<(Ee + 255) / 256, 256>>>((float*)d_out, d2b);

    for (int l = 0; l < Ll; l++) {
        cudaMemsetAsync(nump, 0, (size_t)Nn * Hh * sizeof(float));
        cudaMemsetAsync(denp, 0, (size_t)Nn * Hh * sizeof(float));
        cudaMemsetAsync(statsp, 0, 4 * Hh * sizeof(float));

        {   // fused A|B|D|E GEMM: [N,256] @ [256,1024]
            dim3 grid(4 * Hh / 128, (Nn + 127) / 128);
            gemm_tc2<0><<<grid, 256, SMEM3>>>(xh,
                                              abde_w + (size_t)l * 1024 * 256,
                                              bpackp + l * 4 * Hh, abde, nullptr, nullptr,
                                              Nn, Hh, 4 * Hh);
        }
        {   // Ce GEMM + fused edge phase; layer 0 uses rank-8 collapsed form (K=32)
            dim3 grid(2, (Ee + 127) / 128);
            if (l == 0)
                gemm_ce_fused<1><<<grid, 256, SMEM2>>>(afh, w0p_w, b0pp, ce, 32);
            else if (l < Ll - 1)
                gemm_ce_fused<1><<<grid, 256, SMEM2>>>(eh,
                                                       c_w + (size_t)l * Hh * Hh,
                                                       Cb + l * Hh, ce, 256);
            else
                gemm_ce_fused<0><<<grid, 256, SMEM2>>>(eh,
                                                       c_w + (size_t)l * Hh * Hh,
                                                       Cb + l * Hh, ce, 256);
        }
        k_node<<<Nn / 32, 256>>>();
        k_apply_x<<<(int)(((size_t)Nn * Hh + 255) / 256), 256>>>(bxg + l * Hh, bxb + l * Hh);
        if (l < Ll - 1)  // e dead after last layer
            k_apply_e<<<(int)(((size_t)Ee * Hh + 255) / 256), 256>>>(ce, beg + l * Hh, beb + l * Hh);
    }

    // --- decoder (dec1 GEMM with fused dec2 dot-product epilogue) ---
    {
        dim3 grid(2, (Ee + 127) / 128);
        gemm_dec_fused<<<grid, 256, SMEM2>>>(d1b, d2w, (float*)d_out);
    }
}

// round 16
// speedup vs baseline: 1.4009x; 1.0108x over previous
#include <cuda_runtime.h>
#include <cuda_fp16.h>
#include <math.h>
#include <stdint.h>

// Problem constants
#define Hh 256
#define Ll 4
#define Nn 100000
#define Ee 300000
#define BN_EPS 1e-5f
#define AGG_EPS 1e-6f
#define K_DEC 544   // 520 padded to multiple of 32

typedef __half h16;

// ------------------------- static device scratch -------------------------
__device__ h16   g_ABDE[(size_t)Nn * 4 * Hh];   // fp16 [N,1024]: A|B|D|E (bias folded in)
__device__ h16   g_EH[(size_t)Ee * Hh];         // e_hat fp16 (sorted edge order)
__device__ float g_num[(size_t)Nn * Hh];
__device__ float g_den[(size_t)Nn * Hh];
__device__ float g_stats[4 * Hh];
__device__ float g_bpack[Ll * 4 * Hh];
__device__ float g_fbias[Hh];
__device__ float g_b0p[Hh];
__device__ int   g_src[Ee];     // sorted by dst
__device__ int   g_dst[Ee];     // sorted (non-decreasing)
__device__ int   g_eorig[Ee];
__device__ int   g_srcO[Ee];
__device__ int   g_dstO[Ee];
__device__ int   g_hist[Nn];
__device__ int   g_idx64;

// fp16 weights, transposed to [N][K]
__device__ h16 g_abde_w[(size_t)Ll * 1024 * 256];
__device__ h16 g_c_w[(size_t)Ll * 256 * 256];
__device__ h16 g_fw_w[256 * 256];
__device__ h16 g_d1_w[256 * K_DEC];
__device__ h16 g_w0p_w[256 * 32];

// fp16 hi/lo activations (residual stream = hi+lo; GEMMs read hi only)
__device__ h16 g_xh[(size_t)Nn * Hh];
__device__ h16 g_xl[(size_t)Nn * Hh];
__device__ h16 g_eh[(size_t)Ee * Hh];
__device__ h16 g_el[(size_t)Ee * Hh];
__device__ h16 g_hh[(size_t)Nn * Hh];
__device__ h16 g_afh[(size_t)Ee * 32];

// ------------------------- prep kernels -------------------------
__global__ void k_detect_idx(const unsigned int* __restrict__ w) {
    unsigned int s = 0;
    for (int i = threadIdx.x; i < 1024; i += 256) s |= w[2 * i + 1];
#pragma unroll
    for (int off = 16; off; off >>= 1) s |= __shfl_xor_sync(0xFFFFFFFFu, s, off);
    __shared__ unsigned int red[8];
    if ((threadIdx.x & 31) == 0) red[threadIdx.x >> 5] = s;
    __syncthreads();
    if (threadIdx.x == 0) {
        unsigned int t = 0;
        for (int i = 0; i < 8; i++) t |= red[i];
        g_idx64 = (t == 0u) ? 1 : 0;
    }
}

__global__ void k_convert_idx(const void* __restrict__ eidx) {
    int i = blockIdx.x * blockDim.x + threadIdx.x;
    if (i < Ee) {
        int s, d;
        if (g_idx64) {
            const long long* p = (const long long*)eidx;
            s = (int)p[i];
            d = (int)p[(size_t)Ee + i];
        } else {
            const int* p = (const int*)eidx;
            s = p[i];
            d = p[Ee + i];
        }
        g_srcO[i] = s;
        g_dstO[i] = d;
        atomicAdd(&g_hist[d], 1);
    }
}

__global__ __launch_bounds__(1024) void k_scan() {
    __shared__ int part[1024];
    int t = threadIdx.x;
    const int CH = (Nn + 1023) / 1024;
    int base = t * CH;
    int s = 0;
    for (int j = 0; j < CH; j++) {
        int b = base + j;
        if (b < Nn) s += g_hist[b];
    }
    part[t] = s;
    __syncthreads();
    if (t == 0) {
        int acc = 0;
        for (int i = 0; i < 1024; i++) { int v = part[i]; part[i] = acc; acc += v; }
    }
    __syncthreads();
    int acc = part[t];
    for (int j = 0; j < CH; j++) {
        int b = base + j;
        if (b < Nn) { int v = g_hist[b]; g_hist[b] = acc; acc += v; }
    }
}

__global__ void k_scatter() {
    int i = blockIdx.x * blockDim.x + threadIdx.x;
    if (i < Ee) {
        int d = g_dstO[i];
        int pos = atomicAdd(&g_hist[d], 1);
        g_src[pos] = g_srcO[i];
        g_dst[pos] = d;
        g_eorig[pos] = i;
    }
}

__device__ __forceinline__ void split_write(float v, h16* hi, h16* lo, size_t i) {
    h16 h = __float2half_rn(v);
    hi[i] = h;
    lo[i] = __float2half_rn(v - __half2float(h));
}

__global__ void k_split_abde(const float* __restrict__ Aw, const float* __restrict__ Bw,
                             const float* __restrict__ Dw, const float* __restrict__ Ew) {
    size_t i = (size_t)blockIdx.x * 256 + threadIdx.x;
    if (i < (size_t)Ll * 1024 * 256) {
        int k = (int)(i & 255);
        int n = (int)((i >> 8) & 1023);
        int l = (int)(i >> 18);
        const float* W = (n < 256) ? Aw : (n < 512) ? Bw : (n < 768) ? Dw : Ew;
        g_abde_w[i] = __float2half_rn(W[(size_t)l * 65536 + (size_t)k * 256 + (n & 255)]);
    }
}

// layer-0 collapsed Ce: W0'[k8][n] = epw@C0; b0' = epb@C0 + C0b
__global__ void k_w0prime(const float* __restrict__ epw, const float* __restrict__ epb,
                          const float* __restrict__ C0, const float* __restrict__ C0b) {
    int i = blockIdx.x * 256 + threadIdx.x;
    int n = i >> 5, k = i & 31;
    float v = 0.f;
    if (k < 8) {
        for (int m = 0; m < 256; m++) v += epw[k * 256 + m] * C0[(size_t)m * 256 + n];
    }
    g_w0p_w[(size_t)n * 32 + k] = __float2half_rn(v);
    if (k == 0) {
        float b = C0b[n];
        for (int m = 0; m < 256; m++) b += epb[m] * C0[(size_t)m * 256 + n];
        g_b0p[n] = b;
    }
}

// block-range partitioned prep (af uses g_eorig -> run AFTER scatter)
#define MB0 16
#define MB1 1
#define MB2 256
#define MB3 1024
#define MB4 576
#define MB5 100000
#define MB6 75000
__global__ void k_megaprep(
    const float* __restrict__ Ab, const float* __restrict__ Bb,
    const float* __restrict__ Db, const float* __restrict__ Eb,
    const float* __restrict__ fw, const float* __restrict__ fb,
    const float* __restrict__ Cw, const float* __restrict__ d1w,
    const float* __restrict__ hold, const float* __restrict__ af)
{
    int b = blockIdx.x, t = threadIdx.x;
    if (b < MB0) {
        int i = b * 256 + t;
        if (i < Ll * 4 * Hh) {
            int j4 = i % (4 * Hh);
            int l = i / (4 * Hh);
            int which = j4 >> 8, j = j4 & 255;
            const float* B = (which == 0) ? Ab : (which == 1) ? Bb : (which == 2) ? Db : Eb;
            g_bpack[i] = B[l * Hh + j];
        }
        return;
    }
    b -= MB0;
    if (b < MB1) {
        float s = fb[t];
        for (int k = 0; k < Hh; k++) s += fw[(size_t)k * Hh + t];
        g_fbias[t] = s;
        return;
    }
    b -= MB1;
    if (b < MB2) {
        int i = b * 256 + t;
        int k = i & 255, n = i >> 8;
        g_fw_w[i] = __float2half_rn(fw[(size_t)(Hh + k) * Hh + n]);
        return;
    }
    b -= MB2;
    if (b < MB3) {
        size_t i = (size_t)b * 256 + t;
        int k = (int)(i & 255), n = (int)((i >> 8) & 255), l = (int)(i >> 16);
        g_c_w[i] = __float2half_rn(Cw[(size_t)l * 65536 + (size_t)k * 256 + n]);
        return;
    }
    b -= MB3;
    if (b < MB4) {
        int i = b * 256 + t;
        if (i < 256 * K_DEC) {
            int k = i % K_DEC, n = i / K_DEC;
            float v = (k < 520) ? d1w[(size_t)k * 256 + n] : 0.0f;
            g_d1_w[i] = __float2half_rn(v);
        }
        return;
    }
    b -= MB4;
    if (b < MB5) {
        size_t i = (size_t)b * 256 + t;
        if (i < (size_t)Nn * Hh) g_hh[i] = __float2half_rn(hold[i]);
        return;
    }
    b -= MB5;
    {
        size_t i = (size_t)b * 256 + t;
        if (i < (size_t)Ee * 32) {
            int c = (int)(i & 31);
            size_t e = i >> 5;
            float v = (c < 8) ? af[(size_t)g_eorig[e] * 8 + c] : 0.0f;
            g_afh[i] = __float2half_rn(v);
        }
    }
}

__global__ void k_init_out(float* __restrict__ out, const float* __restrict__ b2) {
    int i = blockIdx.x * blockDim.x + threadIdx.x;
    if (i < Ee) out[i] = b2[0];
}

// ------------------------- tensor-core machinery -------------------------
__device__ __forceinline__ void mma16816(float* c, const uint32_t* a, const uint32_t* b) {
    asm volatile(
        "mma.sync.aligned.m16n8k16.row.col.f32.f16.f16.f32 "
        "{%0,%1,%2,%3}, {%4,%5,%6,%7}, {%8,%9}, {%0,%1,%2,%3};"
        : "+f"(c[0]), "+f"(c[1]), "+f"(c[2]), "+f"(c[3])
        : "r"(a[0]), "r"(a[1]), "r"(a[2]), "r"(a[3]), "r"(b[0]), "r"(b[1]));
}
__device__ __forceinline__ void ldm_x4(uint32_t* r, uint32_t addr) {
    asm volatile("ldmatrix.sync.aligned.m8n8.x4.shared.b16 {%0,%1,%2,%3}, [%4];"
                 : "=r"(r[0]), "=r"(r[1]), "=r"(r[2]), "=r"(r[3]) : "r"(addr));
}
__device__ __forceinline__ void ldm_x2(uint32_t* r, uint32_t addr) {
    asm volatile("ldmatrix.sync.aligned.m8n8.x2.shared.b16 {%0,%1}, [%2];"
                 : "=r"(r[0]), "=r"(r[1]) : "r"(addr));
}
__device__ __forceinline__ void cpa16(uint32_t s, const void* g) {
    asm volatile("cp.async.cg.shared.global [%0], [%1], 16;" :: "r"(s), "l"(g));
}
__device__ __forceinline__ void cpa_commit() { asm volatile("cp.async.commit_group;"); }
template<int N>
__device__ __forceinline__ void cpa_wait() { asm volatile("cp.async.wait_group %0;" :: "n"(N) : "memory"); }

__device__ __forceinline__ int sw_off(int row, int chunk) {
    return row * 64 + ((chunk ^ ((row >> 1) & 3)) << 4);
}

__device__ __forceinline__ unsigned long long pk2(float a, float b) {
    return (unsigned long long)__float_as_uint(a) | ((unsigned long long)__float_as_uint(b) << 32);
}
__device__ __forceinline__ void upk2(unsigned long long v, float& a, float& b) {
    a = __uint_as_float((unsigned int)v);
    b = __uint_as_float((unsigned int)(v >> 32));
}
__device__ __forceinline__ uint32_t pack_h2(float a, float b) {
    __half2 t = __floats2half2_rn(a, b);
    return *(uint32_t*)&t;
}
__device__ __forceinline__ float2 ldh2(const h16* p) {
    __half2 v = *(const __half2*)p;
    return __half22float2(v);
}

// stage: A @0, B @8192; stride 16 KB
#define ST_B   8192
#define ST_STRIDE 16384
#define SMEM3 (3 * ST_STRIDE)   // 48 KB (pure GEMM)
#define SMEM2 (2 * ST_STRIDE)   // 32 KB (gather kernels)

// fp16x1: single pass A x B
__device__ __forceinline__ void tile_compute(
    float acc[4][4][4], uint32_t sbase, int lane, int wr, int wc) {
    uint32_t sAB = sbase, sBB = sbase + ST_B;
#pragma unroll
    for (int kg = 0; kg < 2; kg++) {
        uint32_t ra[4][4], rb[4][2];
#pragma unroll
        for (int tm = 0; tm < 4; tm++) {
            int row = wr * 64 + tm * 16 + (lane & 15);
            int ch = 2 * kg + (lane >> 4);
            ldm_x4(ra[tm], sAB + sw_off(row, ch));
        }
#pragma unroll
        for (int tn = 0; tn < 4; tn++) {
            int row = wc * 32 + tn * 8 + (lane & 7);
            int ch = 2 * kg + ((lane >> 3) & 1);
            ldm_x2(rb[tn], sBB + sw_off(row, ch));
        }
#pragma unroll
        for (int tm = 0; tm < 4; tm++)
#pragma unroll
            for (int tn = 0; tn < 4; tn++)
                mma16816(acc[tm][tn], ra[tm], rb[tn]);
    }
}

// 3-stage mainloop (pure GEMM kernels)
#define PIPE_MAIN3(K, LOADER) do { \
    LOADER(sbase0, 0); \
    if ((K) > 32) LOADER(sbase0 + ST_STRIDE, 32); else cpa_commit(); \
    for (int k0 = 0, st = 0; k0 < (K); k0 += 32, st = (st == 2) ? 0 : st + 1) { \
        cpa_wait<1>(); \
        __syncthreads(); \
        if (k0 + 64 < (K)) { \
            int st2 = st + 2; if (st2 >= 3) st2 -= 3; \
            LOADER(sbase0 + st2 * ST_STRIDE, k0 + 64); \
        } else cpa_commit(); \
        tile_compute(acc, sbase0 + st * ST_STRIDE, lane, wr, wc); \
    } \
} while (0)

// 2-stage mainloop (gather kernels)
#define PIPE_MAIN2(K, LOADER) do { \
    LOADER(sbase0, 0); \
    int cur = 0; \
    for (int k0 = 0; k0 < (K); k0 += 32) { \
        cpa_wait<0>(); \
        __syncthreads(); \
        if (k0 + 32 < (K)) LOADER(sbase0 + (cur ^ 1) * ST_STRIDE, k0 + 32); \
        tile_compute(acc, sbase0 + cur * ST_STRIDE, lane, wr, wc); \
        cur ^= 1; \
    } \
} while (0)

// ------------------------- fp16 GEMM, 3-stage pipeline -------------------------
// EPI: 0 = bias -> fp16 Chi; 2 = bias+relu -> fp16 hi/lo (Chi/Clo)
template<int EPI>
__global__ __launch_bounds__(256) void gemm_tc2(
    const h16* __restrict__ A, const h16* __restrict__ Bw,
    const float* __restrict__ bias,
    h16* __restrict__ Chi, h16* __restrict__ Clo,
    int M, int K, int Nc)
{
    extern __shared__ __align__(16) char smem[];
    uint32_t sbase0 = (uint32_t)__cvta_generic_to_shared(smem);

    int tid = threadIdx.x, lane = tid & 31, w = tid >> 5;
    int wr = w >> 2, wc = w & 3;
    int bm = blockIdx.y * 128, bn = blockIdx.x * 128;

    int r = tid >> 1, ch0 = (tid & 1) * 2;
    int gr = bm + r; if (gr >= M) gr = M - 1;
    size_t aRow = (size_t)gr * K;
    size_t bRow = (size_t)(bn + r) * K;

    float acc[4][4][4];
#pragma unroll
    for (int i = 0; i < 4; i++)
#pragma unroll
        for (int j = 0; j < 4; j++)
#pragma unroll
            for (int q = 0; q < 4; q++) acc[i][j][q] = 0.f;

    auto load_stage = [&](uint32_t sb, int k0) {
#pragma unroll
        for (int i = 0; i < 2; i++) {
            int ch = ch0 + i;
            uint32_t so = sw_off(r, ch);
            size_t go = (size_t)k0 + ch * 8;
            cpa16(sb + so,        A + aRow + go);
            cpa16(sb + ST_B + so, Bw + bRow + go);
        }
        cpa_commit();
    };

    PIPE_MAIN3(K, load_stage);

    int g = lane >> 2, tig = lane & 3;
#pragma unroll
    for (int tm = 0; tm < 4; tm++) {
        int r0 = bm + wr * 64 + tm * 16 + g;
#pragma unroll
        for (int tn = 0; tn < 4; tn++) {
            int col = bn + wc * 32 + tn * 8 + 2 * tig;
            float b0 = bias[col], b1 = bias[col + 1];
            float v0 = acc[tm][tn][0] + b0, v1 = acc[tm][tn][1] + b1;
            float v2 = acc[tm][tn][2] + b0, v3 = acc[tm][tn][3] + b1;
            if (EPI >= 1) {
                v0 = fmaxf(v0, 0.f); v1 = fmaxf(v1, 0.f);
                v2 = fmaxf(v2, 0.f); v3 = fmaxf(v3, 0.f);
            }
            if (r0 < M) {
                size_t o = (size_t)r0 * Nc + col;
                if (EPI == 0) *(uint32_t*)&Chi[o] = pack_h2(v0, v1);
                else {
                    h16 h0 = __float2half_rn(v0), h1 = __float2half_rn(v1);
                    __half2 hp = __halves2half2(h0, h1);
                    *(uint32_t*)&Chi[o] = *(uint32_t*)&hp;
                    *(uint32_t*)&Clo[o] = pack_h2(v0 - __half2float(h0), v1 - __half2float(h1));
                }
            }
            if (r0 + 8 < M) {
                size_t o = (size_t)(r0 + 8) * Nc + col;
                if (EPI == 0) *(uint32_t*)&Chi[o] = pack_h2(v2, v3);
                else {
                    h16 h2 = __float2half_rn(v2), h3 = __float2half_rn(v3);
                    __half2 hp = __halves2half2(h2, h3);
                    *(uint32_t*)&Chi[o] = *(uint32_t*)&hp;
                    *(uint32_t*)&Clo[o] = pack_h2(v2 - __half2float(h2), v3 - __half2float(h3));
                }
            }
        }
    }
}

// ------------------------- Ce GEMM with fused edge epilogue (2-stage, runtime K) -------------------------
template<int WRITE_EH>
__global__ __launch_bounds__(256) void gemm_ce_fused(
    const h16* __restrict__ A, const h16* __restrict__ Bw,
    const float* __restrict__ bias, h16* __restrict__ EHout, int K)
{
    const int M = Ee, Nc = 256;
    const unsigned FULL = 0xFFFFFFFFu;
    extern __shared__ __align__(16) char smem[];
    uint32_t sbase0 = (uint32_t)__cvta_generic_to_shared(smem);

    int tid = threadIdx.x, lane = tid & 31, w = tid >> 5;
    int wr = w >> 2, wc = w & 3;
    int bm = blockIdx.y * 128, bn = blockIdx.x * 128;

    int r = tid >> 1, ch0 = (tid & 1) * 2;
    int gr = bm + r; if (gr >= M) gr = M - 1;
    size_t aRow = (size_t)gr * K;
    size_t bRow = (size_t)(bn + r) * K;

    float acc[4][4][4];
#pragma unroll
    for (int i = 0; i < 4; i++)
#pragma unroll
        for (int j = 0; j < 4; j++)
#pragma unroll
            for (int q = 0; q < 4; q++) acc[i][j][q] = 0.f;

    auto load_stage = [&](uint32_t sb, int k0) {
#pragma unroll
        for (int i = 0; i < 2; i++) {
            int ch = ch0 + i;
            uint32_t so = sw_off(r, ch);
            size_t go = (size_t)k0 + ch * 8;
            cpa16(sb + so,        A + aRow + go);
            cpa16(sb + ST_B + so, Bw + bRow + go);
        }
        cpa_commit();
    };

    PIPE_MAIN2(K, load_stage);

    int g = lane >> 2, tig = lane & 3;
    float ls[4][2], lq[4][2];
    if (WRITE_EH) {
#pragma unroll
        for (int tn = 0; tn < 4; tn++) { ls[tn][0] = ls[tn][1] = lq[tn][0] = lq[tn][1] = 0.f; }
    }

#pragma unroll
    for (int tm = 0; tm < 4; tm++) {
#pragma unroll
        for (int half = 0; half < 2; half++) {
            int e = bm + wr * 64 + tm * 16 + g + 8 * half;
            bool ok = e < M;
            int ec = ok ? e : (M - 1);
            int sN = g_src[ec], dN = g_dst[ec];
            int dkey = ok ? dN : (-1 - g);
            const h16* Drow = g_ABDE + (size_t)dN * 1024 + 512;
            const h16* Erow = g_ABDE + (size_t)sN * 1024 + 768;
            const h16* Brow = g_ABDE + (size_t)sN * 1024 + 256;
            float* nrow = g_num + (size_t)dN * Hh;
            float* drow = g_den + (size_t)dN * Hh;

            int od1 = __shfl_down_sync(FULL, dkey, 4);
            int od2 = __shfl_down_sync(FULL, dkey, 8);
            int od4 = __shfl_down_sync(FULL, dkey, 16);
            int dup = __shfl_up_sync(FULL, dkey, 4);
            bool t1 = (g + 1 < 8) && (od1 == dkey);
            bool t2 = (g + 2 < 8) && (od2 == dkey);
            bool t4 = (g + 4 < 8) && (od4 == dkey);
            bool leader = ok && (g == 0 || dup != dkey);

#pragma unroll
            for (int tn = 0; tn < 4; tn++) {
                int col = bn + wc * 32 + tn * 8 + 2 * tig;
                float2 dv = ldh2(&Drow[col]);
                float2 ev = ldh2(&Erow[col]);
                float2 bv = ldh2(&Brow[col]);
                float eh0 = acc[tm][tn][2 * half + 0] + bias[col]     + dv.x + ev.x;
                float eh1 = acc[tm][tn][2 * half + 1] + bias[col + 1] + dv.y + ev.y;
                float sg0 = 1.f / (1.f + __expf(-eh0));
                float sg1 = 1.f / (1.f + __expf(-eh1));
                float n0 = ok ? sg0 * bv.x : 0.f;
                float n1 = ok ? sg1 * bv.y : 0.f;
                float s0 = ok ? sg0 : 0.f;
                float s1 = ok ? sg1 : 0.f;

                if (WRITE_EH && ok) {
                    *(uint32_t*)&EHout[(size_t)e * Nc + col] = pack_h2(eh0, eh1);
                    ls[tn][0] += eh0; ls[tn][1] += eh1;
                    lq[tn][0] += eh0 * eh0; lq[tn][1] += eh1 * eh1;
                }

                {
                    unsigned long long on = __shfl_down_sync(FULL, pk2(n0, n1), 4);
                    unsigned long long os = __shfl_down_sync(FULL, pk2(s0, s1), 4);
                    if (t1) { float a, b; upk2(on, a, b); n0 += a; n1 += b; upk2(os, a, b); s0 += a; s1 += b; }
                }
                {
                    unsigned long long on = __shfl_down_sync(FULL, pk2(n0, n1), 8);
                    unsigned long long os = __shfl_down_sync(FULL, pk2(s0, s1), 8);
                    if (t2) { float a, b; upk2(on, a, b); n0 += a; n1 += b; upk2(os, a, b); s0 += a; s1 += b; }
                }
                {
                    unsigned long long on = __shfl_down_sync(FULL, pk2(n0, n1), 16);
                    unsigned long long os = __shfl_down_sync(FULL, pk2(s0, s1), 16);
                    if (t4) { float a, b; upk2(on, a, b); n0 += a; n1 += b; upk2(os, a, b); s0 += a; s1 += b; }
                }
                if (leader) {
                    atomicAdd(&nrow[col],     n0);
                    atomicAdd(&nrow[col + 1], n1);
                    atomicAdd(&drow[col],     s0);
                    atomicAdd(&drow[col + 1], s1);
                }
            }
        }
    }

    if (WRITE_EH) {
#pragma unroll
        for (int tn = 0; tn < 4; tn++) {
#pragma unroll
            for (int j = 0; j < 2; j++) {
                float v = ls[tn][j], q = lq[tn][j];
#pragma unroll
                for (int off = 4; off <= 16; off <<= 1) {
                    v += __shfl_xor_sync(0xFFFFFFFFu, v, off);
                    q += __shfl_xor_sync(0xFFFFFFFFu, q, off);
                }
                if (g == 0) {
                    int col = bn + wc * 32 + tn * 8 + 2 * tig + j;
                    atomicAdd(&g_stats[2 * Hh + col], v);
                    atomicAdd(&g_stats[3 * Hh + col], q);
                }
            }
        }
    }
}

// ------------------------- decoder gather-GEMM with fused dec2 (2-stage) -------------------------
__global__ __launch_bounds__(256) void gemm_dec_fused(
    const float* __restrict__ bias, const float* __restrict__ w2,
    float* __restrict__ out)
{
    const int K = K_DEC, M = Ee;
    extern __shared__ __align__(16) char smem[];
    uint32_t sbase0 = (uint32_t)__cvta_generic_to_shared(smem);

    int tid = threadIdx.x, lane = tid & 31, w = tid >> 5;
    int wr = w >> 2, wc = w & 3;
    int bm = blockIdx.y * 128, bn = blockIdx.x * 128;

    int r = tid >> 1, ch0 = (tid & 1) * 2;
    int e = bm + r; if (e >= M) e = M - 1;
    int sN = g_src[e], dN = g_dst[e];
    size_t bRow = (size_t)(bn + r) * K;

    float acc[4][4][4];
#pragma unroll
    for (int i = 0; i < 4; i++)
#pragma unroll
        for (int j = 0; j < 4; j++)
#pragma unroll
            for (int q = 0; q < 4; q++) acc[i][j][q] = 0.f;

    auto load_stage = [&](uint32_t sb, int k0) {
#pragma unroll
        for (int i = 0; i < 2; i++) {
            int ch = ch0 + i;
            uint32_t so = sw_off(r, ch);
            int c0 = k0 + ch * 8;
            const h16* ph;
            if (c0 < 256)      ph = g_xh + (size_t)sN * Hh + c0;
            else if (c0 < 512) ph = g_xh + (size_t)dN * Hh + (c0 - 256);
            else               ph = g_afh + (size_t)e * 32 + (c0 - 512);
            cpa16(sb + so,        ph);
            cpa16(sb + ST_B + so, g_d1_w + bRow + c0);
        }
        cpa_commit();
    };

    PIPE_MAIN2(K, load_stage);

    int g = lane >> 2, tig = lane & 3;
#pragma unroll
    for (int tm = 0; tm < 4; tm++) {
        int r0 = bm + wr * 64 + tm * 16 + g;
        float p0 = 0.f, p1 = 0.f;
#pragma unroll
        for (int tn = 0; tn < 4; tn++) {
            int col = bn + wc * 32 + tn * 8 + 2 * tig;
            float b0 = bias[col], b1 = bias[col + 1];
            float w0 = w2[col], w1 = w2[col + 1];
            p0 += fmaxf(acc[tm][tn][0] + b0, 0.f) * w0 + fmaxf(acc[tm][tn][1] + b1, 0.f) * w1;
            p1 += fmaxf(acc[tm][tn][2] + b0, 0.f) * w0 + fmaxf(acc[tm][tn][3] + b1, 0.f) * w1;
        }
        p0 += __shfl_xor_sync(0xFFFFFFFFu, p0, 1);
        p0 += __shfl_xor_sync(0xFFFFFFFFu, p0, 2);
        p1 += __shfl_xor_sync(0xFFFFFFFFu, p1, 1);
        p1 += __shfl_xor_sync(0xFFFFFFFFu, p1, 2);
        if (tig == 0) {
            if (r0 < M)     atomicAdd(&out[g_eorig[r0]], p0);
            if (r0 + 8 < M) atomicAdd(&out[g_eorig[r0 + 8]], p1);
        }
    }
}

// ------------------------- edge projection (K=8, sorted order) -------------------------
__global__ void k_eproj(const float* __restrict__ af, const float* __restrict__ W,
                        const float* __restrict__ b) {
    size_t idx = (size_t)blockIdx.x * blockDim.x + threadIdx.x;
    if (idx < (size_t)Ee * Hh) {
        int c = (int)(idx & 255);
        size_t e = idx >> 8;
        size_t eo = (size_t)g_eorig[e];
        float v = b[c];
#pragma unroll
        for (int k = 0; k < 8; k++) v += af[eo * 8 + k] * W[k * Hh + c];
        split_write(v, g_eh, g_el, idx);
    }
}

// ------------------------- per-layer node kernels -------------------------
__global__ __launch_bounds__(256) void k_node() {
    int c = threadIdx.x;
    int base = blockIdx.x * 32;
    float s = 0.f, sq = 0.f;
    for (int i = 0; i < 32; i++) {
        int n = base + i;
        size_t o = (size_t)n * Hh + c;
        float xc = __half2float(g_ABDE[(size_t)n * 1024 + c]) + g_num[o] / (g_den[o] + AGG_EPS);
        g_num[o] = xc;
        s += xc; sq += xc * xc;
    }
    atomicAdd(&g_stats[c], s);
    atomicAdd(&g_stats[Hh + c], sq);
}

__global__ void k_apply_x(const float* __restrict__ gam, const float* __restrict__ bet) {
    size_t idx = (size_t)blockIdx.x * blockDim.x + threadIdx.x;
    if (idx < (size_t)Nn * Hh) {
        int c = (int)(idx & 255);
        float mu = g_stats[c] * (1.f / Nn);
        float var = g_stats[Hh + c] * (1.f / Nn) - mu * mu;
        float v = gam[c] * (g_num[idx] - mu) * rsqrtf(var + BN_EPS) + bet[c];
        float old = __half2float(g_xh[idx]) + __half2float(g_xl[idx]);
        float o = old + fmaxf(v, 0.f);
        split_write(o, g_xh, g_xl, idx);
    }
}

__global__ void k_apply_e(const h16* __restrict__ ehat,
                          const float* __restrict__ gam, const float* __restrict__ bet) {
    size_t idx = (size_t)blockIdx.x * blockDim.x + threadIdx.x;
    if (idx < (size_t)Ee * Hh) {
        int c = (int)(idx & 255);
        float mu = g_stats[2 * Hh + c] * (1.f / Ee);
        float var = g_stats[3 * Hh + c] * (1.f / Ee) - mu * mu;
        float v = gam[c] * (__half2float(ehat[idx]) - mu) * rsqrtf(var + BN_EPS) + bet[c];
        float old = __half2float(g_eh[idx]) + __half2float(g_el[idx]);
        float o = old + fmaxf(v, 0.f);
        split_write(o, g_eh, g_el, idx);
    }
}

// ------------------------- host launcher -------------------------
extern "C" void kernel_launch(void* const* d_in, const int* in_sizes, int n_in,
                              void* d_out, int out_size)
{
    int wb = 3;
    for (int i = 3; i < n_in && i < 6; i++) {
        if (in_sizes[i] == 2 * Hh * Hh) { wb = i; break; }
    }

    const void*  eidx = d_in[0];
    const float* af   = (const float*)d_in[1];
    const float* hold = (const float*)d_in[2];
    const float* fw   = (const float*)d_in[wb + 0];
    const float* fb   = (const float*)d_in[wb + 1];
    const float* epw  = (const float*)d_in[wb + 2];
    const float* epb  = (const float*)d_in[wb + 3];
    const float* Aw   = (const float*)d_in[wb + 4];
    const float* Ab   = (const float*)d_in[wb + 5];
    const float* Bw   = (const float*)d_in[wb + 6];
    const float* Bb   = (const float*)d_in[wb + 7];
    const float* Cw   = (const float*)d_in[wb + 8];
    const float* Cb   = (const float*)d_in[wb + 9];
    const float* Dw   = (const float*)d_in[wb + 10];
    const float* Db   = (const float*)d_in[wb + 11];
    const float* Ew   = (const float*)d_in[wb + 12];
    const float* Eb   = (const float*)d_in[wb + 13];
    const float* bxg  = (const float*)d_in[wb + 14];
    const float* bxb  = (const float*)d_in[wb + 15];
    const float* beg  = (const float*)d_in[wb + 16];
    const float* beb  = (const float*)d_in[wb + 17];
    const float* d1w  = (const float*)d_in[wb + 18];
    const float* d1b  = (const float*)d_in[wb + 19];
    const float* d2w  = (const float*)d_in[wb + 20];
    const float* d2b  = (const float*)d_in[wb + 21];

    float *nump, *denp, *statsp, *bpackp, *fbiasp, *b0pp;
    h16 *abdep, *ehp, *abde_w, *c_w, *fw_w, *w0p_w;
    h16 *xh, *xl, *eh, *el, *hh, *afh;
    int *histp;
    cudaGetSymbolAddress((void**)&abdep, g_ABDE);
    cudaGetSymbolAddress((void**)&ehp, g_EH);
    cudaGetSymbolAddress((void**)&nump, g_num);
    cudaGetSymbolAddress((void**)&denp, g_den);
    cudaGetSymbolAddress((void**)&statsp, g_stats);
    cudaGetSymbolAddress((void**)&bpackp, g_bpack);
    cudaGetSymbolAddress((void**)&fbiasp, g_fbias);
    cudaGetSymbolAddress((void**)&b0pp, g_b0p);
    cudaGetSymbolAddress((void**)&abde_w, g_abde_w);
    cudaGetSymbolAddress((void**)&c_w, g_c_w);
    cudaGetSymbolAddress((void**)&fw_w, g_fw_w);
    cudaGetSymbolAddress((void**)&w0p_w, g_w0p_w);
    cudaGetSymbolAddress((void**)&xh, g_xh);
    cudaGetSymbolAddress((void**)&xl, g_xl);
    cudaGetSymbolAddress((void**)&eh, g_eh);
    cudaGetSymbolAddress((void**)&el, g_el);
    cudaGetSymbolAddress((void**)&hh, g_hh);
    cudaGetSymbolAddress((void**)&afh, g_afh);
    cudaGetSymbolAddress((void**)&histp, g_hist);

    cudaFuncSetAttribute(gemm_tc2<0>, cudaFuncAttributeMaxDynamicSharedMemorySize, SMEM3);
    cudaFuncSetAttribute(gemm_tc2<2>, cudaFuncAttributeMaxDynamicSharedMemorySize, SMEM3);
    cudaFuncSetAttribute(gemm_ce_fused<0>, cudaFuncAttributeMaxDynamicSharedMemorySize, SMEM2);
    cudaFuncSetAttribute(gemm_ce_fused<1>, cudaFuncAttributeMaxDynamicSharedMemorySize, SMEM2);
    cudaFuncSetAttribute(gemm_dec_fused, cudaFuncAttributeMaxDynamicSharedMemorySize, SMEM2);

    // --- prep: sort edges by dst, convert weights/activations ---
    cudaMemsetAsync(histp, 0, Nn * sizeof(int));
    k_detect_idx<<<1, 256>>>((const unsigned int*)eidx);
    k_convert_idx<<<(Ee + 255) / 256, 256>>>(eidx);
    k_scan<<<1, 1024>>>();
    k_scatter<<<(Ee + 255) / 256, 256>>>();
    {
        int mg = MB0 + MB1 + MB2 + MB3 + MB4 + MB5 + MB6;
        k_megaprep<<<mg, 256>>>(Ab, Bb, Db, Eb, fw, fb, Cw, d1w, hold, af);
    }
    {
        size_t tw = (size_t)Ll * 1024 * 256;
        k_split_abde<<<(int)((tw + 255) / 256), 256>>>(Aw, Bw, Dw, Ew);
    }
    k_w0prime<<<32, 256>>>(epw, epb, Cw, Cb);
    {
        dim3 grid(Hh / 128, (Nn + 127) / 128);
        gemm_tc2<2><<<grid, 256, SMEM3>>>(hh, fw_w, fbiasp, xh, xl, Nn, Hh, Hh);
    }
    k_eproj<<<(int)(((size_t)Ee * Hh + 255) / 256), 256>>>(af, epw, epb);
    k_init_out<<<(Ee + 255) / 256, 256>>>((float*)d_out, d2b);

    for (int l = 0; l < Ll; l++) {
        cudaMemsetAsync(nump, 0, (size_t)Nn * Hh * sizeof(float));
        cudaMemsetAsync(denp, 0, (size_t)Nn * Hh * sizeof(float));
        cudaMemsetAsync(statsp, 0, 4 * Hh * sizeof(float));

        {   // fused A|B|D|E GEMM: [N,256] @ [256,1024] -> fp16 ABDE
            dim3 grid(4 * Hh / 128, (Nn + 127) / 128);
            gemm_tc2<0><<<grid, 256, SMEM3>>>(xh,
                                              abde_w + (size_t)l * 1024 * 256,
                                              bpackp + l * 4 * Hh, abdep, nullptr,
                                              Nn, Hh, 4 * Hh);
        }
        {   // Ce GEMM + fused edge phase; layer 0 uses rank-8 collapsed form (K=32)
            dim3 grid(2, (Ee + 127) / 128);
            if (l == 0)
                gemm_ce_fused<1><<<grid, 256, SMEM2>>>(afh, w0p_w, b0pp, ehp, 32);
            else if (l < Ll - 1)
                gemm_ce_fused<1><<<grid, 256, SMEM2>>>(eh,
                                                       c_w + (size_t)l * Hh * Hh,
                                                       Cb + l * Hh, ehp, 256);
            else
                gemm_ce_fused<0><<<grid, 256, SMEM2>>>(eh,
                                                       c_w + (size_t)l * Hh * Hh,
                                                       Cb + l * Hh, ehp, 256);
        }
        k_node<<<Nn / 32, 256>>>();
        k_apply_x<<<(int)(((size_t)Nn * Hh + 255) / 256), 256>>>(bxg + l * Hh, bxb + l * Hh);
        if (l < Ll - 1)  // e dead after last layer
            k_apply_e<<<(int)(((size_t)Ee * Hh + 255) / 256), 256>>>(ehp, beg + l * Hh, beb + l * Hh);
    }

    // --- decoder (dec1 GEMM with fused dec2 dot-product epilogue) ---
    {
        dim3 grid(2, (Ee + 127) / 128);
        gemm_dec_fused<<<grid, 256, SMEM2>>>(d1b, d2w, (float*)d_out);
    }
}

// round 17
// speedup vs baseline: 1.4276x; 1.0190x over previous
#include <cuda_runtime.h>
#include <cuda_fp16.h>
#include <math.h>
#include <stdint.h>

// Problem constants
#define Hh 256
#define Ll 4
#define Nn 100000
#define Ee 300000
#define BN_EPS 1e-5f
#define AGG_EPS 1e-6f
#define K_DEC 576   // 520 padded to multiple of 64

typedef __half h16;

// ------------------------- static device scratch -------------------------
__device__ h16   g_ABDE[(size_t)Nn * 4 * Hh];   // fp16 [N,1024]: A|B|D|E
__device__ h16   g_EH[(size_t)Ee * Hh];         // e_hat fp16 (sorted edge order)
__device__ float g_num[(size_t)Nn * Hh];
__device__ float g_den[(size_t)Nn * Hh];
__device__ float g_stats[4 * Hh];
__device__ float g_bpack[Ll * 4 * Hh];
__device__ float g_fbias[Hh];
__device__ float g_b0p[Hh];
__device__ int   g_src[Ee];     // sorted by dst
__device__ int   g_dst[Ee];     // sorted (non-decreasing)
__device__ int   g_eorig[Ee];
__device__ int   g_srcO[Ee];
__device__ int   g_dstO[Ee];
__device__ int   g_hist[Nn];
__device__ int   g_idx64;

// fp16 weights, transposed to [N][K]
__device__ h16 g_abde_w[(size_t)Ll * 1024 * 256];
__device__ h16 g_c_w[(size_t)Ll * 256 * 256];
__device__ h16 g_fw_w[256 * 256];
__device__ h16 g_d1_w[256 * K_DEC];
__device__ h16 g_w0p_w[256 * 64];               // layer-0 collapsed Ce weight [n][64]

// fp16 hi/lo activations (residual = hi+lo; GEMMs read hi only)
__device__ h16 g_xh[(size_t)Nn * Hh];
__device__ h16 g_xl[(size_t)Nn * Hh];
__device__ h16 g_eh[(size_t)Ee * Hh];
__device__ h16 g_el[(size_t)Ee * Hh];
__device__ h16 g_hh[(size_t)Nn * Hh];
__device__ h16 g_afh[(size_t)Ee * 64];

// ------------------------- prep kernels -------------------------
__global__ void k_detect_idx(const unsigned int* __restrict__ w) {
    unsigned int s = 0;
    for (int i = threadIdx.x; i < 1024; i += 256) s |= w[2 * i + 1];
#pragma unroll
    for (int off = 16; off; off >>= 1) s |= __shfl_xor_sync(0xFFFFFFFFu, s, off);
    __shared__ unsigned int red[8];
    if ((threadIdx.x & 31) == 0) red[threadIdx.x >> 5] = s;
    __syncthreads();
    if (threadIdx.x == 0) {
        unsigned int t = 0;
        for (int i = 0; i < 8; i++) t |= red[i];
        g_idx64 = (t == 0u) ? 1 : 0;
    }
}

__global__ void k_convert_idx(const void* __restrict__ eidx) {
    int i = blockIdx.x * blockDim.x + threadIdx.x;
    if (i < Ee) {
        int s, d;
        if (g_idx64) {
            const long long* p = (const long long*)eidx;
            s = (int)p[i];
            d = (int)p[(size_t)Ee + i];
        } else {
            const int* p = (const int*)eidx;
            s = p[i];
            d = p[Ee + i];
        }
        g_srcO[i] = s;
        g_dstO[i] = d;
        atomicAdd(&g_hist[d], 1);
    }
}

__global__ __launch_bounds__(1024) void k_scan() {
    __shared__ int part[1024];
    int t = threadIdx.x;
    const int CH = (Nn + 1023) / 1024;
    int base = t * CH;
    int s = 0;
    for (int j = 0; j < CH; j++) {
        int b = base + j;
        if (b < Nn) s += g_hist[b];
    }
    part[t] = s;
    __syncthreads();
    if (t == 0) {
        int acc = 0;
        for (int i = 0; i < 1024; i++) { int v = part[i]; part[i] = acc; acc += v; }
    }
    __syncthreads();
    int acc = part[t];
    for (int j = 0; j < CH; j++) {
        int b = base + j;
        if (b < Nn) { int v = g_hist[b]; g_hist[b] = acc; acc += v; }
    }
}

__global__ void k_scatter() {
    int i = blockIdx.x * blockDim.x + threadIdx.x;
    if (i < Ee) {
        int d = g_dstO[i];
        int pos = atomicAdd(&g_hist[d], 1);
        g_src[pos] = g_srcO[i];
        g_dst[pos] = d;
        g_eorig[pos] = i;
    }
}

__device__ __forceinline__ void split_write(float v, h16* hi, h16* lo, size_t i) {
    h16 h = __float2half_rn(v);
    hi[i] = h;
    lo[i] = __float2half_rn(v - __half2float(h));
}

__global__ void k_split_abde(const float* __restrict__ Aw, const float* __restrict__ Bw,
                             const float* __restrict__ Dw, const float* __restrict__ Ew) {
    size_t i = (size_t)blockIdx.x * 256 + threadIdx.x;
    if (i < (size_t)Ll * 1024 * 256) {
        int k = (int)(i & 255);
        int n = (int)((i >> 8) & 1023);
        int l = (int)(i >> 18);
        const float* W = (n < 256) ? Aw : (n < 512) ? Bw : (n < 768) ? Dw : Ew;
        g_abde_w[i] = __float2half_rn(W[(size_t)l * 65536 + (size_t)k * 256 + (n & 255)]);
    }
}

// layer-0 collapsed Ce: W0'[k8][n] = epw@C0 (zero pad to K=64); b0' = epb@C0 + C0b
__global__ void k_w0prime(const float* __restrict__ epw, const float* __restrict__ epb,
                          const float* __restrict__ C0, const float* __restrict__ C0b) {
    int i = blockIdx.x * 256 + threadIdx.x;   // 64 blocks: 256n * 64k
    int n = i >> 6, k = i & 63;
    float v = 0.f;
    if (k < 8) {
        for (int m = 0; m < 256; m++) v += epw[k * 256 + m] * C0[(size_t)m * 256 + n];
    }
    g_w0p_w[(size_t)n * 64 + k] = __float2half_rn(v);
    if (k == 0) {
        float b = C0b[n];
        for (int m = 0; m < 256; m++) b += epb[m] * C0[(size_t)m * 256 + n];
        g_b0p[n] = b;
    }
}

__global__ void k_split_af(const float* __restrict__ af) {
    size_t i = (size_t)blockIdx.x * 256 + threadIdx.x;
    if (i < (size_t)Ee * 64) {
        int c = (int)(i & 63);
        size_t e = i >> 6;
        float v = (c < 8) ? af[(size_t)g_eorig[e] * 8 + c] : 0.0f;
        g_afh[i] = __float2half_rn(v);
    }
}

// prep without af (runs before scatter; fusion GEMM can follow immediately)
#define MB0 16
#define MB1 1
#define MB2 256
#define MB3 1024
#define MB4 576
#define MB5 100000
__global__ void k_megaprep(
    const float* __restrict__ Ab, const float* __restrict__ Bb,
    const float* __restrict__ Db, const float* __restrict__ Eb,
    const float* __restrict__ fw, const float* __restrict__ fb,
    const float* __restrict__ Cw, const float* __restrict__ d1w,
    const float* __restrict__ hold)
{
    int b = blockIdx.x, t = threadIdx.x;
    if (b < MB0) {
        int i = b * 256 + t;
        if (i < Ll * 4 * Hh) {
            int j4 = i % (4 * Hh);
            int l = i / (4 * Hh);
            int which = j4 >> 8, j = j4 & 255;
            const float* B = (which == 0) ? Ab : (which == 1) ? Bb : (which == 2) ? Db : Eb;
            g_bpack[i] = B[l * Hh + j];
        }
        return;
    }
    b -= MB0;
    if (b < MB1) {
        float s = fb[t];
        for (int k = 0; k < Hh; k++) s += fw[(size_t)k * Hh + t];
        g_fbias[t] = s;
        return;
    }
    b -= MB1;
    if (b < MB2) {
        int i = b * 256 + t;
        int k = i & 255, n = i >> 8;
        g_fw_w[i] = __float2half_rn(fw[(size_t)(Hh + k) * Hh + n]);
        return;
    }
    b -= MB2;
    if (b < MB3) {
        size_t i = (size_t)b * 256 + t;
        int k = (int)(i & 255), n = (int)((i >> 8) & 255), l = (int)(i >> 16);
        g_c_w[i] = __float2half_rn(Cw[(size_t)l * 65536 + (size_t)k * 256 + n]);
        return;
    }
    b -= MB3;
    if (b < MB4) {
        int i = b * 256 + t;
        if (i < 256 * K_DEC) {
            int k = i % K_DEC, n = i / K_DEC;
            float v = (k < 520) ? d1w[(size_t)k * 256 + n] : 0.0f;
            g_d1_w[i] = __float2half_rn(v);
        }
        return;
    }
    b -= MB4;
    {
        size_t i = (size_t)b * 256 + t;
        if (i < (size_t)Nn * Hh) g_hh[i] = __float2half_rn(hold[i]);
    }
}

__global__ void k_init_out(float* __restrict__ out, const float* __restrict__ b2) {
    int i = blockIdx.x * blockDim.x + threadIdx.x;
    if (i < Ee) out[i] = b2[0];
}

// ------------------------- tensor-core machinery -------------------------
__device__ __forceinline__ void mma16816(float* c, const uint32_t* a, const uint32_t* b) {
    asm volatile(
        "mma.sync.aligned.m16n8k16.row.col.f32.f16.f16.f32 "
        "{%0,%1,%2,%3}, {%4,%5,%6,%7}, {%8,%9}, {%0,%1,%2,%3};"
        : "+f"(c[0]), "+f"(c[1]), "+f"(c[2]), "+f"(c[3])
        : "r"(a[0]), "r"(a[1]), "r"(a[2]), "r"(a[3]), "r"(b[0]), "r"(b[1]));
}
__device__ __forceinline__ void ldm_x4(uint32_t* r, uint32_t addr) {
    asm volatile("ldmatrix.sync.aligned.m8n8.x4.shared.b16 {%0,%1,%2,%3}, [%4];"
                 : "=r"(r[0]), "=r"(r[1]), "=r"(r[2]), "=r"(r[3]) : "r"(addr));
}
__device__ __forceinline__ void ldm_x2(uint32_t* r, uint32_t addr) {
    asm volatile("ldmatrix.sync.aligned.m8n8.x2.shared.b16 {%0,%1}, [%2];"
                 : "=r"(r[0]), "=r"(r[1]) : "r"(addr));
}
__device__ __forceinline__ void cpa16(uint32_t s, const void* g) {
    asm volatile("cp.async.cg.shared.global [%0], [%1], 16;" :: "r"(s), "l"(g));
}
__device__ __forceinline__ void cpa_commit() { asm volatile("cp.async.commit_group;"); }
template<int N>
__device__ __forceinline__ void cpa_wait() { asm volatile("cp.async.wait_group %0;" :: "n"(N) : "memory"); }

// SW128 swizzle for 128-byte rows (64 h16/row, 8 16B-chunks)
__device__ __forceinline__ int sw_off(int row, int chunk) {
    return row * 128 + ((chunk ^ (row & 7)) << 4);
}

__device__ __forceinline__ unsigned long long pk2(float a, float b) {
    return (unsigned long long)__float_as_uint(a) | ((unsigned long long)__float_as_uint(b) << 32);
}
__device__ __forceinline__ void upk2(unsigned long long v, float& a, float& b) {
    a = __uint_as_float((unsigned int)v);
    b = __uint_as_float((unsigned int)(v >> 32));
}
__device__ __forceinline__ uint32_t pack_h2(float a, float b) {
    __half2 t = __floats2half2_rn(a, b);
    return *(uint32_t*)&t;
}
__device__ __forceinline__ float2 ldh2(const h16* p) {
    __half2 v = *(const __half2*)p;
    return __half22float2(v);
}

// stage: A @0 (16 KB), B @16384 (16 KB); stride 32 KB; BK=64
#define ST_B   16384
#define ST_STRIDE 32768
#define SMEM3 (3 * ST_STRIDE)   // 96 KB (pure GEMM)
#define SMEM2 (2 * ST_STRIDE)   // 64 KB (gather kernels)

// fp16x1, BK=64: 4 k-groups of 8 MMAs
__device__ __forceinline__ void tile_compute(
    float acc[4][4][4], uint32_t sbase, int lane, int wr, int wc) {
    uint32_t sAB = sbase, sBB = sbase + ST_B;
#pragma unroll
    for (int kg = 0; kg < 4; kg++) {
        uint32_t ra[4][4], rb[4][2];
#pragma unroll
        for (int tm = 0; tm < 4; tm++) {
            int row = wr * 64 + tm * 16 + (lane & 15);
            int ch = 2 * kg + (lane >> 4);
            ldm_x4(ra[tm], sAB + sw_off(row, ch));
        }
#pragma unroll
        for (int tn = 0; tn < 4; tn++) {
            int row = wc * 32 + tn * 8 + (lane & 7);
            int ch = 2 * kg + ((lane >> 3) & 1);
            ldm_x2(rb[tn], sBB + sw_off(row, ch));
        }
#pragma unroll
        for (int tm = 0; tm < 4; tm++)
#pragma unroll
            for (int tn = 0; tn < 4; tn++)
                mma16816(acc[tm][tn], ra[tm], rb[tn]);
    }
}

// 3-stage mainloop, BK=64
#define PIPE_MAIN3(K, LOADER) do { \
    LOADER(sbase0, 0); \
    if ((K) > 64) LOADER(sbase0 + ST_STRIDE, 64); else cpa_commit(); \
    for (int k0 = 0, st = 0; k0 < (K); k0 += 64, st = (st == 2) ? 0 : st + 1) { \
        cpa_wait<1>(); \
        __syncthreads(); \
        if (k0 + 128 < (K)) { \
            int st2 = st + 2; if (st2 >= 3) st2 -= 3; \
            LOADER(sbase0 + st2 * ST_STRIDE, k0 + 128); \
        } else cpa_commit(); \
        tile_compute(acc, sbase0 + st * ST_STRIDE, lane, wr, wc); \
    } \
} while (0)

// 2-stage mainloop, BK=64
#define PIPE_MAIN2(K, LOADER) do { \
    LOADER(sbase0, 0); \
    int cur = 0; \
    for (int k0 = 0; k0 < (K); k0 += 64) { \
        cpa_wait<0>(); \
        __syncthreads(); \
        if (k0 + 64 < (K)) LOADER(sbase0 + (cur ^ 1) * ST_STRIDE, k0 + 64); \
        tile_compute(acc, sbase0 + cur * ST_STRIDE, lane, wr, wc); \
        cur ^= 1; \
    } \
} while (0)

// ------------------------- fp16 GEMM, 3-stage pipeline -------------------------
// EPI: 0 = bias -> fp16 Chi; 2 = bias+relu -> fp16 hi/lo (Chi/Clo)
template<int EPI>
__global__ __launch_bounds__(256) void gemm_tc2(
    const h16* __restrict__ A, const h16* __restrict__ Bw,
    const float* __restrict__ bias,
    h16* __restrict__ Chi, h16* __restrict__ Clo,
    int M, int K, int Nc)
{
    extern __shared__ __align__(16) char smem[];
    uint32_t sbase0 = (uint32_t)__cvta_generic_to_shared(smem);

    int tid = threadIdx.x, lane = tid & 31, w = tid >> 5;
    int wr = w >> 2, wc = w & 3;
    int bm = blockIdx.y * 128, bn = blockIdx.x * 128;

    int r = tid >> 1, ch0 = (tid & 1) * 4;
    int gr = bm + r; if (gr >= M) gr = M - 1;
    size_t aRow = (size_t)gr * K;
    size_t bRow = (size_t)(bn + r) * K;

    float acc[4][4][4];
#pragma unroll
    for (int i = 0; i < 4; i++)
#pragma unroll
        for (int j = 0; j < 4; j++)
#pragma unroll
            for (int q = 0; q < 4; q++) acc[i][j][q] = 0.f;

    auto load_stage = [&](uint32_t sb, int k0) {
#pragma unroll
        for (int i = 0; i < 4; i++) {
            int ch = ch0 + i;
            uint32_t so = sw_off(r, ch);
            size_t go = (size_t)k0 + ch * 8;
            cpa16(sb + so,        A + aRow + go);
            cpa16(sb + ST_B + so, Bw + bRow + go);
        }
        cpa_commit();
    };

    PIPE_MAIN3(K, load_stage);

    int g = lane >> 2, tig = lane & 3;
#pragma unroll
    for (int tm = 0; tm < 4; tm++) {
        int r0 = bm + wr * 64 + tm * 16 + g;
#pragma unroll
        for (int tn = 0; tn < 4; tn++) {
            int col = bn + wc * 32 + tn * 8 + 2 * tig;
            float b0 = bias[col], b1 = bias[col + 1];
            float v0 = acc[tm][tn][0] + b0, v1 = acc[tm][tn][1] + b1;
            float v2 = acc[tm][tn][2] + b0, v3 = acc[tm][tn][3] + b1;
            if (EPI >= 1) {
                v0 = fmaxf(v0, 0.f); v1 = fmaxf(v1, 0.f);
                v2 = fmaxf(v2, 0.f); v3 = fmaxf(v3, 0.f);
            }
            if (r0 < M) {
                size_t o = (size_t)r0 * Nc + col;
                if (EPI == 0) *(uint32_t*)&Chi[o] = pack_h2(v0, v1);
                else {
                    h16 h0 = __float2half_rn(v0), h1 = __float2half_rn(v1);
                    __half2 hp = __halves2half2(h0, h1);
                    *(uint32_t*)&Chi[o] = *(uint32_t*)&hp;
                    *(uint32_t*)&Clo[o] = pack_h2(v0 - __half2float(h0), v1 - __half2float(h1));
                }
            }
            if (r0 + 8 < M) {
                size_t o = (size_t)(r0 + 8) * Nc + col;
                if (EPI == 0) *(uint32_t*)&Chi[o] = pack_h2(v2, v3);
                else {
                    h16 h2 = __float2half_rn(v2), h3 = __float2half_rn(v3);
                    __half2 hp = __halves2half2(h2, h3);
                    *(uint32_t*)&Chi[o] = *(uint32_t*)&hp;
                    *(uint32_t*)&Clo[o] = pack_h2(v2 - __half2float(h2), v3 - __half2float(h3));
                }
            }
        }
    }
}

// ------------------------- Ce GEMM with fused edge epilogue (2-stage, runtime K) -------------------------
template<int WRITE_EH>
__global__ __launch_bounds__(256) void gemm_ce_fused(
    const h16* __restrict__ A, const h16* __restrict__ Bw,
    const float* __restrict__ bias, h16* __restrict__ EHout, int K)
{
    const int M = Ee, Nc = 256;
    const unsigned FULL = 0xFFFFFFFFu;
    extern __shared__ __align__(16) char smem[];
    uint32_t sbase0 = (uint32_t)__cvta_generic_to_shared(smem);

    int tid = threadIdx.x, lane = tid & 31, w = tid >> 5;
    int wr = w >> 2, wc = w & 3;
    int bm = blockIdx.y * 128, bn = blockIdx.x * 128;

    int r = tid >> 1, ch0 = (tid & 1) * 4;
    int gr = bm + r; if (gr >= M) gr = M - 1;
    size_t aRow = (size_t)gr * K;
    size_t bRow = (size_t)(bn + r) * K;

    float acc[4][4][4];
#pragma unroll
    for (int i = 0; i < 4; i++)
#pragma unroll
        for (int j = 0; j < 4; j++)
#pragma unroll
            for (int q = 0; q < 4; q++) acc[i][j][q] = 0.f;

    auto load_stage = [&](uint32_t sb, int k0) {
#pragma unroll
        for (int i = 0; i < 4; i++) {
            int ch = ch0 + i;
            uint32_t so = sw_off(r, ch);
            size_t go = (size_t)k0 + ch * 8;
            cpa16(sb + so,        A + aRow + go);
            cpa16(sb + ST_B + so, Bw + bRow + go);
        }
        cpa_commit();
    };

    PIPE_MAIN2(K, load_stage);

    int g = lane >> 2, tig = lane & 3;
    float ls[4][2], lq[4][2];
    if (WRITE_EH) {
#pragma unroll
        for (int tn = 0; tn < 4; tn++) { ls[tn][0] = ls[tn][1] = lq[tn][0] = lq[tn][1] = 0.f; }
    }

#pragma unroll
    for (int tm = 0; tm < 4; tm++) {
#pragma unroll
        for (int half = 0; half < 2; half++) {
            int e = bm + wr * 64 + tm * 16 + g + 8 * half;
            bool ok = e < M;
            int ec = ok ? e : (M - 1);
            int sN = g_src[ec], dN = g_dst[ec];
            int dkey = ok ? dN : (-1 - g);
            const h16* Drow = g_ABDE + (size_t)dN * 1024 + 512;
            const h16* Erow = g_ABDE + (size_t)sN * 1024 + 768;
            const h16* Brow = g_ABDE + (size_t)sN * 1024 + 256;
            float* nrow = g_num + (size_t)dN * Hh;
            float* drow = g_den + (size_t)dN * Hh;

            int od1 = __shfl_down_sync(FULL, dkey, 4);
            int od2 = __shfl_down_sync(FULL, dkey, 8);
            int od4 = __shfl_down_sync(FULL, dkey, 16);
            int dup = __shfl_up_sync(FULL, dkey, 4);
            bool t1 = (g + 1 < 8) && (od1 == dkey);
            bool t2 = (g + 2 < 8) && (od2 == dkey);
            bool t4 = (g + 4 < 8) && (od4 == dkey);
            bool leader = ok && (g == 0 || dup != dkey);

#pragma unroll
            for (int tn = 0; tn < 4; tn++) {
                int col = bn + wc * 32 + tn * 8 + 2 * tig;
                float2 dv = ldh2(&Drow[col]);
                float2 ev = ldh2(&Erow[col]);
                float2 bv = ldh2(&Brow[col]);
                float eh0 = acc[tm][tn][2 * half + 0] + bias[col]     + dv.x + ev.x;
                float eh1 = acc[tm][tn][2 * half + 1] + bias[col + 1] + dv.y + ev.y;
                float sg0 = 1.f / (1.f + __expf(-eh0));
                float sg1 = 1.f / (1.f + __expf(-eh1));
                float n0 = ok ? sg0 * bv.x : 0.f;
                float n1 = ok ? sg1 * bv.y : 0.f;
                float s0 = ok ? sg0 : 0.f;
                float s1 = ok ? sg1 : 0.f;

                if (WRITE_EH && ok) {
                    *(uint32_t*)&EHout[(size_t)e * Nc + col] = pack_h2(eh0, eh1);
                    ls[tn][0] += eh0; ls[tn][1] += eh1;
                    lq[tn][0] += eh0 * eh0; lq[tn][1] += eh1 * eh1;
                }

                {
                    unsigned long long on = __shfl_down_sync(FULL, pk2(n0, n1), 4);
                    unsigned long long os = __shfl_down_sync(FULL, pk2(s0, s1), 4);
                    if (t1) { float a, b; upk2(on, a, b); n0 += a; n1 += b; upk2(os, a, b); s0 += a; s1 += b; }
                }
                {
                    unsigned long long on = __shfl_down_sync(FULL, pk2(n0, n1), 8);
                    unsigned long long os = __shfl_down_sync(FULL, pk2(s0, s1), 8);
                    if (t2) { float a, b; upk2(on, a, b); n0 += a; n1 += b; upk2(os, a, b); s0 += a; s1 += b; }
                }
                {
                    unsigned long long on = __shfl_down_sync(FULL, pk2(n0, n1), 16);
                    unsigned long long os = __shfl_down_sync(FULL, pk2(s0, s1), 16);
                    if (t4) { float a, b; upk2(on, a, b); n0 += a; n1 += b; upk2(os, a, b); s0 += a; s1 += b; }
                }
                if (leader) {
                    atomicAdd(&nrow[col],     n0);
                    atomicAdd(&nrow[col + 1], n1);
                    atomicAdd(&drow[col],     s0);
                    atomicAdd(&drow[col + 1], s1);
                }
            }
        }
    }

    if (WRITE_EH) {
#pragma unroll
        for (int tn = 0; tn < 4; tn++) {
#pragma unroll
            for (int j = 0; j < 2; j++) {
                float v = ls[tn][j], q = lq[tn][j];
#pragma unroll
                for (int off = 4; off <= 16; off <<= 1) {
                    v += __shfl_xor_sync(0xFFFFFFFFu, v, off);
                    q += __shfl_xor_sync(0xFFFFFFFFu, q, off);
                }
                if (g == 0) {
                    int col = bn + wc * 32 + tn * 8 + 2 * tig + j;
                    atomicAdd(&g_stats[2 * Hh + col], v);
                    atomicAdd(&g_stats[3 * Hh + col], q);
                }
            }
        }
    }
}

// ------------------------- decoder gather-GEMM with fused dec2 (2-stage) -------------------------
__global__ __launch_bounds__(256) void gemm_dec_fused(
    const float* __restrict__ bias, const float* __restrict__ w2,
    float* __restrict__ out)
{
    const int K = K_DEC, M = Ee;
    extern __shared__ __align__(16) char smem[];
    uint32_t sbase0 = (uint32_t)__cvta_generic_to_shared(smem);

    int tid = threadIdx.x, lane = tid & 31, w = tid >> 5;
    int wr = w >> 2, wc = w & 3;
    int bm = blockIdx.y * 128, bn = blockIdx.x * 128;

    int r = tid >> 1, ch0 = (tid & 1) * 4;
    int e = bm + r; if (e >= M) e = M - 1;
    int sN = g_src[e], dN = g_dst[e];
    size_t bRow = (size_t)(bn + r) * K;

    float acc[4][4][4];
#pragma unroll
    for (int i = 0; i < 4; i++)
#pragma unroll
        for (int j = 0; j < 4; j++)
#pragma unroll
            for (int q = 0; q < 4; q++) acc[i][j][q] = 0.f;

    auto load_stage = [&](uint32_t sb, int k0) {
#pragma unroll
        for (int i = 0; i < 4; i++) {
            int ch = ch0 + i;
            uint32_t so = sw_off(r, ch);
            int c0 = k0 + ch * 8;
            const h16* ph;
            if (c0 < 256)      ph = g_xh + (size_t)sN * Hh + c0;
            else if (c0 < 512) ph = g_xh + (size_t)dN * Hh + (c0 - 256);
            else               ph = g_afh + (size_t)e * 64 + (c0 - 512);
            cpa16(sb + so,        ph);
            cpa16(sb + ST_B + so, g_d1_w + bRow + c0);
        }
        cpa_commit();
    };

    PIPE_MAIN2(K, load_stage);

    int g = lane >> 2, tig = lane & 3;
#pragma unroll
    for (int tm = 0; tm < 4; tm++) {
        int r0 = bm + wr * 64 + tm * 16 + g;
        float p0 = 0.f, p1 = 0.f;
#pragma unroll
        for (int tn = 0; tn < 4; tn++) {
            int col = bn + wc * 32 + tn * 8 + 2 * tig;
            float b0 = bias[col], b1 = bias[col + 1];
            float w0 = w2[col], w1 = w2[col + 1];
            p0 += fmaxf(acc[tm][tn][0] + b0, 0.f) * w0 + fmaxf(acc[tm][tn][1] + b1, 0.f) * w1;
            p1 += fmaxf(acc[tm][tn][2] + b0, 0.f) * w0 + fmaxf(acc[tm][tn][3] + b1, 0.f) * w1;
        }
        p0 += __shfl_xor_sync(0xFFFFFFFFu, p0, 1);
        p0 += __shfl_xor_sync(0xFFFFFFFFu, p0, 2);
        p1 += __shfl_xor_sync(0xFFFFFFFFu, p1, 1);
        p1 += __shfl_xor_sync(0xFFFFFFFFu, p1, 2);
        if (tig == 0) {
            if (r0 < M)     atomicAdd(&out[g_eorig[r0]], p0);
            if (r0 + 8 < M) atomicAdd(&out[g_eorig[r0 + 8]], p1);
        }
    }
}

// ------------------------- edge projection (K=8, sorted order) -------------------------
__global__ void k_eproj(const float* __restrict__ af, const float* __restrict__ W,
                        const float* __restrict__ b) {
    size_t idx = (size_t)blockIdx.x * blockDim.x + threadIdx.x;
    if (idx < (size_t)Ee * Hh) {
        int c = (int)(idx & 255);
        size_t e = idx >> 8;
        size_t eo = (size_t)g_eorig[e];
        float v = b[c];
#pragma unroll
        for (int k = 0; k < 8; k++) v += af[eo * 8 + k] * W[k * Hh + c];
        split_write(v, g_eh, g_el, idx);
    }
}

// ------------------------- per-layer node kernels -------------------------
__global__ __launch_bounds__(256) void k_node() {
    int c = threadIdx.x;
    int base = blockIdx.x * 32;
    float s = 0.f, sq = 0.f;
    for (int i = 0; i < 32; i++) {
        int n = base + i;
        size_t o = (size_t)n * Hh + c;
        float xc = __half2float(g_ABDE[(size_t)n * 1024 + c]) + g_num[o] / (g_den[o] + AGG_EPS);
        g_num[o] = xc;
        s += xc; sq += xc * xc;
    }
    atomicAdd(&g_stats[c], s);
    atomicAdd(&g_stats[Hh + c], sq);
}

__global__ void k_apply_x(const float* __restrict__ gam, const float* __restrict__ bet) {
    size_t idx = (size_t)blockIdx.x * blockDim.x + threadIdx.x;
    if (idx < (size_t)Nn * Hh) {
        int c = (int)(idx & 255);
        float mu = g_stats[c] * (1.f / Nn);
        float var = g_stats[Hh + c] * (1.f / Nn) - mu * mu;
        float v = gam[c] * (g_num[idx] - mu) * rsqrtf(var + BN_EPS) + bet[c];
        float old = __half2float(g_xh[idx]) + __half2float(g_xl[idx]);
        float o = old + fmaxf(v, 0.f);
        split_write(o, g_xh, g_xl, idx);
    }
}

__global__ void k_apply_e(const h16* __restrict__ ehat,
                          const float* __restrict__ gam, const float* __restrict__ bet) {
    size_t idx = (size_t)blockIdx.x * blockDim.x + threadIdx.x;
    if (idx < (size_t)Ee * Hh) {
        int c = (int)(idx & 255);
        float mu = g_stats[2 * Hh + c] * (1.f / Ee);
        float var = g_stats[3 * Hh + c] * (1.f / Ee) - mu * mu;
        float v = gam[c] * (__half2float(ehat[idx]) - mu) * rsqrtf(var + BN_EPS) + bet[c];
        float old = __half2float(g_eh[idx]) + __half2float(g_el[idx]);
        float o = old + fmaxf(v, 0.f);
        split_write(o, g_eh, g_el, idx);
    }
}

// ------------------------- host launcher -------------------------
extern "C" void kernel_launch(void* const* d_in, const int* in_sizes, int n_in,
                              void* d_out, int out_size)
{
    int wb = 3;
    for (int i = 3; i < n_in && i < 6; i++) {
        if (in_sizes[i] == 2 * Hh * Hh) { wb = i; break; }
    }

    const void*  eidx = d_in[0];
    const float* af   = (const float*)d_in[1];
    const float* hold = (const float*)d_in[2];
    const float* fw   = (const float*)d_in[wb + 0];
    const float* fb   = (const float*)d_in[wb + 1];
    const float* epw  = (const float*)d_in[wb + 2];
    const float* epb  = (const float*)d_in[wb + 3];
    const float* Aw   = (const float*)d_in[wb + 4];
    const float* Ab   = (const float*)d_in[wb + 5];
    const float* Bw   = (const float*)d_in[wb + 6];
    const float* Bb   = (const float*)d_in[wb + 7];
    const float* Cw   = (const float*)d_in[wb + 8];
    const float* Cb   = (const float*)d_in[wb + 9];
    const float* Dw   = (const float*)d_in[wb + 10];
    const float* Db   = (const float*)d_in[wb + 11];
    const float* Ew   = (const float*)d_in[wb + 12];
    const float* Eb   = (const float*)d_in[wb + 13];
    const float* bxg  = (const float*)d_in[wb + 14];
    const float* bxb  = (const float*)d_in[wb + 15];
    const float* beg  = (const float*)d_in[wb + 16];
    const float* beb  = (const float*)d_in[wb + 17];
    const float* d1w  = (const float*)d_in[wb + 18];
    const float* d1b  = (const float*)d_in[wb + 19];
    const float* d2w  = (const float*)d_in[wb + 20];
    const float* d2b  = (const float*)d_in[wb + 21];

    float *nump, *denp, *statsp, *bpackp, *fbiasp, *b0pp;
    h16 *abdep, *ehp, *abde_w, *c_w, *fw_w, *w0p_w;
    h16 *xh, *xl, *eh, *el, *hh, *afh;
    int *histp;
    cudaGetSymbolAddress((void**)&abdep, g_ABDE);
    cudaGetSymbolAddress((void**)&ehp, g_EH);
    cudaGetSymbolAddress((void**)&nump, g_num);
    cudaGetSymbolAddress((void**)&denp, g_den);
    cudaGetSymbolAddress((void**)&statsp, g_stats);
    cudaGetSymbolAddress((void**)&bpackp, g_bpack);
    cudaGetSymbolAddress((void**)&fbiasp, g_fbias);
    cudaGetSymbolAddress((void**)&b0pp, g_b0p);
    cudaGetSymbolAddress((void**)&abde_w, g_abde_w);
    cudaGetSymbolAddress((void**)&c_w, g_c_w);
    cudaGetSymbolAddress((void**)&fw_w, g_fw_w);
    cudaGetSymbolAddress((void**)&w0p_w, g_w0p_w);
    cudaGetSymbolAddress((void**)&xh, g_xh);
    cudaGetSymbolAddress((void**)&xl, g_xl);
    cudaGetSymbolAddress((void**)&eh, g_eh);
    cudaGetSymbolAddress((void**)&el, g_el);
    cudaGetSymbolAddress((void**)&hh, g_hh);
    cudaGetSymbolAddress((void**)&afh, g_afh);
    cudaGetSymbolAddress((void**)&histp, g_hist);

    cudaFuncSetAttribute(gemm_tc2<0>, cudaFuncAttributeMaxDynamicSharedMemorySize, SMEM3);
    cudaFuncSetAttribute(gemm_tc2<2>, cudaFuncAttributeMaxDynamicSharedMemorySize, SMEM3);
    cudaFuncSetAttribute(gemm_ce_fused<0>, cudaFuncAttributeMaxDynamicSharedMemorySize, SMEM2);
    cudaFuncSetAttribute(gemm_ce_fused<1>, cudaFuncAttributeMaxDynamicSharedMemorySize, SMEM2);
    cudaFuncSetAttribute(gemm_dec_fused, cudaFuncAttributeMaxDynamicSharedMemorySize, SMEM2);

    // --- prep; fusion GEMM placed at launch index 3 for ncu capture ---
    cudaMemsetAsync(histp, 0, Nn * sizeof(int));
    k_detect_idx<<<1, 256>>>((const unsigned int*)eidx);                          // 0
    k_convert_idx<<<(Ee + 255) / 256, 256>>>(eidx);                               // 1
    {
        int mg = MB0 + MB1 + MB2 + MB3 + MB4 + MB5;
        k_megaprep<<<mg, 256>>>(Ab, Bb, Db, Eb, fw, fb, Cw, d1w, hold);           // 2
    }
    {
        dim3 grid(Hh / 128, (Nn + 127) / 128);
        gemm_tc2<2><<<grid, 256, SMEM3>>>(hh, fw_w, fbiasp, xh, xl, Nn, Hh, Hh);  // 3 <- profiled
    }
    k_scan<<<1, 1024>>>();                                                        // 4
    k_scatter<<<(Ee + 255) / 256, 256>>>();                                       // 5
    k_split_af<<<(int)(((size_t)Ee * 64 + 255) / 256), 256>>>(af);                // 6
    {
        size_t tw = (size_t)Ll * 1024 * 256;
        k_split_abde<<<(int)((tw + 255) / 256), 256>>>(Aw, Bw, Dw, Ew);           // 7
    }
    k_w0prime<<<64, 256>>>(epw, epb, Cw, Cb);                                     // 8
    k_eproj<<<(int)(((size_t)Ee * Hh + 255) / 256), 256>>>(af, epw, epb);         // 9
    k_init_out<<<(Ee + 255) / 256, 256>>>((float*)d_out, d2b);                    // 10

    for (int l = 0; l < Ll; l++) {
        cudaMemsetAsync(nump, 0, (size_t)Nn * Hh * sizeof(float));
        cudaMemsetAsync(denp, 0, (size_t)Nn * Hh * sizeof(float));
        cudaMemsetAsync(statsp, 0, 4 * Hh * sizeof(float));

        {   // fused A|B|D|E GEMM: [N,256] @ [256,1024] -> fp16 ABDE
            dim3 grid(4 * Hh / 128, (Nn + 127) / 128);
            gemm_tc2<0><<<grid, 256, SMEM3>>>(xh,
                                              abde_w + (size_t)l * 1024 * 256,
                                              bpackp + l * 4 * Hh, abdep, nullptr,
                                              Nn, Hh, 4 * Hh);
        }
        {   // Ce GEMM + fused edge phase; layer 0 uses rank-8 collapsed form (K=64)
            dim3 grid(2, (Ee + 127) / 128);
            if (l == 0)
                gemm_ce_fused<1><<<grid, 256, SMEM2>>>(afh, w0p_w, b0pp, ehp, 64);
            else if (l < Ll - 1)
                gemm_ce_fused<1><<<grid, 256, SMEM2>>>(eh,
                                                       c_w + (size_t)l * Hh * Hh,
                                                       Cb + l * Hh, ehp, 256);
            else
                gemm_ce_fused<0><<<grid, 256, SMEM2>>>(eh,
                                                       c_w + (size_t)l * Hh * Hh,
                                                       Cb + l * Hh, ehp, 256);
        }
        k_node<<<Nn / 32, 256>>>();
        k_apply_x<<<(int)(((size_t)Nn * Hh + 255) / 256), 256>>>(bxg + l * Hh, bxb + l * Hh);
        if (l < Ll - 1)  // e dead after last layer
            k_apply_e<<<(int)(((size_t)Ee * Hh + 255) / 256), 256>>>(ehp, beg + l * Hh, beb + l * Hh);
    }

    // --- decoder (dec1 GEMM with fused dec2 dot-product epilogue) ---
    {
        dim3 grid(2, (Ee + 127) / 128);
        gemm_dec_fused<<<grid, 256, SMEM2>>>(d1b, d2w, (float*)d_out);
    }
}